// round 5
// baseline (speedup 1.0000x reference)
#include <cuda_runtime.h>
#include <cuda_bf16.h>
#include <math.h>

#define N_NODES 2048
#define DMODEL  256
#define NHEAD   8
#define DK      32
#define NEDGE   65536
#define HID     512
#define KSPLIT  4
#define NSLOT   (KSPLIT + 1)   // + correction slot

typedef unsigned long long ull;
typedef unsigned int u32;

// ---- packed f32x2 helpers ----
__device__ __forceinline__ ull fma2(ull a, ull b, ull c) {
    ull d; asm("fma.rn.f32x2 %0,%1,%2,%3;" : "=l"(d) : "l"(a), "l"(b), "l"(c)); return d;
}
__device__ __forceinline__ ull pack2(float x, float y) {
    ull r; asm("mov.b64 %0,{%1,%2};" : "=l"(r) : "f"(x), "f"(y)); return r;
}
__device__ __forceinline__ float2 unpack2(ull v) {
    float x, y; asm("mov.b64 {%0,%1},%2;" : "=f"(x), "=f"(y) : "l"(v));
    return make_float2(x, y);
}
// ---- mma / ldmatrix helpers ----
__device__ __forceinline__ u32 su32(const void* p) {
    return (u32)__cvta_generic_to_shared(p);
}
__device__ __forceinline__ void ldsm_x4(u32& r0, u32& r1, u32& r2, u32& r3, u32 a) {
    asm volatile("ldmatrix.sync.aligned.m8n8.x4.shared.b16 {%0,%1,%2,%3},[%4];"
                 : "=r"(r0), "=r"(r1), "=r"(r2), "=r"(r3) : "r"(a));
}
__device__ __forceinline__ void ldsm_x4t(u32& r0, u32& r1, u32& r2, u32& r3, u32 a) {
    asm volatile("ldmatrix.sync.aligned.m8n8.x4.trans.shared.b16 {%0,%1,%2,%3},[%4];"
                 : "=r"(r0), "=r"(r1), "=r"(r2), "=r"(r3) : "r"(a));
}
__device__ __forceinline__ void mma16816(float& c0, float& c1, float& c2, float& c3,
                                         u32 a0, u32 a1, u32 a2, u32 a3, u32 b0, u32 b1) {
    asm volatile("mma.sync.aligned.m16n8k16.row.col.f32.bf16.bf16.f32 "
                 "{%0,%1,%2,%3},{%4,%5,%6,%7},{%8,%9},{%0,%1,%2,%3};"
                 : "+f"(c0), "+f"(c1), "+f"(c2), "+f"(c3)
                 : "r"(a0), "r"(a1), "r"(a2), "r"(a3), "r"(b0), "r"(b1));
}
__device__ __forceinline__ float ex2f(float x) {
    float r; asm("ex2.approx.f32 %0,%1;" : "=f"(r) : "f"(x)); return r;
}
__device__ __forceinline__ u32 cvt2bf(float hi, float lo) {
    u32 r; asm("cvt.rn.bf16x2.f32 %0,%1,%2;" : "=r"(r) : "f"(hi), "f"(lo)); return r;
}
__device__ __forceinline__ float bflo(u32 w) { return __uint_as_float(w << 16); }
__device__ __forceinline__ float bfhi(u32 w) { return __uint_as_float(w & 0xffff0000u); }

// ---------------- scratch ----------------
__device__ __nv_bfloat16 g_Qb[N_NODES * DMODEL];
__device__ __nv_bfloat16 g_Kb[N_NODES * DMODEL];
__device__ __nv_bfloat16 g_Vb[N_NODES * DMODEL];
__device__ float g_eb[NEDGE * NHEAD];                 // pre-scaled by log2(e)
__device__ int   g_win[N_NODES * N_NODES];
__device__ float g_part[NSLOT * N_NODES * DMODEL];    // unnormalized O partials
__device__ float g_lp[NSLOT * N_NODES * NHEAD];       // denominator partials
__device__ float g_attn[N_NODES * DMODEL];
__device__ float g_Y[N_NODES * DMODEL];
__device__ float g_h1[N_NODES * DMODEL];
__device__ float g_x2[N_NODES * DMODEL];
__device__ float g_G[N_NODES * HID];

// ---------------- reset winner map ----------------
__global__ __launch_bounds__(1024) void reset_winner_kernel() {
    int i = blockIdx.x * blockDim.x + threadIdx.x;
    ((int4*)g_win)[i] = make_int4(-1, -1, -1, -1);
}

// ---------------- edge bias (log2e-scaled) + scatter winner ----------------
__global__ __launch_bounds__(256) void edge_kernel(const float* __restrict__ ea,
                                                   const float* __restrict__ We,
                                                   const float* __restrict__ be,
                                                   const int*   __restrict__ eidx) {
    const float L2E = 1.4426950408889634f;
    int e = blockIdx.x * blockDim.x + threadIdx.x;
    float a[7];
#pragma unroll
    for (int j = 0; j < 7; j++) a[j] = ea[e * 7 + j];
#pragma unroll
    for (int hh = 0; hh < 8; hh++) {
        float v = be[hh];
#pragma unroll
        for (int j = 0; j < 7; j++) v += a[j] * We[j * 8 + hh];
        g_eb[e * 8 + hh] = v * L2E;
    }
    int src = eidx[e];
    int dst = eidx[NEDGE + e];
    atomicMax(&g_win[src * N_NODES + dst], e);
}

// ---------------- SGEMM body: 64x64 tile, BK=16, 256 threads, f32x2 math ----------
__device__ __forceinline__ void gemm_body(const float* __restrict__ A,
                                          const float* __restrict__ B,
                                          const float* __restrict__ bias,
                                          const float* __restrict__ R,
                                          float* __restrict__ C,
                                          __nv_bfloat16* __restrict__ Cb,
                                          int N, int K, int gelu,
                                          int bm, int bn) {
    __shared__ float As[16][68];
    __shared__ float Bs[16][68];
    const int tid = threadIdx.x;
    const int tn = tid & 15, tm = tid >> 4;
    const int arow = tid >> 2, acol = (tid & 3) << 2;
    const int brow = tid >> 4, bcol = (tid & 15) << 2;
    const float* Aptr = A + (size_t)(bm + arow) * K + acol;
    const float* Bptr = B + (size_t)brow * N + bn + bcol;
    ull acc[4][2];
#pragma unroll
    for (int i = 0; i < 4; i++) { acc[i][0] = 0ull; acc[i][1] = 0ull; }

    for (int k0 = 0; k0 < K; k0 += 16) {
        float4 a4 = *(const float4*)(Aptr + k0);
        float4 b4 = *(const float4*)(Bptr + (size_t)k0 * N);
        __syncthreads();
        As[acol + 0][arow] = a4.x;
        As[acol + 1][arow] = a4.y;
        As[acol + 2][arow] = a4.z;
        As[acol + 3][arow] = a4.w;
        *(float4*)&Bs[brow][bcol] = b4;
        __syncthreads();
#pragma unroll
        for (int kk = 0; kk < 16; kk++) {
            float4 av = *(const float4*)&As[kk][tm << 2];
            ulonglong2 bv = *(const ulonglong2*)&Bs[kk][tn << 2];
            ull a0 = pack2(av.x, av.x);
            ull a1 = pack2(av.y, av.y);
            ull a2 = pack2(av.z, av.z);
            ull a3 = pack2(av.w, av.w);
            acc[0][0] = fma2(a0, bv.x, acc[0][0]); acc[0][1] = fma2(a0, bv.y, acc[0][1]);
            acc[1][0] = fma2(a1, bv.x, acc[1][0]); acc[1][1] = fma2(a1, bv.y, acc[1][1]);
            acc[2][0] = fma2(a2, bv.x, acc[2][0]); acc[2][1] = fma2(a2, bv.y, acc[2][1]);
            acc[3][0] = fma2(a3, bv.x, acc[3][0]); acc[3][1] = fma2(a3, bv.y, acc[3][1]);
        }
    }

    const int crow = bm + (tm << 2), ccol = bn + (tn << 2);
#pragma unroll
    for (int i = 0; i < 4; i++) {
        float2 u0 = unpack2(acc[i][0]);
        float2 u1 = unpack2(acc[i][1]);
        float o[4] = {u0.x, u0.y, u1.x, u1.y};
#pragma unroll
        for (int j = 0; j < 4; j++) {
            float v = o[j] + bias[ccol + j];
            if (gelu) v = v * normcdff(v);
            if (R) v += R[(size_t)(crow + i) * N + ccol + j];
            o[j] = v;
        }
        if (Cb) {
            uint2 p;
            p.x = cvt2bf(o[1], o[0]);
            p.y = cvt2bf(o[3], o[2]);
            *(uint2*)&Cb[(size_t)(crow + i) * N + ccol] = p;
        } else {
            *(float4*)&C[(size_t)(crow + i) * N + ccol] =
                make_float4(o[0], o[1], o[2], o[3]);
        }
    }
}

__global__ __launch_bounds__(256) void gemm64(const float* __restrict__ A,
                                              const float* __restrict__ B,
                                              const float* __restrict__ bias,
                                              const float* __restrict__ R,
                                              float* __restrict__ C,
                                              int N, int K, int gelu) {
    gemm_body(A, B, bias, R, C, nullptr, N, K, gelu, blockIdx.y * 64, blockIdx.x * 64);
}

// fused QKV -> bf16 outputs
__global__ __launch_bounds__(256) void gemm_qkv(const float* __restrict__ A,
                                                const float* __restrict__ Wq,
                                                const float* __restrict__ bq,
                                                const float* __restrict__ Wk,
                                                const float* __restrict__ bk,
                                                const float* __restrict__ Wv,
                                                const float* __restrict__ bv) {
    int sel = blockIdx.x >> 2;
    int bn  = (blockIdx.x & 3) * 64;
    const float* B    = (sel == 0) ? Wq : (sel == 1) ? Wk : Wv;
    const float* bias = (sel == 0) ? bq : (sel == 1) ? bk : bv;
    __nv_bfloat16* Cb = (sel == 0) ? g_Qb : (sel == 1) ? g_Kb : g_Vb;
    gemm_body(A, B, bias, nullptr, nullptr, Cb, DMODEL, DMODEL, 0, blockIdx.y * 64, bn);
}

// ---------------- dense tensor-core flash attention, split-K, NO bias ----------
__global__ __launch_bounds__(128, 5) void attn_mma(const __nv_bfloat16* __restrict__ Qb,
                                                   const __nv_bfloat16* __restrict__ Kb,
                                                   const __nv_bfloat16* __restrict__ Vb) {
    __shared__ __align__(16) __nv_bfloat16 Ks[64][40];
    __shared__ __align__(16) __nv_bfloat16 Vs[64][40];

    const int h     = blockIdx.y;
    const int qb    = blockIdx.x * 64;
    const int chunk = blockIdx.z;
    const int kb0   = chunk * (N_NODES / KSPLIT);
    const int tid = threadIdx.x;
    const int warp = tid >> 5, lane = tid & 31;

    // stage Q tile into Ks, build per-warp A-fragments
#pragma unroll
    for (int i = 0; i < 2; i++) {
        int task = tid + 128 * i;
        int row = task >> 2, ch = task & 3;
        uint4 v = *(const uint4*)((const char*)(Qb + (size_t)(qb + row) * DMODEL + h * DK) + ch * 16);
        *(uint4*)((char*)&Ks[row][0] + ch * 16) = v;
    }
    __syncthreads();
    const int lr = lane & 7, lm = lane >> 3;
    u32 qa[2][4];
    {
        int row = warp * 16 + lr + (lm & 1) * 8;
#pragma unroll
        for (int c = 0; c < 2; c++) {
            u32 a = su32(&Ks[row][c * 16 + (lm >> 1) * 8]);
            ldsm_x4(qa[c][0], qa[c][1], qa[c][2], qa[c][3], a);
        }
    }

    const u32 kaddr = su32(&Ks[lr][lm * 8]);
    const u32 vaddr = su32(&Vs[lr + (lm & 1) * 8][(lm >> 1) * 8]);

    float O[4][4];
#pragma unroll
    for (int t = 0; t < 4; t++)
#pragma unroll
        for (int j = 0; j < 4; j++) O[t][j] = 0.f;
    float l0 = 0.f, l1 = 0.f;

    const float SCALE2 = 1.4426950408889634f * 0.17677669529663688f;

    for (int kt = 0; kt < (N_NODES / KSPLIT) / 64; kt++) {
        const int kb = kb0 + kt * 64;
        __syncthreads();
#pragma unroll
        for (int i = 0; i < 2; i++) {
            int task = tid + 128 * i;
            int row = task >> 2, ch = task & 3;
            const char* kp = (const char*)(Kb + (size_t)(kb + row) * DMODEL + h * DK) + ch * 16;
            const char* vp = (const char*)(Vb + (size_t)(kb + row) * DMODEL + h * DK) + ch * 16;
            *(uint4*)((char*)&Ks[row][0] + ch * 16) = *(const uint4*)kp;
            *(uint4*)((char*)&Vs[row][0] + ch * 16) = *(const uint4*)vp;
        }
        __syncthreads();

        // scores + exp -> packed bf16 P frags
        u32 P[8][2];
#pragma unroll
        for (int kg = 0; kg < 8; kg++) {
            u32 b0, b1, b2, b3;
            ldsm_x4(b0, b1, b2, b3, kaddr + kg * 640);
            float c0 = 0.f, c1 = 0.f, c2 = 0.f, c3 = 0.f;
            mma16816(c0, c1, c2, c3, qa[0][0], qa[0][1], qa[0][2], qa[0][3], b0, b1);
            mma16816(c0, c1, c2, c3, qa[1][0], qa[1][1], qa[1][2], qa[1][3], b2, b3);
            float p0 = ex2f(c0 * SCALE2);
            float p1 = ex2f(c1 * SCALE2);
            float p2 = ex2f(c2 * SCALE2);
            float p3 = ex2f(c3 * SCALE2);
            l0 += p0 + p1;
            l1 += p2 + p3;
            P[kg][0] = cvt2bf(p1, p0);
            P[kg][1] = cvt2bf(p3, p2);
        }

        // PV
#pragma unroll
        for (int ck = 0; ck < 4; ck++) {
            u32 a0 = P[2 * ck][0], a1 = P[2 * ck][1];
            u32 a2 = P[2 * ck + 1][0], a3 = P[2 * ck + 1][1];
#pragma unroll
            for (int tp = 0; tp < 2; tp++) {
                u32 v0, v1, v2, v3;
                ldsm_x4t(v0, v1, v2, v3, vaddr + ck * 1280 + tp * 32);
                mma16816(O[2 * tp][0], O[2 * tp][1], O[2 * tp][2], O[2 * tp][3],
                         a0, a1, a2, a3, v0, v1);
                mma16816(O[2 * tp + 1][0], O[2 * tp + 1][1], O[2 * tp + 1][2], O[2 * tp + 1][3],
                         a0, a1, a2, a3, v2, v3);
            }
        }
    }

    l0 += __shfl_xor_sync(0xffffffffu, l0, 1);
    l0 += __shfl_xor_sync(0xffffffffu, l0, 2);
    l1 += __shfl_xor_sync(0xffffffffu, l1, 1);
    l1 += __shfl_xor_sync(0xffffffffu, l1, 2);

    const int r0 = qb + warp * 16 + (lane >> 2);
    const int r1 = r0 + 8;
    const int cql = 2 * (lane & 3);

    float* part = g_part + (size_t)chunk * N_NODES * DMODEL;
#pragma unroll
    for (int t = 0; t < 4; t++) {
        int col = h * DK + t * 8 + cql;
        *(float2*)&part[(size_t)r0 * DMODEL + col] = make_float2(O[t][0], O[t][1]);
        *(float2*)&part[(size_t)r1 * DMODEL + col] = make_float2(O[t][2], O[t][3]);
    }
    if ((lane & 3) == 0) {
        g_lp[((size_t)chunk * N_NODES + r0) * NHEAD + h] = l0;
        g_lp[((size_t)chunk * N_NODES + r1) * NHEAD + h] = l1;
    }
}

// ---------------- sparse bias correction: slot KSPLIT ----------------
// one warp per query row; lane = h*4+g owns dims [g*8, g*8+8) of head h.
__global__ __launch_bounds__(256) void corr_kernel(const __nv_bfloat16* __restrict__ Qb,
                                                   const __nv_bfloat16* __restrict__ Kb,
                                                   const __nv_bfloat16* __restrict__ Vb) {
    const int q    = (blockIdx.x * 256 + threadIdx.x) >> 5;
    const int lane = threadIdx.x & 31;
    const int h = lane >> 2, g = lane & 3;
    const float SCALE2 = 1.4426950408889634f * 0.17677669529663688f;

    // load & pre-scale this lane's Q slice
    float qv[8];
    {
        uint4 w = *(const uint4*)(Qb + (size_t)q * DMODEL + h * DK + g * 8);
        const u32 ws[4] = {w.x, w.y, w.z, w.w};
#pragma unroll
        for (int i = 0; i < 4; i++) {
            qv[2 * i]     = bflo(ws[i]) * SCALE2;
            qv[2 * i + 1] = bfhi(ws[i]) * SCALE2;
        }
    }

    float O[8];
#pragma unroll
    for (int i = 0; i < 8; i++) O[i] = 0.f;
    float lacc = 0.f;

    const int* wrow = g_win + (size_t)q * N_NODES;
    for (int base = 0; base < N_NODES; base += 32) {
        int w = wrow[base + lane];
        unsigned mask = __ballot_sync(0xffffffffu, w >= 0);
        while (mask) {
            int bit = __ffs(mask) - 1;
            mask &= mask - 1;
            int k = base + bit;
            int widx = __shfl_sync(0xffffffffu, w, bit);

            // K slice dot
            uint4 kw = *(const uint4*)(Kb + (size_t)k * DMODEL + h * DK + g * 8);
            const u32 ks[4] = {kw.x, kw.y, kw.z, kw.w};
            float s = 0.f;
#pragma unroll
            for (int i = 0; i < 4; i++) {
                s += qv[2 * i] * bflo(ks[i]);
                s += qv[2 * i + 1] * bfhi(ks[i]);
            }
            s += __shfl_xor_sync(0xffffffffu, s, 1);
            s += __shfl_xor_sync(0xffffffffu, s, 2);

            float eb = g_eb[(size_t)widx * 8 + h];
            float pd = ex2f(s + eb) - ex2f(s);
            lacc += pd;

            uint4 vw = *(const uint4*)(Vb + (size_t)k * DMODEL + h * DK + g * 8);
            const u32 vs[4] = {vw.x, vw.y, vw.z, vw.w};
#pragma unroll
            for (int i = 0; i < 4; i++) {
                O[2 * i]     += pd * bflo(vs[i]);
                O[2 * i + 1] += pd * bfhi(vs[i]);
            }
        }
    }

    float* part = g_part + (size_t)KSPLIT * N_NODES * DMODEL + (size_t)q * DMODEL + h * DK + g * 8;
    *(float4*)&part[0] = make_float4(O[0], O[1], O[2], O[3]);
    *(float4*)&part[4] = make_float4(O[4], O[5], O[6], O[7]);
    if (g == 0)
        g_lp[((size_t)KSPLIT * N_NODES + q) * NHEAD + h] = lacc;
}

// ---------------- combine partials (deterministic) ----------------
__global__ __launch_bounds__(256) void combine_kernel() {
    int gid = blockIdx.x * 256 + threadIdx.x;   // 2048*64
    int row = gid >> 6;
    int col = (gid & 63) << 2;
    int h = col >> 5;
    float ls = 0.f;
    float4 acc = make_float4(0.f, 0.f, 0.f, 0.f);
#pragma unroll
    for (int c = 0; c < NSLOT; c++) {
        ls += g_lp[((size_t)c * N_NODES + row) * NHEAD + h];
        float4 p = *(const float4*)&g_part[((size_t)c * N_NODES + row) * DMODEL + col];
        acc.x += p.x; acc.y += p.y; acc.z += p.z; acc.w += p.w;
    }
    float inv = 1.f / ls;
    *(float4*)&g_attn[(size_t)row * DMODEL + col] =
        make_float4(acc.x * inv, acc.y * inv, acc.z * inv, acc.w * inv);
}

// ---------------- fused double LayerNorm ----------------
__global__ __launch_bounds__(256) void ln_kernel(const float* __restrict__ Y,
                                                 const float* __restrict__ g1,
                                                 const float* __restrict__ b1,
                                                 const float* __restrict__ g2,
                                                 const float* __restrict__ b2,
                                                 float* __restrict__ H1,
                                                 float* __restrict__ X2) {
    const int lane = threadIdx.x & 31;
    const int row  = blockIdx.x * 8 + (threadIdx.x >> 5);
    const float* y = Y + (size_t)row * DMODEL;
    float v[8];
#pragma unroll
    for (int j = 0; j < 8; j++) v[j] = y[lane + 32 * j];

    float s = 0.f;
#pragma unroll
    for (int j = 0; j < 8; j++) s += v[j];
#pragma unroll
    for (int o = 16; o; o >>= 1) s += __shfl_xor_sync(0xffffffffu, s, o);
    float mu = s * (1.f / 256.f);
    float q = 0.f;
#pragma unroll
    for (int j = 0; j < 8; j++) { float d = v[j] - mu; q += d * d; }
#pragma unroll
    for (int o = 16; o; o >>= 1) q += __shfl_xor_sync(0xffffffffu, q, o);
    float rs = rsqrtf(q * (1.f / 256.f) + 1e-5f);

    float hv[8];
#pragma unroll
    for (int j = 0; j < 8; j++) {
        int c = lane + 32 * j;
        hv[j] = (v[j] - mu) * rs * g1[c] + b1[c];
        H1[(size_t)row * DMODEL + c] = hv[j];
    }

    s = 0.f;
#pragma unroll
    for (int j = 0; j < 8; j++) s += hv[j];
#pragma unroll
    for (int o = 16; o; o >>= 1) s += __shfl_xor_sync(0xffffffffu, s, o);
    mu = s * (1.f / 256.f);
    q = 0.f;
#pragma unroll
    for (int j = 0; j < 8; j++) { float d = hv[j] - mu; q += d * d; }
#pragma unroll
    for (int o = 16; o; o >>= 1) q += __shfl_xor_sync(0xffffffffu, q, o);
    rs = rsqrtf(q * (1.f / 256.f) + 1e-5f);
#pragma unroll
    for (int j = 0; j < 8; j++) {
        int c = lane + 32 * j;
        X2[(size_t)row * DMODEL + c] = (hv[j] - mu) * rs * g2[c] + b2[c];
    }
}

// ---------------- launch ----------------
extern "C" void kernel_launch(void* const* d_in, const int* in_sizes, int n_in,
                              void* d_out, int out_size) {
    const float* h    = (const float*)d_in[0];
    const float* ea   = (const float*)d_in[1];
    const float* Wq   = (const float*)d_in[2];
    const float* bq   = (const float*)d_in[3];
    const float* Wk   = (const float*)d_in[4];
    const float* bk   = (const float*)d_in[5];
    const float* Wv   = (const float*)d_in[6];
    const float* bv   = (const float*)d_in[7];
    const float* Wo   = (const float*)d_in[8];
    const float* bo   = (const float*)d_in[9];
    const float* We   = (const float*)d_in[10];
    const float* be   = (const float*)d_in[11];
    const float* ln1g = (const float*)d_in[12];
    const float* ln1b = (const float*)d_in[13];
    const float* flng = (const float*)d_in[14];
    const float* flnb = (const float*)d_in[15];
    const float* W1   = (const float*)d_in[16];
    const float* b1   = (const float*)d_in[17];
    const float* W2   = (const float*)d_in[18];
    const float* b2   = (const float*)d_in[19];
    const int*   eidx = (const int*)d_in[20];
    float* out = (float*)d_out;

    __nv_bfloat16 *pQb, *pKb, *pVb;
    float *pAttn, *pY, *pH1, *pX2, *pG;
    cudaGetSymbolAddress((void**)&pQb,   g_Qb);
    cudaGetSymbolAddress((void**)&pKb,   g_Kb);
    cudaGetSymbolAddress((void**)&pVb,   g_Vb);
    cudaGetSymbolAddress((void**)&pAttn, g_attn);
    cudaGetSymbolAddress((void**)&pY,    g_Y);
    cudaGetSymbolAddress((void**)&pH1,   g_h1);
    cudaGetSymbolAddress((void**)&pX2,   g_x2);
    cudaGetSymbolAddress((void**)&pG,    g_G);

    reset_winner_kernel<<<1024, 1024>>>();
    edge_kernel<<<NEDGE / 256, 256>>>(ea, We, be, eidx);

    gemm_qkv<<<dim3(12, 32), 256>>>(h, Wq, bq, Wk, bk, Wv, bv);

    attn_mma<<<dim3(N_NODES / 64, NHEAD, KSPLIT), 128>>>(pQb, pKb, pVb);
    corr_kernel<<<N_NODES / 8, 256>>>(pQb, pKb, pVb);
    combine_kernel<<<(N_NODES * DMODEL / 4) / 256, 256>>>();

    gemm64<<<dim3(4, 32), 256>>>(pAttn, Wo, bo, h, pY, DMODEL, DMODEL, 0);

    ln_kernel<<<N_NODES / 8, 256>>>(pY, ln1g, ln1b, flng, flnb, pH1, pX2);

    gemm64<<<dim3(8, 32), 256>>>(pX2, W1, b1, nullptr, pG, HID, DMODEL, 1);
    gemm64<<<dim3(4, 32), 256>>>(pG, W2, b2, pH1, out, DMODEL, HID, 0);
}

// round 6
// speedup vs baseline: 1.1180x; 1.1180x over previous
#include <cuda_runtime.h>
#include <cuda_bf16.h>
#include <math.h>

#define N_NODES 2048
#define DMODEL  256
#define NHEAD   8
#define DK      32
#define NEDGE   65536
#define HID     512
#define KSPLIT  4
#define NSLOT   (KSPLIT + 1)   // + correction slot
#define CAP     512            // per-warp hit-list capacity

typedef unsigned long long ull;
typedef unsigned int u32;

// ---- packed f32x2 helpers ----
__device__ __forceinline__ ull fma2(ull a, ull b, ull c) {
    ull d; asm("fma.rn.f32x2 %0,%1,%2,%3;" : "=l"(d) : "l"(a), "l"(b), "l"(c)); return d;
}
__device__ __forceinline__ ull pack2(float x, float y) {
    ull r; asm("mov.b64 %0,{%1,%2};" : "=l"(r) : "f"(x), "f"(y)); return r;
}
__device__ __forceinline__ float2 unpack2(ull v) {
    float x, y; asm("mov.b64 {%0,%1},%2;" : "=f"(x), "=f"(y) : "l"(v));
    return make_float2(x, y);
}
// ---- mma / ldmatrix helpers ----
__device__ __forceinline__ u32 su32(const void* p) {
    return (u32)__cvta_generic_to_shared(p);
}
__device__ __forceinline__ void ldsm_x4(u32& r0, u32& r1, u32& r2, u32& r3, u32 a) {
    asm volatile("ldmatrix.sync.aligned.m8n8.x4.shared.b16 {%0,%1,%2,%3},[%4];"
                 : "=r"(r0), "=r"(r1), "=r"(r2), "=r"(r3) : "r"(a));
}
__device__ __forceinline__ void ldsm_x4t(u32& r0, u32& r1, u32& r2, u32& r3, u32 a) {
    asm volatile("ldmatrix.sync.aligned.m8n8.x4.trans.shared.b16 {%0,%1,%2,%3},[%4];"
                 : "=r"(r0), "=r"(r1), "=r"(r2), "=r"(r3) : "r"(a));
}
__device__ __forceinline__ void mma16816(float& c0, float& c1, float& c2, float& c3,
                                         u32 a0, u32 a1, u32 a2, u32 a3, u32 b0, u32 b1) {
    asm volatile("mma.sync.aligned.m16n8k16.row.col.f32.bf16.bf16.f32 "
                 "{%0,%1,%2,%3},{%4,%5,%6,%7},{%8,%9},{%0,%1,%2,%3};"
                 : "+f"(c0), "+f"(c1), "+f"(c2), "+f"(c3)
                 : "r"(a0), "r"(a1), "r"(a2), "r"(a3), "r"(b0), "r"(b1));
}
__device__ __forceinline__ float ex2f(float x) {
    float r; asm("ex2.approx.f32 %0,%1;" : "=f"(r) : "f"(x)); return r;
}
__device__ __forceinline__ u32 cvt2bf(float hi, float lo) {
    u32 r; asm("cvt.rn.bf16x2.f32 %0,%1,%2;" : "=r"(r) : "f"(hi), "f"(lo)); return r;
}
__device__ __forceinline__ float bflo(u32 w) { return __uint_as_float(w << 16); }
__device__ __forceinline__ float bfhi(u32 w) { return __uint_as_float(w & 0xffff0000u); }

// ---------------- scratch ----------------
__device__ __nv_bfloat16 g_Qb[N_NODES * DMODEL];
__device__ __nv_bfloat16 g_Kb[N_NODES * DMODEL];
__device__ __nv_bfloat16 g_Vb[N_NODES * DMODEL];
__device__ float g_eb[NEDGE * NHEAD];                 // pre-scaled by log2(e)
__device__ int   g_win[N_NODES * N_NODES];
__device__ float g_part[NSLOT * N_NODES * DMODEL];    // unnormalized O partials
__device__ float g_lp[NSLOT * N_NODES * NHEAD];       // denominator partials
__device__ float g_attn[N_NODES * DMODEL];
__device__ float g_Y[N_NODES * DMODEL];
__device__ float g_h1[N_NODES * DMODEL];
__device__ float g_x2[N_NODES * DMODEL];
__device__ float g_G[N_NODES * HID];

// ---------------- reset winner map ----------------
__global__ __launch_bounds__(1024) void reset_winner_kernel() {
    int i = blockIdx.x * blockDim.x + threadIdx.x;
    ((int4*)g_win)[i] = make_int4(-1, -1, -1, -1);
}

// ---------------- edge bias (log2e-scaled) + scatter winner ----------------
__global__ __launch_bounds__(256) void edge_kernel(const float* __restrict__ ea,
                                                   const float* __restrict__ We,
                                                   const float* __restrict__ be,
                                                   const int*   __restrict__ eidx) {
    const float L2E = 1.4426950408889634f;
    int e = blockIdx.x * blockDim.x + threadIdx.x;
    float a[7];
#pragma unroll
    for (int j = 0; j < 7; j++) a[j] = ea[e * 7 + j];
#pragma unroll
    for (int hh = 0; hh < 8; hh++) {
        float v = be[hh];
#pragma unroll
        for (int j = 0; j < 7; j++) v += a[j] * We[j * 8 + hh];
        g_eb[e * 8 + hh] = v * L2E;
    }
    int src = eidx[e];
    int dst = eidx[NEDGE + e];
    atomicMax(&g_win[src * N_NODES + dst], e);
}

// ---------------- SGEMM body: 64x64 tile, BK=16, 256 threads, f32x2 math ----------
__device__ __forceinline__ void gemm_body(const float* __restrict__ A,
                                          const float* __restrict__ B,
                                          const float* __restrict__ bias,
                                          const float* __restrict__ R,
                                          float* __restrict__ C,
                                          __nv_bfloat16* __restrict__ Cb,
                                          int N, int K, int gelu,
                                          int bm, int bn) {
    __shared__ float As[16][68];
    __shared__ float Bs[16][68];
    const int tid = threadIdx.x;
    const int tn = tid & 15, tm = tid >> 4;
    const int arow = tid >> 2, acol = (tid & 3) << 2;
    const int brow = tid >> 4, bcol = (tid & 15) << 2;
    const float* Aptr = A + (size_t)(bm + arow) * K + acol;
    const float* Bptr = B + (size_t)brow * N + bn + bcol;
    ull acc[4][2];
#pragma unroll
    for (int i = 0; i < 4; i++) { acc[i][0] = 0ull; acc[i][1] = 0ull; }

    for (int k0 = 0; k0 < K; k0 += 16) {
        float4 a4 = *(const float4*)(Aptr + k0);
        float4 b4 = *(const float4*)(Bptr + (size_t)k0 * N);
        __syncthreads();
        As[acol + 0][arow] = a4.x;
        As[acol + 1][arow] = a4.y;
        As[acol + 2][arow] = a4.z;
        As[acol + 3][arow] = a4.w;
        *(float4*)&Bs[brow][bcol] = b4;
        __syncthreads();
#pragma unroll
        for (int kk = 0; kk < 16; kk++) {
            float4 av = *(const float4*)&As[kk][tm << 2];
            ulonglong2 bv = *(const ulonglong2*)&Bs[kk][tn << 2];
            ull a0 = pack2(av.x, av.x);
            ull a1 = pack2(av.y, av.y);
            ull a2 = pack2(av.z, av.z);
            ull a3 = pack2(av.w, av.w);
            acc[0][0] = fma2(a0, bv.x, acc[0][0]); acc[0][1] = fma2(a0, bv.y, acc[0][1]);
            acc[1][0] = fma2(a1, bv.x, acc[1][0]); acc[1][1] = fma2(a1, bv.y, acc[1][1]);
            acc[2][0] = fma2(a2, bv.x, acc[2][0]); acc[2][1] = fma2(a2, bv.y, acc[2][1]);
            acc[3][0] = fma2(a3, bv.x, acc[3][0]); acc[3][1] = fma2(a3, bv.y, acc[3][1]);
        }
    }

    const int crow = bm + (tm << 2), ccol = bn + (tn << 2);
#pragma unroll
    for (int i = 0; i < 4; i++) {
        float2 u0 = unpack2(acc[i][0]);
        float2 u1 = unpack2(acc[i][1]);
        float o[4] = {u0.x, u0.y, u1.x, u1.y};
#pragma unroll
        for (int j = 0; j < 4; j++) {
            float v = o[j] + bias[ccol + j];
            if (gelu) v = v * normcdff(v);
            if (R) v += R[(size_t)(crow + i) * N + ccol + j];
            o[j] = v;
        }
        if (Cb) {
            uint2 p;
            p.x = cvt2bf(o[1], o[0]);
            p.y = cvt2bf(o[3], o[2]);
            *(uint2*)&Cb[(size_t)(crow + i) * N + ccol] = p;
        } else {
            *(float4*)&C[(size_t)(crow + i) * N + ccol] =
                make_float4(o[0], o[1], o[2], o[3]);
        }
    }
}

__global__ __launch_bounds__(256) void gemm64(const float* __restrict__ A,
                                              const float* __restrict__ B,
                                              const float* __restrict__ bias,
                                              const float* __restrict__ R,
                                              float* __restrict__ C,
                                              int N, int K, int gelu) {
    gemm_body(A, B, bias, R, C, nullptr, N, K, gelu, blockIdx.y * 64, blockIdx.x * 64);
}

// fused QKV -> bf16 outputs
__global__ __launch_bounds__(256) void gemm_qkv(const float* __restrict__ A,
                                                const float* __restrict__ Wq,
                                                const float* __restrict__ bq,
                                                const float* __restrict__ Wk,
                                                const float* __restrict__ bk,
                                                const float* __restrict__ Wv,
                                                const float* __restrict__ bv) {
    int sel = blockIdx.x >> 2;
    int bn  = (blockIdx.x & 3) * 64;
    const float* B    = (sel == 0) ? Wq : (sel == 1) ? Wk : Wv;
    const float* bias = (sel == 0) ? bq : (sel == 1) ? bk : bv;
    __nv_bfloat16* Cb = (sel == 0) ? g_Qb : (sel == 1) ? g_Kb : g_Vb;
    gemm_body(A, B, bias, nullptr, nullptr, Cb, DMODEL, DMODEL, 0, blockIdx.y * 64, bn);
}

// ---------------- dense tensor-core flash attention, split-K, NO bias ----------
__global__ __launch_bounds__(128, 5) void attn_mma(const __nv_bfloat16* __restrict__ Qb,
                                                   const __nv_bfloat16* __restrict__ Kb,
                                                   const __nv_bfloat16* __restrict__ Vb) {
    __shared__ __align__(16) __nv_bfloat16 Ks[64][40];
    __shared__ __align__(16) __nv_bfloat16 Vs[64][40];

    const int h     = blockIdx.y;
    const int qb    = blockIdx.x * 64;
    const int chunk = blockIdx.z;
    const int kb0   = chunk * (N_NODES / KSPLIT);
    const int tid = threadIdx.x;
    const int warp = tid >> 5, lane = tid & 31;

    // stage Q tile into Ks, build per-warp A-fragments
#pragma unroll
    for (int i = 0; i < 2; i++) {
        int task = tid + 128 * i;
        int row = task >> 2, ch = task & 3;
        uint4 v = *(const uint4*)((const char*)(Qb + (size_t)(qb + row) * DMODEL + h * DK) + ch * 16);
        *(uint4*)((char*)&Ks[row][0] + ch * 16) = v;
    }
    __syncthreads();
    const int lr = lane & 7, lm = lane >> 3;
    u32 qa[2][4];
    {
        int row = warp * 16 + lr + (lm & 1) * 8;
#pragma unroll
        for (int c = 0; c < 2; c++) {
            u32 a = su32(&Ks[row][c * 16 + (lm >> 1) * 8]);
            ldsm_x4(qa[c][0], qa[c][1], qa[c][2], qa[c][3], a);
        }
    }

    const u32 kaddr = su32(&Ks[lr][lm * 8]);
    const u32 vaddr = su32(&Vs[lr + (lm & 1) * 8][(lm >> 1) * 8]);

    float O[4][4];
#pragma unroll
    for (int t = 0; t < 4; t++)
#pragma unroll
        for (int j = 0; j < 4; j++) O[t][j] = 0.f;
    float l0 = 0.f, l1 = 0.f;

    const float SCALE2 = 1.4426950408889634f * 0.17677669529663688f;

    for (int kt = 0; kt < (N_NODES / KSPLIT) / 64; kt++) {
        const int kb = kb0 + kt * 64;
        __syncthreads();
#pragma unroll
        for (int i = 0; i < 2; i++) {
            int task = tid + 128 * i;
            int row = task >> 2, ch = task & 3;
            const char* kp = (const char*)(Kb + (size_t)(kb + row) * DMODEL + h * DK) + ch * 16;
            const char* vp = (const char*)(Vb + (size_t)(kb + row) * DMODEL + h * DK) + ch * 16;
            *(uint4*)((char*)&Ks[row][0] + ch * 16) = *(const uint4*)kp;
            *(uint4*)((char*)&Vs[row][0] + ch * 16) = *(const uint4*)vp;
        }
        __syncthreads();

        // scores + exp -> packed bf16 P frags
        u32 P[8][2];
#pragma unroll
        for (int kg = 0; kg < 8; kg++) {
            u32 b0, b1, b2, b3;
            ldsm_x4(b0, b1, b2, b3, kaddr + kg * 640);
            float c0 = 0.f, c1 = 0.f, c2 = 0.f, c3 = 0.f;
            mma16816(c0, c1, c2, c3, qa[0][0], qa[0][1], qa[0][2], qa[0][3], b0, b1);
            mma16816(c0, c1, c2, c3, qa[1][0], qa[1][1], qa[1][2], qa[1][3], b2, b3);
            float p0 = ex2f(c0 * SCALE2);
            float p1 = ex2f(c1 * SCALE2);
            float p2 = ex2f(c2 * SCALE2);
            float p3 = ex2f(c3 * SCALE2);
            l0 += p0 + p1;
            l1 += p2 + p3;
            P[kg][0] = cvt2bf(p1, p0);
            P[kg][1] = cvt2bf(p3, p2);
        }

        // PV
#pragma unroll
        for (int ck = 0; ck < 4; ck++) {
            u32 a0 = P[2 * ck][0], a1 = P[2 * ck][1];
            u32 a2 = P[2 * ck + 1][0], a3 = P[2 * ck + 1][1];
#pragma unroll
            for (int tp = 0; tp < 2; tp++) {
                u32 v0, v1, v2, v3;
                ldsm_x4t(v0, v1, v2, v3, vaddr + ck * 1280 + tp * 32);
                mma16816(O[2 * tp][0], O[2 * tp][1], O[2 * tp][2], O[2 * tp][3],
                         a0, a1, a2, a3, v0, v1);
                mma16816(O[2 * tp + 1][0], O[2 * tp + 1][1], O[2 * tp + 1][2], O[2 * tp + 1][3],
                         a0, a1, a2, a3, v2, v3);
            }
        }
    }

    l0 += __shfl_xor_sync(0xffffffffu, l0, 1);
    l0 += __shfl_xor_sync(0xffffffffu, l0, 2);
    l1 += __shfl_xor_sync(0xffffffffu, l1, 1);
    l1 += __shfl_xor_sync(0xffffffffu, l1, 2);

    const int r0 = qb + warp * 16 + (lane >> 2);
    const int r1 = r0 + 8;
    const int cql = 2 * (lane & 3);

    float* part = g_part + (size_t)chunk * N_NODES * DMODEL;
#pragma unroll
    for (int t = 0; t < 4; t++) {
        int col = h * DK + t * 8 + cql;
        *(float2*)&part[(size_t)r0 * DMODEL + col] = make_float2(O[t][0], O[t][1]);
        *(float2*)&part[(size_t)r1 * DMODEL + col] = make_float2(O[t][2], O[t][3]);
    }
    if ((lane & 3) == 0) {
        g_lp[((size_t)chunk * N_NODES + r0) * NHEAD + h] = l0;
        g_lp[((size_t)chunk * N_NODES + r1) * NHEAD + h] = l1;
    }
}

// ---------------- sparse bias correction (MLP-friendly) ----------------
// One warp per query row; lane = h*4+g owns dims [g*8, g*8+8) of head h.
// Phase 1: strip-scan winner row into per-warp smem hit list (ballot+popc writes).
// Phase 2: process hits 4 at a time with independent loads.
__device__ __forceinline__ void corr_process(const u32* mylist, int i0, int cnt,
                                             const float* qv, float* O, float& lacc,
                                             int h, int g,
                                             const __nv_bfloat16* __restrict__ Kb,
                                             const __nv_bfloat16* __restrict__ Vb) {
    for (int i = i0; i < cnt; i += 4) {
#pragma unroll
        for (int j = 0; j < 4; j++) {
            if (i + j >= cnt) break;                 // warp-uniform
            u32 e = mylist[i + j];
            int k    = (int)(e >> 16);
            int widx = (int)(e & 0xFFFFu);
            uint4 kw = *(const uint4*)(Kb + (size_t)k * DMODEL + h * DK + g * 8);
            uint4 vw = *(const uint4*)(Vb + (size_t)k * DMODEL + h * DK + g * 8);
            float eb = g_eb[(size_t)widx * 8 + h];
            const u32 ks[4] = {kw.x, kw.y, kw.z, kw.w};
            float s = 0.f;
#pragma unroll
            for (int t = 0; t < 4; t++) {
                s += qv[2 * t] * bflo(ks[t]);
                s += qv[2 * t + 1] * bfhi(ks[t]);
            }
            s += __shfl_xor_sync(0xffffffffu, s, 1);
            s += __shfl_xor_sync(0xffffffffu, s, 2);
            float pd = ex2f(s + eb) - ex2f(s);
            lacc += pd;
            const u32 vs[4] = {vw.x, vw.y, vw.z, vw.w};
#pragma unroll
            for (int t = 0; t < 4; t++) {
                O[2 * t]     += pd * bflo(vs[t]);
                O[2 * t + 1] += pd * bfhi(vs[t]);
            }
        }
    }
}

__global__ __launch_bounds__(256) void corr_kernel(const __nv_bfloat16* __restrict__ Qb,
                                                   const __nv_bfloat16* __restrict__ Kb,
                                                   const __nv_bfloat16* __restrict__ Vb) {
    __shared__ u32 list[8][CAP];
    const int wwarp = threadIdx.x >> 5;
    const int q     = blockIdx.x * 8 + wwarp;
    const int lane  = threadIdx.x & 31;
    const int h = lane >> 2, g = lane & 3;
    const float SCALE2 = 1.4426950408889634f * 0.17677669529663688f;
    const u32 lmask_lt = (1u << lane) - 1u;

    // load & pre-scale this lane's Q slice
    float qv[8];
    {
        uint4 w = *(const uint4*)(Qb + (size_t)q * DMODEL + h * DK + g * 8);
        const u32 ws[4] = {w.x, w.y, w.z, w.w};
#pragma unroll
        for (int i = 0; i < 4; i++) {
            qv[2 * i]     = bflo(ws[i]) * SCALE2;
            qv[2 * i + 1] = bfhi(ws[i]) * SCALE2;
        }
    }

    float O[8];
#pragma unroll
    for (int i = 0; i < 8; i++) O[i] = 0.f;
    float lacc = 0.f;

    u32* mylist = list[wwarp];
    int cnt = 0, done = 0;
    const int* wrow = g_win + (size_t)q * N_NODES;

    for (int base = 0; base < N_NODES; base += 128) {
        int4 w4 = *(const int4*)&wrow[base + lane * 4];
        const int vv[4] = {w4.x, w4.y, w4.z, w4.w};
#pragma unroll
        for (int j = 0; j < 4; j++) {
            u32 m = __ballot_sync(0xffffffffu, vv[j] >= 0);
            if (vv[j] >= 0) {
                int pos = cnt + __popc(m & lmask_lt);
                mylist[pos] = ((u32)(base + lane * 4 + j) << 16) | (u32)vv[j];
            }
            cnt += __popc(m);
        }
        if (cnt >= CAP - 128) {          // flush (warp-uniform; effectively never)
            int c4 = cnt & ~3;
            corr_process(mylist, done, c4, qv, O, lacc, h, g, Kb, Vb);
            // move tail to front
            if (lane < (cnt - c4)) mylist[lane] = mylist[c4 + lane];
            cnt -= c4;
            done = 0;
        }
    }
    corr_process(mylist, done, cnt, qv, O, lacc, h, g, Kb, Vb);

    float* part = g_part + (size_t)KSPLIT * N_NODES * DMODEL + (size_t)q * DMODEL + h * DK + g * 8;
    *(float4*)&part[0] = make_float4(O[0], O[1], O[2], O[3]);
    *(float4*)&part[4] = make_float4(O[4], O[5], O[6], O[7]);
    if (g == 0)
        g_lp[((size_t)KSPLIT * N_NODES + q) * NHEAD + h] = lacc;
}

// ---------------- combine partials (deterministic) ----------------
__global__ __launch_bounds__(256) void combine_kernel() {
    int gid = blockIdx.x * 256 + threadIdx.x;   // 2048*64
    int row = gid >> 6;
    int col = (gid & 63) << 2;
    int h = col >> 5;
    float ls = 0.f;
    float4 acc = make_float4(0.f, 0.f, 0.f, 0.f);
#pragma unroll
    for (int c = 0; c < NSLOT; c++) {
        ls += g_lp[((size_t)c * N_NODES + row) * NHEAD + h];
        float4 p = *(const float4*)&g_part[((size_t)c * N_NODES + row) * DMODEL + col];
        acc.x += p.x; acc.y += p.y; acc.z += p.z; acc.w += p.w;
    }
    float inv = 1.f / ls;
    *(float4*)&g_attn[(size_t)row * DMODEL + col] =
        make_float4(acc.x * inv, acc.y * inv, acc.z * inv, acc.w * inv);
}

// ---------------- fused double LayerNorm ----------------
__global__ __launch_bounds__(256) void ln_kernel(const float* __restrict__ Y,
                                                 const float* __restrict__ g1,
                                                 const float* __restrict__ b1,
                                                 const float* __restrict__ g2,
                                                 const float* __restrict__ b2,
                                                 float* __restrict__ H1,
                                                 float* __restrict__ X2) {
    const int lane = threadIdx.x & 31;
    const int row  = blockIdx.x * 8 + (threadIdx.x >> 5);
    const float* y = Y + (size_t)row * DMODEL;
    float v[8];
#pragma unroll
    for (int j = 0; j < 8; j++) v[j] = y[lane + 32 * j];

    float s = 0.f;
#pragma unroll
    for (int j = 0; j < 8; j++) s += v[j];
#pragma unroll
    for (int o = 16; o; o >>= 1) s += __shfl_xor_sync(0xffffffffu, s, o);
    float mu = s * (1.f / 256.f);
    float q = 0.f;
#pragma unroll
    for (int j = 0; j < 8; j++) { float d = v[j] - mu; q += d * d; }
#pragma unroll
    for (int o = 16; o; o >>= 1) q += __shfl_xor_sync(0xffffffffu, q, o);
    float rs = rsqrtf(q * (1.f / 256.f) + 1e-5f);

    float hv[8];
#pragma unroll
    for (int j = 0; j < 8; j++) {
        int c = lane + 32 * j;
        hv[j] = (v[j] - mu) * rs * g1[c] + b1[c];
        H1[(size_t)row * DMODEL + c] = hv[j];
    }

    s = 0.f;
#pragma unroll
    for (int j = 0; j < 8; j++) s += hv[j];
#pragma unroll
    for (int o = 16; o; o >>= 1) s += __shfl_xor_sync(0xffffffffu, s, o);
    mu = s * (1.f / 256.f);
    q = 0.f;
#pragma unroll
    for (int j = 0; j < 8; j++) { float d = hv[j] - mu; q += d * d; }
#pragma unroll
    for (int o = 16; o; o >>= 1) q += __shfl_xor_sync(0xffffffffu, q, o);
    rs = rsqrtf(q * (1.f / 256.f) + 1e-5f);
#pragma unroll
    for (int j = 0; j < 8; j++) {
        int c = lane + 32 * j;
        X2[(size_t)row * DMODEL + c] = (hv[j] - mu) * rs * g2[c] + b2[c];
    }
}

// ---------------- launch ----------------
extern "C" void kernel_launch(void* const* d_in, const int* in_sizes, int n_in,
                              void* d_out, int out_size) {
    const float* h    = (const float*)d_in[0];
    const float* ea   = (const float*)d_in[1];
    const float* Wq   = (const float*)d_in[2];
    const float* bq   = (const float*)d_in[3];
    const float* Wk   = (const float*)d_in[4];
    const float* bk   = (const float*)d_in[5];
    const float* Wv   = (const float*)d_in[6];
    const float* bv   = (const float*)d_in[7];
    const float* Wo   = (const float*)d_in[8];
    const float* bo   = (const float*)d_in[9];
    const float* We   = (const float*)d_in[10];
    const float* be   = (const float*)d_in[11];
    const float* ln1g = (const float*)d_in[12];
    const float* ln1b = (const float*)d_in[13];
    const float* flng = (const float*)d_in[14];
    const float* flnb = (const float*)d_in[15];
    const float* W1   = (const float*)d_in[16];
    const float* b1   = (const float*)d_in[17];
    const float* W2   = (const float*)d_in[18];
    const float* b2   = (const float*)d_in[19];
    const int*   eidx = (const int*)d_in[20];
    float* out = (float*)d_out;

    __nv_bfloat16 *pQb, *pKb, *pVb;
    float *pAttn, *pY, *pH1, *pX2, *pG;
    cudaGetSymbolAddress((void**)&pQb,   g_Qb);
    cudaGetSymbolAddress((void**)&pKb,   g_Kb);
    cudaGetSymbolAddress((void**)&pVb,   g_Vb);
    cudaGetSymbolAddress((void**)&pAttn, g_attn);
    cudaGetSymbolAddress((void**)&pY,    g_Y);
    cudaGetSymbolAddress((void**)&pH1,   g_h1);
    cudaGetSymbolAddress((void**)&pX2,   g_x2);
    cudaGetSymbolAddress((void**)&pG,    g_G);

    reset_winner_kernel<<<1024, 1024>>>();
    edge_kernel<<<NEDGE / 256, 256>>>(ea, We, be, eidx);

    gemm_qkv<<<dim3(12, 32), 256>>>(h, Wq, bq, Wk, bk, Wv, bv);

    attn_mma<<<dim3(N_NODES / 64, NHEAD, KSPLIT), 128>>>(pQb, pKb, pVb);
    corr_kernel<<<N_NODES / 8, 256>>>(pQb, pKb, pVb);
    combine_kernel<<<(N_NODES * DMODEL / 4) / 256, 256>>>();

    gemm64<<<dim3(4, 32), 256>>>(pAttn, Wo, bo, h, pY, DMODEL, DMODEL, 0);

    ln_kernel<<<N_NODES / 8, 256>>>(pY, ln1g, ln1b, flng, flnb, pH1, pX2);

    gemm64<<<dim3(8, 32), 256>>>(pX2, W1, b1, nullptr, pG, HID, DMODEL, 1);
    gemm64<<<dim3(4, 32), 256>>>(pG, W2, b2, pH1, out, DMODEL, HID, 0);
}

// round 7
// speedup vs baseline: 1.5191x; 1.3588x over previous
#include <cuda_runtime.h>
#include <cuda_bf16.h>
#include <math.h>

#define N_NODES 2048
#define DMODEL  256
#define NHEAD   8
#define DK      32
#define NEDGE   65536
#define HID     512
#define KSPLIT  4
#define NSLOT   (KSPLIT + 1)
#define CAP     512

typedef unsigned long long ull;
typedef unsigned int u32;

// ---- mma / ldmatrix helpers ----
__device__ __forceinline__ u32 su32(const void* p) {
    return (u32)__cvta_generic_to_shared(p);
}
__device__ __forceinline__ void ldsm_x4(u32& r0, u32& r1, u32& r2, u32& r3, u32 a) {
    asm volatile("ldmatrix.sync.aligned.m8n8.x4.shared.b16 {%0,%1,%2,%3},[%4];"
                 : "=r"(r0), "=r"(r1), "=r"(r2), "=r"(r3) : "r"(a));
}
__device__ __forceinline__ void ldsm_x4t(u32& r0, u32& r1, u32& r2, u32& r3, u32 a) {
    asm volatile("ldmatrix.sync.aligned.m8n8.x4.trans.shared.b16 {%0,%1,%2,%3},[%4];"
                 : "=r"(r0), "=r"(r1), "=r"(r2), "=r"(r3) : "r"(a));
}
__device__ __forceinline__ void mma16816(float& c0, float& c1, float& c2, float& c3,
                                         u32 a0, u32 a1, u32 a2, u32 a3, u32 b0, u32 b1) {
    asm volatile("mma.sync.aligned.m16n8k16.row.col.f32.bf16.bf16.f32 "
                 "{%0,%1,%2,%3},{%4,%5,%6,%7},{%8,%9},{%0,%1,%2,%3};"
                 : "+f"(c0), "+f"(c1), "+f"(c2), "+f"(c3)
                 : "r"(a0), "r"(a1), "r"(a2), "r"(a3), "r"(b0), "r"(b1));
}
__device__ __forceinline__ float ex2f(float x) {
    float r; asm("ex2.approx.f32 %0,%1;" : "=f"(r) : "f"(x)); return r;
}
__device__ __forceinline__ u32 cvt2bf(float hi, float lo) {
    u32 r; asm("cvt.rn.bf16x2.f32 %0,%1,%2;" : "=r"(r) : "f"(hi), "f"(lo)); return r;
}
__device__ __forceinline__ float bflo(u32 w) { return __uint_as_float(w << 16); }
__device__ __forceinline__ float bfhi(u32 w) { return __uint_as_float(w & 0xffff0000u); }

// ---------------- scratch ----------------
__device__ __nv_bfloat16 g_hb[N_NODES * DMODEL];
__device__ __nv_bfloat16 g_Wqb[DMODEL * DMODEL];
__device__ __nv_bfloat16 g_Wkb[DMODEL * DMODEL];
__device__ __nv_bfloat16 g_Wvb[DMODEL * DMODEL];
__device__ __nv_bfloat16 g_Wob[DMODEL * DMODEL];
__device__ __nv_bfloat16 g_W1b[DMODEL * HID];
__device__ __nv_bfloat16 g_W2b[HID * DMODEL];
__device__ __nv_bfloat16 g_Qb[N_NODES * DMODEL];
__device__ __nv_bfloat16 g_Kb[N_NODES * DMODEL];
__device__ __nv_bfloat16 g_Vb[N_NODES * DMODEL];
__device__ __nv_bfloat16 g_attnb[N_NODES * DMODEL];
__device__ __nv_bfloat16 g_x2b[N_NODES * DMODEL];
__device__ __nv_bfloat16 g_Gb[N_NODES * HID];
__device__ float g_eb[NEDGE * NHEAD];                 // pre-scaled by log2(e)
__device__ int   g_win[N_NODES * N_NODES];
__device__ float g_part[NSLOT * N_NODES * DMODEL];
__device__ float g_lp[NSLOT * N_NODES * NHEAD];
__device__ float g_Y[N_NODES * DMODEL];
__device__ float g_h1[N_NODES * DMODEL];

// ---------------- reset winner map ----------------
__global__ __launch_bounds__(1024) void reset_winner_kernel() {
    int i = blockIdx.x * blockDim.x + threadIdx.x;
    ((int4*)g_win)[i] = make_int4(-1, -1, -1, -1);
}

// ---------------- fp32 -> bf16 conversions (h + weights) ----------------
__global__ __launch_bounds__(256) void conv_kernel(const float* __restrict__ h,
                                                   const float* __restrict__ Wq,
                                                   const float* __restrict__ Wk,
                                                   const float* __restrict__ Wv,
                                                   const float* __restrict__ Wo,
                                                   const float* __restrict__ W1,
                                                   const float* __restrict__ W2) {
    int gid = blockIdx.x * 256 + threadIdx.x;   // 262144 float4 tasks
    const float* src; __nv_bfloat16* dst; int off;
    if (gid < 131072)      { src = h;  dst = g_hb;  off = gid; }
    else if (gid < 147456) { src = Wq; dst = g_Wqb; off = gid - 131072; }
    else if (gid < 163840) { src = Wk; dst = g_Wkb; off = gid - 147456; }
    else if (gid < 180224) { src = Wv; dst = g_Wvb; off = gid - 163840; }
    else if (gid < 196608) { src = Wo; dst = g_Wob; off = gid - 180224; }
    else if (gid < 229376) { src = W1; dst = g_W1b; off = gid - 196608; }
    else                   { src = W2; dst = g_W2b; off = gid - 229376; }
    float4 v = ((const float4*)src)[off];
    uint2 p;
    p.x = cvt2bf(v.y, v.x);
    p.y = cvt2bf(v.w, v.z);
    ((uint2*)dst)[off] = p;
}

// ---------------- edge bias (log2e-scaled) + scatter winner ----------------
__global__ __launch_bounds__(256) void edge_kernel(const float* __restrict__ ea,
                                                   const float* __restrict__ We,
                                                   const float* __restrict__ be,
                                                   const int*   __restrict__ eidx) {
    const float L2E = 1.4426950408889634f;
    int e = blockIdx.x * blockDim.x + threadIdx.x;
    float a[7];
#pragma unroll
    for (int j = 0; j < 7; j++) a[j] = ea[e * 7 + j];
#pragma unroll
    for (int hh = 0; hh < 8; hh++) {
        float v = be[hh];
#pragma unroll
        for (int j = 0; j < 7; j++) v += a[j] * We[j * 8 + hh];
        g_eb[e * 8 + hh] = v * L2E;
    }
    int src = eidx[e];
    int dst = eidx[NEDGE + e];
    atomicMax(&g_win[src * N_NODES + dst], e);
}

// ---------------- bf16 tensor-core GEMM: 64x64 tile, BK=16, 4 warps ----------------
__device__ __forceinline__ void gemm_bf16_body(const __nv_bfloat16* __restrict__ A,
                                               const __nv_bfloat16* __restrict__ B,
                                               const float* __restrict__ bias,
                                               const float* __restrict__ R,
                                               float* __restrict__ Cf,
                                               __nv_bfloat16* __restrict__ Cb,
                                               int N, int K, int gelu,
                                               int bm, int bn) {
    __shared__ __align__(16) __nv_bfloat16 As[64][24];   // 48B rows (3r mod 8 distinct)
    __shared__ __align__(16) __nv_bfloat16 Bs[16][72];   // 144B rows (9r mod 8 distinct)
    const int tid = threadIdx.x, warp = tid >> 5, lane = tid & 31;
    const int lr = lane & 7, lm = lane >> 3;
    const int arow = tid >> 1, ac = (tid & 1) * 8;
    const int brow = tid >> 3, bc = (tid & 7) * 8;

    float acc[8][4] = {};
    const u32 aaddr = su32(&As[warp * 16 + lr + (lm & 1) * 8][(lm >> 1) * 8]);
    const u32 baddr = su32(&Bs[lr + (lm & 1) * 8][(lm >> 1) * 8]);

    for (int k0 = 0; k0 < K; k0 += 16) {
        uint4 av = *(const uint4*)(A + (size_t)(bm + arow) * K + k0 + ac);
        uint4 bv = *(const uint4*)(B + (size_t)(k0 + brow) * N + bn + bc);
        __syncthreads();
        *(uint4*)&As[arow][ac] = av;
        *(uint4*)&Bs[brow][bc] = bv;
        __syncthreads();
        u32 a0, a1, a2, a3;
        ldsm_x4(a0, a1, a2, a3, aaddr);
#pragma unroll
        for (int ng = 0; ng < 4; ng++) {
            u32 b0, b1, b2, b3;
            ldsm_x4t(b0, b1, b2, b3, baddr + ng * 32);
            mma16816(acc[ng * 2][0], acc[ng * 2][1], acc[ng * 2][2], acc[ng * 2][3],
                     a0, a1, a2, a3, b0, b1);
            mma16816(acc[ng * 2 + 1][0], acc[ng * 2 + 1][1], acc[ng * 2 + 1][2], acc[ng * 2 + 1][3],
                     a0, a1, a2, a3, b2, b3);
        }
    }

    const int rr = lane >> 2, cql = 2 * (lane & 3);
    const int r0 = bm + warp * 16 + rr, r1 = r0 + 8;
#pragma unroll
    for (int ng = 0; ng < 4; ng++) {
#pragma unroll
        for (int tp = 0; tp < 2; tp++) {
            const int idx = ng * 2 + tp;
            const int col = bn + ng * 16 + tp * 8 + cql;
            float b0 = bias[col], b1 = bias[col + 1];
            float o0 = acc[idx][0] + b0, o1 = acc[idx][1] + b1;
            float o2 = acc[idx][2] + b0, o3 = acc[idx][3] + b1;
            if (gelu) {
                o0 *= normcdff(o0); o1 *= normcdff(o1);
                o2 *= normcdff(o2); o3 *= normcdff(o3);
            }
            if (R) {
                o0 += R[(size_t)r0 * N + col]; o1 += R[(size_t)r0 * N + col + 1];
                o2 += R[(size_t)r1 * N + col]; o3 += R[(size_t)r1 * N + col + 1];
            }
            if (Cb) {
                *(u32*)&Cb[(size_t)r0 * N + col] = cvt2bf(o1, o0);
                *(u32*)&Cb[(size_t)r1 * N + col] = cvt2bf(o3, o2);
            } else {
                *(float2*)&Cf[(size_t)r0 * N + col] = make_float2(o0, o1);
                *(float2*)&Cf[(size_t)r1 * N + col] = make_float2(o2, o3);
            }
        }
    }
}

__global__ __launch_bounds__(128) void gemm_bf16(const __nv_bfloat16* __restrict__ A,
                                                 const __nv_bfloat16* __restrict__ B,
                                                 const float* __restrict__ bias,
                                                 const float* __restrict__ R,
                                                 float* __restrict__ Cf,
                                                 __nv_bfloat16* __restrict__ Cb,
                                                 int N, int K, int gelu) {
    gemm_bf16_body(A, B, bias, R, Cf, Cb, N, K, gelu, blockIdx.y * 64, blockIdx.x * 64);
}

// fused QKV: grid.x = 12 (3 matrices x 4 col tiles)
__global__ __launch_bounds__(128) void gemm_qkv_bf16(const float* __restrict__ bq,
                                                     const float* __restrict__ bk,
                                                     const float* __restrict__ bv) {
    int sel = blockIdx.x >> 2;
    int bn  = (blockIdx.x & 3) * 64;
    const __nv_bfloat16* B = (sel == 0) ? g_Wqb : (sel == 1) ? g_Wkb : g_Wvb;
    const float* bias      = (sel == 0) ? bq : (sel == 1) ? bk : bv;
    __nv_bfloat16* Cb      = (sel == 0) ? g_Qb : (sel == 1) ? g_Kb : g_Vb;
    gemm_bf16_body(g_hb, B, bias, nullptr, nullptr, Cb, DMODEL, DMODEL, 0,
                   blockIdx.y * 64, bn);
}

// ---------------- dense tensor-core flash attention, split-K, NO bias ----------
__global__ __launch_bounds__(128, 5) void attn_mma(const __nv_bfloat16* __restrict__ Qb,
                                                   const __nv_bfloat16* __restrict__ Kb,
                                                   const __nv_bfloat16* __restrict__ Vb) {
    __shared__ __align__(16) __nv_bfloat16 Ks[64][40];
    __shared__ __align__(16) __nv_bfloat16 Vs[64][40];

    const int h     = blockIdx.y;
    const int qb    = blockIdx.x * 64;
    const int chunk = blockIdx.z;
    const int kb0   = chunk * (N_NODES / KSPLIT);
    const int tid = threadIdx.x;
    const int warp = tid >> 5, lane = tid & 31;

#pragma unroll
    for (int i = 0; i < 2; i++) {
        int task = tid + 128 * i;
        int row = task >> 2, ch = task & 3;
        uint4 v = *(const uint4*)((const char*)(Qb + (size_t)(qb + row) * DMODEL + h * DK) + ch * 16);
        *(uint4*)((char*)&Ks[row][0] + ch * 16) = v;
    }
    __syncthreads();
    const int lr = lane & 7, lm = lane >> 3;
    u32 qa[2][4];
    {
        int row = warp * 16 + lr + (lm & 1) * 8;
#pragma unroll
        for (int c = 0; c < 2; c++) {
            u32 a = su32(&Ks[row][c * 16 + (lm >> 1) * 8]);
            ldsm_x4(qa[c][0], qa[c][1], qa[c][2], qa[c][3], a);
        }
    }

    const u32 kaddr = su32(&Ks[lr][lm * 8]);
    const u32 vaddr = su32(&Vs[lr + (lm & 1) * 8][(lm >> 1) * 8]);

    float O[4][4];
#pragma unroll
    for (int t = 0; t < 4; t++)
#pragma unroll
        for (int j = 0; j < 4; j++) O[t][j] = 0.f;
    float l0 = 0.f, l1 = 0.f;

    const float SCALE2 = 1.4426950408889634f * 0.17677669529663688f;

    for (int kt = 0; kt < (N_NODES / KSPLIT) / 64; kt++) {
        const int kb = kb0 + kt * 64;
        __syncthreads();
#pragma unroll
        for (int i = 0; i < 2; i++) {
            int task = tid + 128 * i;
            int row = task >> 2, ch = task & 3;
            const char* kp = (const char*)(Kb + (size_t)(kb + row) * DMODEL + h * DK) + ch * 16;
            const char* vp = (const char*)(Vb + (size_t)(kb + row) * DMODEL + h * DK) + ch * 16;
            *(uint4*)((char*)&Ks[row][0] + ch * 16) = *(const uint4*)kp;
            *(uint4*)((char*)&Vs[row][0] + ch * 16) = *(const uint4*)vp;
        }
        __syncthreads();

        u32 P[8][2];
#pragma unroll
        for (int kg = 0; kg < 8; kg++) {
            u32 b0, b1, b2, b3;
            ldsm_x4(b0, b1, b2, b3, kaddr + kg * 640);
            float c0 = 0.f, c1 = 0.f, c2 = 0.f, c3 = 0.f;
            mma16816(c0, c1, c2, c3, qa[0][0], qa[0][1], qa[0][2], qa[0][3], b0, b1);
            mma16816(c0, c1, c2, c3, qa[1][0], qa[1][1], qa[1][2], qa[1][3], b2, b3);
            float p0 = ex2f(c0 * SCALE2);
            float p1 = ex2f(c1 * SCALE2);
            float p2 = ex2f(c2 * SCALE2);
            float p3 = ex2f(c3 * SCALE2);
            l0 += p0 + p1;
            l1 += p2 + p3;
            P[kg][0] = cvt2bf(p1, p0);
            P[kg][1] = cvt2bf(p3, p2);
        }

#pragma unroll
        for (int ck = 0; ck < 4; ck++) {
            u32 a0 = P[2 * ck][0], a1 = P[2 * ck][1];
            u32 a2 = P[2 * ck + 1][0], a3 = P[2 * ck + 1][1];
#pragma unroll
            for (int tp = 0; tp < 2; tp++) {
                u32 v0, v1, v2, v3;
                ldsm_x4t(v0, v1, v2, v3, vaddr + ck * 1280 + tp * 32);
                mma16816(O[2 * tp][0], O[2 * tp][1], O[2 * tp][2], O[2 * tp][3],
                         a0, a1, a2, a3, v0, v1);
                mma16816(O[2 * tp + 1][0], O[2 * tp + 1][1], O[2 * tp + 1][2], O[2 * tp + 1][3],
                         a0, a1, a2, a3, v2, v3);
            }
        }
    }

    l0 += __shfl_xor_sync(0xffffffffu, l0, 1);
    l0 += __shfl_xor_sync(0xffffffffu, l0, 2);
    l1 += __shfl_xor_sync(0xffffffffu, l1, 1);
    l1 += __shfl_xor_sync(0xffffffffu, l1, 2);

    const int r0 = qb + warp * 16 + (lane >> 2);
    const int r1 = r0 + 8;
    const int cql = 2 * (lane & 3);

    float* part = g_part + (size_t)chunk * N_NODES * DMODEL;
#pragma unroll
    for (int t = 0; t < 4; t++) {
        int col = h * DK + t * 8 + cql;
        *(float2*)&part[(size_t)r0 * DMODEL + col] = make_float2(O[t][0], O[t][1]);
        *(float2*)&part[(size_t)r1 * DMODEL + col] = make_float2(O[t][2], O[t][3]);
    }
    if ((lane & 3) == 0) {
        g_lp[((size_t)chunk * N_NODES + r0) * NHEAD + h] = l0;
        g_lp[((size_t)chunk * N_NODES + r1) * NHEAD + h] = l1;
    }
}

// ---------------- sparse bias correction ----------------
__device__ __forceinline__ void corr_process(const u32* mylist, int i0, int cnt,
                                             const float* qv, float* O, float& lacc,
                                             int h, int g,
                                             const __nv_bfloat16* __restrict__ Kb,
                                             const __nv_bfloat16* __restrict__ Vb) {
    for (int i = i0; i < cnt; i += 4) {
#pragma unroll
        for (int j = 0; j < 4; j++) {
            if (i + j >= cnt) break;
            u32 e = mylist[i + j];
            int k    = (int)(e >> 16);
            int widx = (int)(e & 0xFFFFu);
            uint4 kw = *(const uint4*)(Kb + (size_t)k * DMODEL + h * DK + g * 8);
            uint4 vw = *(const uint4*)(Vb + (size_t)k * DMODEL + h * DK + g * 8);
            float eb = g_eb[(size_t)widx * 8 + h];
            const u32 ks[4] = {kw.x, kw.y, kw.z, kw.w};
            float s = 0.f;
#pragma unroll
            for (int t = 0; t < 4; t++) {
                s += qv[2 * t] * bflo(ks[t]);
                s += qv[2 * t + 1] * bfhi(ks[t]);
            }
            s += __shfl_xor_sync(0xffffffffu, s, 1);
            s += __shfl_xor_sync(0xffffffffu, s, 2);
            float pd = ex2f(s + eb) - ex2f(s);
            lacc += pd;
            const u32 vs[4] = {vw.x, vw.y, vw.z, vw.w};
#pragma unroll
            for (int t = 0; t < 4; t++) {
                O[2 * t]     += pd * bflo(vs[t]);
                O[2 * t + 1] += pd * bfhi(vs[t]);
            }
        }
    }
}

__global__ __launch_bounds__(256) void corr_kernel(const __nv_bfloat16* __restrict__ Qb,
                                                   const __nv_bfloat16* __restrict__ Kb,
                                                   const __nv_bfloat16* __restrict__ Vb) {
    __shared__ u32 list[8][CAP];
    const int wwarp = threadIdx.x >> 5;
    const int q     = blockIdx.x * 8 + wwarp;
    const int lane  = threadIdx.x & 31;
    const int h = lane >> 2, g = lane & 3;
    const float SCALE2 = 1.4426950408889634f * 0.17677669529663688f;
    const u32 lmask_lt = (1u << lane) - 1u;

    float qv[8];
    {
        uint4 w = *(const uint4*)(Qb + (size_t)q * DMODEL + h * DK + g * 8);
        const u32 ws[4] = {w.x, w.y, w.z, w.w};
#pragma unroll
        for (int i = 0; i < 4; i++) {
            qv[2 * i]     = bflo(ws[i]) * SCALE2;
            qv[2 * i + 1] = bfhi(ws[i]) * SCALE2;
        }
    }

    float O[8];
#pragma unroll
    for (int i = 0; i < 8; i++) O[i] = 0.f;
    float lacc = 0.f;

    u32* mylist = list[wwarp];
    int cnt = 0, done = 0;
    const int* wrow = g_win + (size_t)q * N_NODES;

    for (int base = 0; base < N_NODES; base += 128) {
        int4 w4 = *(const int4*)&wrow[base + lane * 4];
        const int vv[4] = {w4.x, w4.y, w4.z, w4.w};
#pragma unroll
        for (int j = 0; j < 4; j++) {
            u32 m = __ballot_sync(0xffffffffu, vv[j] >= 0);
            if (vv[j] >= 0) {
                int pos = cnt + __popc(m & lmask_lt);
                mylist[pos] = ((u32)(base + lane * 4 + j) << 16) | (u32)vv[j];
            }
            cnt += __popc(m);
        }
        if (cnt >= CAP - 128) {
            int c4 = cnt & ~3;
            corr_process(mylist, done, c4, qv, O, lacc, h, g, Kb, Vb);
            if (lane < (cnt - c4)) mylist[lane] = mylist[c4 + lane];
            cnt -= c4;
            done = 0;
        }
    }
    corr_process(mylist, done, cnt, qv, O, lacc, h, g, Kb, Vb);

    float* part = g_part + (size_t)KSPLIT * N_NODES * DMODEL + (size_t)q * DMODEL + h * DK + g * 8;
    *(float4*)&part[0] = make_float4(O[0], O[1], O[2], O[3]);
    *(float4*)&part[4] = make_float4(O[4], O[5], O[6], O[7]);
    if (g == 0)
        g_lp[((size_t)KSPLIT * N_NODES + q) * NHEAD + h] = lacc;
}

// ---------------- combine partials -> bf16 attn ----------------
__global__ __launch_bounds__(256) void combine_kernel() {
    int gid = blockIdx.x * 256 + threadIdx.x;   // 2048*64
    int row = gid >> 6;
    int col = (gid & 63) << 2;
    int h = col >> 5;
    float ls = 0.f;
    float4 acc = make_float4(0.f, 0.f, 0.f, 0.f);
#pragma unroll
    for (int c = 0; c < NSLOT; c++) {
        ls += g_lp[((size_t)c * N_NODES + row) * NHEAD + h];
        float4 p = *(const float4*)&g_part[((size_t)c * N_NODES + row) * DMODEL + col];
        acc.x += p.x; acc.y += p.y; acc.z += p.z; acc.w += p.w;
    }
    float inv = 1.f / ls;
    uint2 p;
    p.x = cvt2bf(acc.y * inv, acc.x * inv);
    p.y = cvt2bf(acc.w * inv, acc.z * inv);
    *(uint2*)&g_attnb[(size_t)row * DMODEL + col] = p;
}

// ---------------- fused double LayerNorm: Y -> h1 (fp32), fln(h1) -> x2 (bf16) ----
__global__ __launch_bounds__(256) void ln_kernel(const float* __restrict__ Y,
                                                 const float* __restrict__ g1,
                                                 const float* __restrict__ b1,
                                                 const float* __restrict__ g2,
                                                 const float* __restrict__ b2,
                                                 float* __restrict__ H1,
                                                 __nv_bfloat16* __restrict__ X2b) {
    const int lane = threadIdx.x & 31;
    const int row  = blockIdx.x * 8 + (threadIdx.x >> 5);
    const float4* y4 = (const float4*)(Y + (size_t)row * DMODEL);
    float v[8];
    {
        float4 a = y4[lane * 2], b = y4[lane * 2 + 1];
        v[0] = a.x; v[1] = a.y; v[2] = a.z; v[3] = a.w;
        v[4] = b.x; v[5] = b.y; v[6] = b.z; v[7] = b.w;
    }

    float s = 0.f;
#pragma unroll
    for (int j = 0; j < 8; j++) s += v[j];
#pragma unroll
    for (int o = 16; o; o >>= 1) s += __shfl_xor_sync(0xffffffffu, s, o);
    float mu = s * (1.f / 256.f);
    float q = 0.f;
#pragma unroll
    for (int j = 0; j < 8; j++) { float d = v[j] - mu; q += d * d; }
#pragma unroll
    for (int o = 16; o; o >>= 1) q += __shfl_xor_sync(0xffffffffu, q, o);
    float rs = rsqrtf(q * (1.f / 256.f) + 1e-5f);

    const int c0 = lane * 8;
    float hv[8];
#pragma unroll
    for (int j = 0; j < 8; j++)
        hv[j] = (v[j] - mu) * rs * g1[c0 + j] + b1[c0 + j];
    {
        float4* h4 = (float4*)(H1 + (size_t)row * DMODEL + c0);
        h4[0] = make_float4(hv[0], hv[1], hv[2], hv[3]);
        h4[1] = make_float4(hv[4], hv[5], hv[6], hv[7]);
    }

    s = 0.f;
#pragma unroll
    for (int j = 0; j < 8; j++) s += hv[j];
#pragma unroll
    for (int o = 16; o; o >>= 1) s += __shfl_xor_sync(0xffffffffu, s, o);
    mu = s * (1.f / 256.f);
    q = 0.f;
#pragma unroll
    for (int j = 0; j < 8; j++) { float d = hv[j] - mu; q += d * d; }
#pragma unroll
    for (int o = 16; o; o >>= 1) q += __shfl_xor_sync(0xffffffffu, q, o);
    rs = rsqrtf(q * (1.f / 256.f) + 1e-5f);

    uint4 px;
    float x0 = (hv[0] - mu) * rs * g2[c0 + 0] + b2[c0 + 0];
    float x1 = (hv[1] - mu) * rs * g2[c0 + 1] + b2[c0 + 1];
    float x2 = (hv[2] - mu) * rs * g2[c0 + 2] + b2[c0 + 2];
    float x3 = (hv[3] - mu) * rs * g2[c0 + 3] + b2[c0 + 3];
    float x4 = (hv[4] - mu) * rs * g2[c0 + 4] + b2[c0 + 4];
    float x5 = (hv[5] - mu) * rs * g2[c0 + 5] + b2[c0 + 5];
    float x6 = (hv[6] - mu) * rs * g2[c0 + 6] + b2[c0 + 6];
    float x7 = (hv[7] - mu) * rs * g2[c0 + 7] + b2[c0 + 7];
    px.x = cvt2bf(x1, x0);
    px.y = cvt2bf(x3, x2);
    px.z = cvt2bf(x5, x4);
    px.w = cvt2bf(x7, x6);
    *(uint4*)&X2b[(size_t)row * DMODEL + c0] = px;
}

// ---------------- launch ----------------
extern "C" void kernel_launch(void* const* d_in, const int* in_sizes, int n_in,
                              void* d_out, int out_size) {
    const float* h    = (const float*)d_in[0];
    const float* ea   = (const float*)d_in[1];
    const float* Wq   = (const float*)d_in[2];
    const float* bq   = (const float*)d_in[3];
    const float* Wk   = (const float*)d_in[4];
    const float* bk   = (const float*)d_in[5];
    const float* Wv   = (const float*)d_in[6];
    const float* bv   = (const float*)d_in[7];
    const float* Wo   = (const float*)d_in[8];
    const float* bo   = (const float*)d_in[9];
    const float* We   = (const float*)d_in[10];
    const float* be   = (const float*)d_in[11];
    const float* ln1g = (const float*)d_in[12];
    const float* ln1b = (const float*)d_in[13];
    const float* flng = (const float*)d_in[14];
    const float* flnb = (const float*)d_in[15];
    const float* W1   = (const float*)d_in[16];
    const float* b1   = (const float*)d_in[17];
    const float* W2   = (const float*)d_in[18];
    const float* b2   = (const float*)d_in[19];
    const int*   eidx = (const int*)d_in[20];
    float* out = (float*)d_out;

    __nv_bfloat16 *pQb, *pKb, *pVb, *pAttnb, *pX2b, *pGb, *pWob, *pW1b, *pW2b;
    float *pY, *pH1;
    cudaGetSymbolAddress((void**)&pQb,    g_Qb);
    cudaGetSymbolAddress((void**)&pKb,    g_Kb);
    cudaGetSymbolAddress((void**)&pVb,    g_Vb);
    cudaGetSymbolAddress((void**)&pAttnb, g_attnb);
    cudaGetSymbolAddress((void**)&pX2b,   g_x2b);
    cudaGetSymbolAddress((void**)&pGb,    g_Gb);
    cudaGetSymbolAddress((void**)&pWob,   g_Wob);
    cudaGetSymbolAddress((void**)&pW1b,   g_W1b);
    cudaGetSymbolAddress((void**)&pW2b,   g_W2b);
    cudaGetSymbolAddress((void**)&pY,     g_Y);
    cudaGetSymbolAddress((void**)&pH1,    g_h1);

    conv_kernel<<<1024, 256>>>(h, Wq, Wk, Wv, Wo, W1, W2);
    reset_winner_kernel<<<1024, 1024>>>();
    edge_kernel<<<NEDGE / 256, 256>>>(ea, We, be, eidx);

    gemm_qkv_bf16<<<dim3(12, 32), 128>>>(bq, bk, bv);

    attn_mma<<<dim3(N_NODES / 64, NHEAD, KSPLIT), 128>>>(pQb, pKb, pVb);
    corr_kernel<<<N_NODES / 8, 256>>>(pQb, pKb, pVb);
    combine_kernel<<<(N_NODES * DMODEL / 4) / 256, 256>>>();

    gemm_bf16<<<dim3(4, 32), 128>>>(pAttnb, pWob, bo, h, pY, nullptr,
                                    DMODEL, DMODEL, 0);

    ln_kernel<<<N_NODES / 8, 256>>>(pY, ln1g, ln1b, flng, flnb, pH1, pX2b);

    gemm_bf16<<<dim3(8, 32), 128>>>(pX2b, pW1b, b1, nullptr, nullptr, pGb,
                                    HID, DMODEL, 1);
    gemm_bf16<<<dim3(4, 32), 128>>>(pGb, pW2b, b2, pH1, out, nullptr,
                                    DMODEL, HID, 0);
}

// round 8
// speedup vs baseline: 1.7068x; 1.1235x over previous
#include <cuda_runtime.h>
#include <cuda_bf16.h>
#include <math.h>

#define N_NODES 2048
#define DMODEL  256
#define NHEAD   8
#define DK      32
#define NEDGE   65536
#define HID     512
#define KSPLIT  4
#define NSLOT   (KSPLIT + 1)
#define CAPL    256

typedef unsigned long long ull;
typedef unsigned int u32;

// ---- mma / ldmatrix / cp.async helpers ----
__device__ __forceinline__ u32 su32(const void* p) {
    return (u32)__cvta_generic_to_shared(p);
}
__device__ __forceinline__ void ldsm_x4(u32& r0, u32& r1, u32& r2, u32& r3, u32 a) {
    asm volatile("ldmatrix.sync.aligned.m8n8.x4.shared.b16 {%0,%1,%2,%3},[%4];"
                 : "=r"(r0), "=r"(r1), "=r"(r2), "=r"(r3) : "r"(a));
}
__device__ __forceinline__ void ldsm_x4t(u32& r0, u32& r1, u32& r2, u32& r3, u32 a) {
    asm volatile("ldmatrix.sync.aligned.m8n8.x4.trans.shared.b16 {%0,%1,%2,%3},[%4];"
                 : "=r"(r0), "=r"(r1), "=r"(r2), "=r"(r3) : "r"(a));
}
__device__ __forceinline__ void mma16816(float& c0, float& c1, float& c2, float& c3,
                                         u32 a0, u32 a1, u32 a2, u32 a3, u32 b0, u32 b1) {
    asm volatile("mma.sync.aligned.m16n8k16.row.col.f32.bf16.bf16.f32 "
                 "{%0,%1,%2,%3},{%4,%5,%6,%7},{%8,%9},{%0,%1,%2,%3};"
                 : "+f"(c0), "+f"(c1), "+f"(c2), "+f"(c3)
                 : "r"(a0), "r"(a1), "r"(a2), "r"(a3), "r"(b0), "r"(b1));
}
__device__ __forceinline__ float ex2f(float x) {
    float r; asm("ex2.approx.f32 %0,%1;" : "=f"(r) : "f"(x)); return r;
}
__device__ __forceinline__ u32 cvt2bf(float hi, float lo) {
    u32 r; asm("cvt.rn.bf16x2.f32 %0,%1,%2;" : "=r"(r) : "f"(hi), "f"(lo)); return r;
}
__device__ __forceinline__ float bflo(u32 w) { return __uint_as_float(w << 16); }
__device__ __forceinline__ float bfhi(u32 w) { return __uint_as_float(w & 0xffff0000u); }
__device__ __forceinline__ void cp16(u32 dst, const void* src) {
    asm volatile("cp.async.ca.shared.global [%0],[%1],16;" :: "r"(dst), "l"(src));
}

// ---------------- scratch ----------------
__device__ __nv_bfloat16 g_hb[N_NODES * DMODEL];
__device__ __nv_bfloat16 g_Wqb[DMODEL * DMODEL];
__device__ __nv_bfloat16 g_Wkb[DMODEL * DMODEL];
__device__ __nv_bfloat16 g_Wvb[DMODEL * DMODEL];
__device__ __nv_bfloat16 g_Wob[DMODEL * DMODEL];
__device__ __nv_bfloat16 g_W1b[DMODEL * HID];
__device__ __nv_bfloat16 g_W2b[HID * DMODEL];
__device__ __nv_bfloat16 g_Qb[N_NODES * DMODEL];
__device__ __nv_bfloat16 g_Kb[N_NODES * DMODEL];
__device__ __nv_bfloat16 g_Vb[N_NODES * DMODEL];
__device__ __nv_bfloat16 g_attnb[N_NODES * DMODEL];
__device__ __nv_bfloat16 g_x2b[N_NODES * DMODEL];
__device__ __nv_bfloat16 g_Gb[N_NODES * HID];
__device__ float g_eb[NEDGE * NHEAD];                 // pre-scaled by log2(e)
__device__ int   g_win[N_NODES * N_NODES];
__device__ int   g_cnt[N_NODES];
__device__ u32   g_list[N_NODES * CAPL];
__device__ float g_part[NSLOT * N_NODES * DMODEL];
__device__ float g_lp[NSLOT * N_NODES * NHEAD];
__device__ float g_Y[N_NODES * DMODEL];
__device__ float g_h1[N_NODES * DMODEL];

// ---------------- reset winner map + counters ----------------
__global__ __launch_bounds__(1024) void reset_winner_kernel() {
    int i = blockIdx.x * blockDim.x + threadIdx.x;
    ((int4*)g_win)[i] = make_int4(-1, -1, -1, -1);
    if (i < N_NODES / 4) ((int4*)g_cnt)[i] = make_int4(0, 0, 0, 0);
}

// ---------------- fp32 -> bf16 conversions (h + weights) ----------------
__global__ __launch_bounds__(256) void conv_kernel(const float* __restrict__ h,
                                                   const float* __restrict__ Wq,
                                                   const float* __restrict__ Wk,
                                                   const float* __restrict__ Wv,
                                                   const float* __restrict__ Wo,
                                                   const float* __restrict__ W1,
                                                   const float* __restrict__ W2) {
    int gid = blockIdx.x * 256 + threadIdx.x;   // 262144 float4 tasks
    const float* src; __nv_bfloat16* dst; int off;
    if (gid < 131072)      { src = h;  dst = g_hb;  off = gid; }
    else if (gid < 147456) { src = Wq; dst = g_Wqb; off = gid - 131072; }
    else if (gid < 163840) { src = Wk; dst = g_Wkb; off = gid - 147456; }
    else if (gid < 180224) { src = Wv; dst = g_Wvb; off = gid - 163840; }
    else if (gid < 196608) { src = Wo; dst = g_Wob; off = gid - 180224; }
    else if (gid < 229376) { src = W1; dst = g_W1b; off = gid - 196608; }
    else                   { src = W2; dst = g_W2b; off = gid - 229376; }
    float4 v = ((const float4*)src)[off];
    uint2 p;
    p.x = cvt2bf(v.y, v.x);
    p.y = cvt2bf(v.w, v.z);
    ((uint2*)dst)[off] = p;
}

// ---------------- edge bias (log2e-scaled) + scatter winner ----------------
__global__ __launch_bounds__(256) void edge_kernel(const float* __restrict__ ea,
                                                   const float* __restrict__ We,
                                                   const float* __restrict__ be,
                                                   const int*   __restrict__ eidx) {
    const float L2E = 1.4426950408889634f;
    int e = blockIdx.x * blockDim.x + threadIdx.x;
    float a[7];
#pragma unroll
    for (int j = 0; j < 7; j++) a[j] = ea[e * 7 + j];
#pragma unroll
    for (int hh = 0; hh < 8; hh++) {
        float v = be[hh];
#pragma unroll
        for (int j = 0; j < 7; j++) v += a[j] * We[j * 8 + hh];
        g_eb[e * 8 + hh] = v * L2E;
    }
    int src = eidx[e];
    int dst = eidx[NEDGE + e];
    atomicMax(&g_win[src * N_NODES + dst], e);
}

// ---------------- winner-edge list extraction ----------------
__global__ __launch_bounds__(256) void winner_kernel(const int* __restrict__ eidx) {
    int e = blockIdx.x * 256 + threadIdx.x;
    int src = eidx[e];
    int dst = eidx[NEDGE + e];
    if (g_win[(size_t)src * N_NODES + dst] == e) {
        int pos = atomicAdd(&g_cnt[src], 1);
        if (pos < CAPL) g_list[(size_t)src * CAPL + pos] = ((u32)dst << 16) | (u32)e;
    }
}

// ---------------- bf16 tensor-core GEMM: 32x64 tile, BK=32, cp.async 3-stage ------
__device__ __forceinline__ void gemm_bf16_body(const __nv_bfloat16* __restrict__ A,
                                               const __nv_bfloat16* __restrict__ B,
                                               const float* __restrict__ bias,
                                               const float* __restrict__ R,
                                               float* __restrict__ Cf,
                                               __nv_bfloat16* __restrict__ Cb,
                                               int N, int K, int gelu,
                                               int bm, int bn) {
    __shared__ __align__(16) __nv_bfloat16 As[3][32][40];   // 80B rows
    __shared__ __align__(16) __nv_bfloat16 Bs[3][32][72];   // 144B rows
    const int tid = threadIdx.x, warp = tid >> 5, lane = tid & 31;
    const int wm = warp & 1, wn = warp >> 1;
    const int lr = lane & 7, lm = lane >> 3;

    const int ar = tid >> 2, ac = tid & 3;          // A: row 0..31, 16B chunk 0..3
    const int br0 = tid >> 3, bc = tid & 7;         // B: rows 0..15 / 16..31
    const int br1 = br0 + 16;

    const u32 sA = su32(&As[0][0][0]);
    const u32 sB = su32(&Bs[0][0][0]);
    const u32 dstA  = sA + ar * 80 + ac * 16;
    const u32 dstB0 = sB + br0 * 144 + bc * 16;
    const u32 dstB1 = sB + br1 * 144 + bc * 16;
    const __nv_bfloat16* srcA = A + (size_t)(bm + ar) * K + ac * 8;

    const int Kk = K >> 5;
    float acc[4][4] = {};

    auto issue = [&](int kb, int st) {
        if (kb < Kk) {
            cp16(dstA + st * 2560, srcA + kb * 32);
            cp16(dstB0 + st * 4608, B + (size_t)(kb * 32 + br0) * N + bn + bc * 8);
            cp16(dstB1 + st * 4608, B + (size_t)(kb * 32 + br1) * N + bn + bc * 8);
        }
        asm volatile("cp.async.commit_group;");
    };
    issue(0, 0);
    issue(1, 1);

    const u32 aBase = sA + (wm * 16 + lr + (lm & 1) * 8) * 80 + (lm >> 1) * 16;
    const u32 bBase = sB + (lr + (lm & 1) * 8) * 144 + (wn * 32 + (lm >> 1) * 8) * 2;

    for (int kb = 0; kb < Kk; kb++) {
        asm volatile("cp.async.wait_group 1;");
        __syncthreads();
        issue(kb + 2, (kb + 2) % 3);
        const u32 aS = aBase + (kb % 3) * 2560;
        const u32 bS = bBase + (kb % 3) * 4608;
#pragma unroll
        for (int ks = 0; ks < 2; ks++) {
            u32 a0, a1, a2, a3;
            ldsm_x4(a0, a1, a2, a3, aS + ks * 32);
#pragma unroll
            for (int ng2 = 0; ng2 < 2; ng2++) {
                u32 b0, b1, b2, b3;
                ldsm_x4t(b0, b1, b2, b3, bS + ks * 16 * 144 + ng2 * 32);
                mma16816(acc[ng2 * 2][0], acc[ng2 * 2][1], acc[ng2 * 2][2], acc[ng2 * 2][3],
                         a0, a1, a2, a3, b0, b1);
                mma16816(acc[ng2 * 2 + 1][0], acc[ng2 * 2 + 1][1],
                         acc[ng2 * 2 + 1][2], acc[ng2 * 2 + 1][3],
                         a0, a1, a2, a3, b2, b3);
            }
        }
    }

    const int rr = lane >> 2, cql = 2 * (lane & 3);
    const int r0 = bm + wm * 16 + rr, r1 = r0 + 8;
#pragma unroll
    for (int idx = 0; idx < 4; idx++) {
        const int col = bn + wn * 32 + idx * 8 + cql;
        float b0 = bias[col], b1 = bias[col + 1];
        float o0 = acc[idx][0] + b0, o1 = acc[idx][1] + b1;
        float o2 = acc[idx][2] + b0, o3 = acc[idx][3] + b1;
        if (gelu) {
            o0 *= normcdff(o0); o1 *= normcdff(o1);
            o2 *= normcdff(o2); o3 *= normcdff(o3);
        }
        if (R) {
            o0 += R[(size_t)r0 * N + col]; o1 += R[(size_t)r0 * N + col + 1];
            o2 += R[(size_t)r1 * N + col]; o3 += R[(size_t)r1 * N + col + 1];
        }
        if (Cb) {
            *(u32*)&Cb[(size_t)r0 * N + col] = cvt2bf(o1, o0);
            *(u32*)&Cb[(size_t)r1 * N + col] = cvt2bf(o3, o2);
        } else {
            *(float2*)&Cf[(size_t)r0 * N + col] = make_float2(o0, o1);
            *(float2*)&Cf[(size_t)r1 * N + col] = make_float2(o2, o3);
        }
    }
}

__global__ __launch_bounds__(128) void gemm_bf16(const __nv_bfloat16* __restrict__ A,
                                                 const __nv_bfloat16* __restrict__ B,
                                                 const float* __restrict__ bias,
                                                 const float* __restrict__ R,
                                                 float* __restrict__ Cf,
                                                 __nv_bfloat16* __restrict__ Cb,
                                                 int N, int K, int gelu) {
    gemm_bf16_body(A, B, bias, R, Cf, Cb, N, K, gelu, blockIdx.y * 32, blockIdx.x * 64);
}

// fused QKV: grid.x = 12 (3 matrices x 4 col tiles), grid.y = 64 row tiles
__global__ __launch_bounds__(128) void gemm_qkv_bf16(const float* __restrict__ bq,
                                                     const float* __restrict__ bk,
                                                     const float* __restrict__ bv) {
    int sel = blockIdx.x >> 2;
    int bn  = (blockIdx.x & 3) * 64;
    const __nv_bfloat16* B = (sel == 0) ? g_Wqb : (sel == 1) ? g_Wkb : g_Wvb;
    const float* bias      = (sel == 0) ? bq : (sel == 1) ? bk : bv;
    __nv_bfloat16* Cb      = (sel == 0) ? g_Qb : (sel == 1) ? g_Kb : g_Vb;
    gemm_bf16_body(g_hb, B, bias, nullptr, nullptr, Cb, DMODEL, DMODEL, 0,
                   blockIdx.y * 32, bn);
}

// ---------------- dense tensor-core flash attention, split-K, NO bias ----------
__global__ __launch_bounds__(128, 5) void attn_mma(const __nv_bfloat16* __restrict__ Qb,
                                                   const __nv_bfloat16* __restrict__ Kb,
                                                   const __nv_bfloat16* __restrict__ Vb) {
    __shared__ __align__(16) __nv_bfloat16 Ks[64][40];
    __shared__ __align__(16) __nv_bfloat16 Vs[64][40];

    const int h     = blockIdx.y;
    const int qb    = blockIdx.x * 64;
    const int chunk = blockIdx.z;
    const int kb0   = chunk * (N_NODES / KSPLIT);
    const int tid = threadIdx.x;
    const int warp = tid >> 5, lane = tid & 31;

#pragma unroll
    for (int i = 0; i < 2; i++) {
        int task = tid + 128 * i;
        int row = task >> 2, ch = task & 3;
        uint4 v = *(const uint4*)((const char*)(Qb + (size_t)(qb + row) * DMODEL + h * DK) + ch * 16);
        *(uint4*)((char*)&Ks[row][0] + ch * 16) = v;
    }
    __syncthreads();
    const int lr = lane & 7, lm = lane >> 3;
    u32 qa[2][4];
    {
        int row = warp * 16 + lr + (lm & 1) * 8;
#pragma unroll
        for (int c = 0; c < 2; c++) {
            u32 a = su32(&Ks[row][c * 16 + (lm >> 1) * 8]);
            ldsm_x4(qa[c][0], qa[c][1], qa[c][2], qa[c][3], a);
        }
    }

    const u32 kaddr = su32(&Ks[lr][lm * 8]);
    const u32 vaddr = su32(&Vs[lr + (lm & 1) * 8][(lm >> 1) * 8]);

    float O[4][4];
#pragma unroll
    for (int t = 0; t < 4; t++)
#pragma unroll
        for (int j = 0; j < 4; j++) O[t][j] = 0.f;
    float l0 = 0.f, l1 = 0.f;

    const float SCALE2 = 1.4426950408889634f * 0.17677669529663688f;

    for (int kt = 0; kt < (N_NODES / KSPLIT) / 64; kt++) {
        const int kb = kb0 + kt * 64;
        __syncthreads();
#pragma unroll
        for (int i = 0; i < 2; i++) {
            int task = tid + 128 * i;
            int row = task >> 2, ch = task & 3;
            const char* kp = (const char*)(Kb + (size_t)(kb + row) * DMODEL + h * DK) + ch * 16;
            const char* vp = (const char*)(Vb + (size_t)(kb + row) * DMODEL + h * DK) + ch * 16;
            *(uint4*)((char*)&Ks[row][0] + ch * 16) = *(const uint4*)kp;
            *(uint4*)((char*)&Vs[row][0] + ch * 16) = *(const uint4*)vp;
        }
        __syncthreads();

        u32 P[8][2];
#pragma unroll
        for (int kg = 0; kg < 8; kg++) {
            u32 b0, b1, b2, b3;
            ldsm_x4(b0, b1, b2, b3, kaddr + kg * 640);
            float c0 = 0.f, c1 = 0.f, c2 = 0.f, c3 = 0.f;
            mma16816(c0, c1, c2, c3, qa[0][0], qa[0][1], qa[0][2], qa[0][3], b0, b1);
            mma16816(c0, c1, c2, c3, qa[1][0], qa[1][1], qa[1][2], qa[1][3], b2, b3);
            float p0 = ex2f(c0 * SCALE2);
            float p1 = ex2f(c1 * SCALE2);
            float p2 = ex2f(c2 * SCALE2);
            float p3 = ex2f(c3 * SCALE2);
            l0 += p0 + p1;
            l1 += p2 + p3;
            P[kg][0] = cvt2bf(p1, p0);
            P[kg][1] = cvt2bf(p3, p2);
        }

#pragma unroll
        for (int ck = 0; ck < 4; ck++) {
            u32 a0 = P[2 * ck][0], a1 = P[2 * ck][1];
            u32 a2 = P[2 * ck + 1][0], a3 = P[2 * ck + 1][1];
#pragma unroll
            for (int tp = 0; tp < 2; tp++) {
                u32 v0, v1, v2, v3;
                ldsm_x4t(v0, v1, v2, v3, vaddr + ck * 1280 + tp * 32);
                mma16816(O[2 * tp][0], O[2 * tp][1], O[2 * tp][2], O[2 * tp][3],
                         a0, a1, a2, a3, v0, v1);
                mma16816(O[2 * tp + 1][0], O[2 * tp + 1][1], O[2 * tp + 1][2], O[2 * tp + 1][3],
                         a0, a1, a2, a3, v2, v3);
            }
        }
    }

    l0 += __shfl_xor_sync(0xffffffffu, l0, 1);
    l0 += __shfl_xor_sync(0xffffffffu, l0, 2);
    l1 += __shfl_xor_sync(0xffffffffu, l1, 1);
    l1 += __shfl_xor_sync(0xffffffffu, l1, 2);

    const int r0 = qb + warp * 16 + (lane >> 2);
    const int r1 = r0 + 8;
    const int cql = 2 * (lane & 3);

    float* part = g_part + (size_t)chunk * N_NODES * DMODEL;
#pragma unroll
    for (int t = 0; t < 4; t++) {
        int col = h * DK + t * 8 + cql;
        *(float2*)&part[(size_t)r0 * DMODEL + col] = make_float2(O[t][0], O[t][1]);
        *(float2*)&part[(size_t)r1 * DMODEL + col] = make_float2(O[t][2], O[t][3]);
    }
    if ((lane & 3) == 0) {
        g_lp[((size_t)chunk * N_NODES + r0) * NHEAD + h] = l0;
        g_lp[((size_t)chunk * N_NODES + r1) * NHEAD + h] = l1;
    }
}

// ---------------- sparse bias correction from compact winner lists ----------------
__global__ __launch_bounds__(256) void corr_kernel(const __nv_bfloat16* __restrict__ Qb,
                                                   const __nv_bfloat16* __restrict__ Kb,
                                                   const __nv_bfloat16* __restrict__ Vb) {
    const int q    = blockIdx.x * 8 + (threadIdx.x >> 5);
    const int lane = threadIdx.x & 31;
    const int h = lane >> 2, g = lane & 3;
    const float SCALE2 = 1.4426950408889634f * 0.17677669529663688f;

    float qv[8];
    {
        uint4 w = *(const uint4*)(Qb + (size_t)q * DMODEL + h * DK + g * 8);
        const u32 ws[4] = {w.x, w.y, w.z, w.w};
#pragma unroll
        for (int i = 0; i < 4; i++) {
            qv[2 * i]     = bflo(ws[i]) * SCALE2;
            qv[2 * i + 1] = bfhi(ws[i]) * SCALE2;
        }
    }

    float O[8];
#pragma unroll
    for (int i = 0; i < 8; i++) O[i] = 0.f;
    float lacc = 0.f;

    int cnt = g_cnt[q];
    if (cnt > CAPL) cnt = CAPL;
    const u32* lst = g_list + (size_t)q * CAPL;

    for (int i = 0; i < cnt; i += 4) {
#pragma unroll
        for (int j = 0; j < 4; j++) {
            if (i + j >= cnt) break;                 // warp-uniform
            u32 e = lst[i + j];
            int k    = (int)(e >> 16);
            int widx = (int)(e & 0xFFFFu);
            uint4 kw = *(const uint4*)(Kb + (size_t)k * DMODEL + h * DK + g * 8);
            uint4 vw = *(const uint4*)(Vb + (size_t)k * DMODEL + h * DK + g * 8);
            float eb = g_eb[(size_t)widx * 8 + h];
            const u32 ks[4] = {kw.x, kw.y, kw.z, kw.w};
            float s = 0.f;
#pragma unroll
            for (int t = 0; t < 4; t++) {
                s += qv[2 * t] * bflo(ks[t]);
                s += qv[2 * t + 1] * bfhi(ks[t]);
            }
            s += __shfl_xor_sync(0xffffffffu, s, 1);
            s += __shfl_xor_sync(0xffffffffu, s, 2);
            float pd = ex2f(s + eb) - ex2f(s);
            lacc += pd;
            const u32 vs[4] = {vw.x, vw.y, vw.z, vw.w};
#pragma unroll
            for (int t = 0; t < 4; t++) {
                O[2 * t]     += pd * bflo(vs[t]);
                O[2 * t + 1] += pd * bfhi(vs[t]);
            }
        }
    }

    float* part = g_part + (size_t)KSPLIT * N_NODES * DMODEL + (size_t)q * DMODEL + h * DK + g * 8;
    *(float4*)&part[0] = make_float4(O[0], O[1], O[2], O[3]);
    *(float4*)&part[4] = make_float4(O[4], O[5], O[6], O[7]);
    if (g == 0)
        g_lp[((size_t)KSPLIT * N_NODES + q) * NHEAD + h] = lacc;
}

// ---------------- combine partials -> bf16 attn ----------------
__global__ __launch_bounds__(256) void combine_kernel() {
    int gid = blockIdx.x * 256 + threadIdx.x;   // 2048*64
    int row = gid >> 6;
    int col = (gid & 63) << 2;
    int h = col >> 5;
    float ls = 0.f;
    float4 acc = make_float4(0.f, 0.f, 0.f, 0.f);
#pragma unroll
    for (int c = 0; c < NSLOT; c++) {
        ls += g_lp[((size_t)c * N_NODES + row) * NHEAD + h];
        float4 p = *(const float4*)&g_part[((size_t)c * N_NODES + row) * DMODEL + col];
        acc.x += p.x; acc.y += p.y; acc.z += p.z; acc.w += p.w;
    }
    float inv = 1.f / ls;
    uint2 p;
    p.x = cvt2bf(acc.y * inv, acc.x * inv);
    p.y = cvt2bf(acc.w * inv, acc.z * inv);
    *(uint2*)&g_attnb[(size_t)row * DMODEL + col] = p;
}

// ---------------- fused double LayerNorm: Y -> h1 (fp32), fln(h1) -> x2 (bf16) ----
__global__ __launch_bounds__(256) void ln_kernel(const float* __restrict__ Y,
                                                 const float* __restrict__ g1,
                                                 const float* __restrict__ b1,
                                                 const float* __restrict__ g2,
                                                 const float* __restrict__ b2,
                                                 float* __restrict__ H1,
                                                 __nv_bfloat16* __restrict__ X2b) {
    const int lane = threadIdx.x & 31;
    const int row  = blockIdx.x * 8 + (threadIdx.x >> 5);
    const float4* y4 = (const float4*)(Y + (size_t)row * DMODEL);
    float v[8];
    {
        float4 a = y4[lane * 2], b = y4[lane * 2 + 1];
        v[0] = a.x; v[1] = a.y; v[2] = a.z; v[3] = a.w;
        v[4] = b.x; v[5] = b.y; v[6] = b.z; v[7] = b.w;
    }

    float s = 0.f;
#pragma unroll
    for (int j = 0; j < 8; j++) s += v[j];
#pragma unroll
    for (int o = 16; o; o >>= 1) s += __shfl_xor_sync(0xffffffffu, s, o);
    float mu = s * (1.f / 256.f);
    float q = 0.f;
#pragma unroll
    for (int j = 0; j < 8; j++) { float d = v[j] - mu; q += d * d; }
#pragma unroll
    for (int o = 16; o; o >>= 1) q += __shfl_xor_sync(0xffffffffu, q, o);
    float rs = rsqrtf(q * (1.f / 256.f) + 1e-5f);

    const int c0 = lane * 8;
    float hv[8];
#pragma unroll
    for (int j = 0; j < 8; j++)
        hv[j] = (v[j] - mu) * rs * g1[c0 + j] + b1[c0 + j];
    {
        float4* h4 = (float4*)(H1 + (size_t)row * DMODEL + c0);
        h4[0] = make_float4(hv[0], hv[1], hv[2], hv[3]);
        h4[1] = make_float4(hv[4], hv[5], hv[6], hv[7]);
    }

    s = 0.f;
#pragma unroll
    for (int j = 0; j < 8; j++) s += hv[j];
#pragma unroll
    for (int o = 16; o; o >>= 1) s += __shfl_xor_sync(0xffffffffu, s, o);
    mu = s * (1.f / 256.f);
    q = 0.f;
#pragma unroll
    for (int j = 0; j < 8; j++) { float d = hv[j] - mu; q += d * d; }
#pragma unroll
    for (int o = 16; o; o >>= 1) q += __shfl_xor_sync(0xffffffffu, q, o);
    rs = rsqrtf(q * (1.f / 256.f) + 1e-5f);

    uint4 px;
    float x0 = (hv[0] - mu) * rs * g2[c0 + 0] + b2[c0 + 0];
    float x1 = (hv[1] - mu) * rs * g2[c0 + 1] + b2[c0 + 1];
    float x2 = (hv[2] - mu) * rs * g2[c0 + 2] + b2[c0 + 2];
    float x3 = (hv[3] - mu) * rs * g2[c0 + 3] + b2[c0 + 3];
    float x4 = (hv[4] - mu) * rs * g2[c0 + 4] + b2[c0 + 4];
    float x5 = (hv[5] - mu) * rs * g2[c0 + 5] + b2[c0 + 5];
    float x6 = (hv[6] - mu) * rs * g2[c0 + 6] + b2[c0 + 6];
    float x7 = (hv[7] - mu) * rs * g2[c0 + 7] + b2[c0 + 7];
    px.x = cvt2bf(x1, x0);
    px.y = cvt2bf(x3, x2);
    px.z = cvt2bf(x5, x4);
    px.w = cvt2bf(x7, x6);
    *(uint4*)&X2b[(size_t)row * DMODEL + c0] = px;
}

// ---------------- launch ----------------
extern "C" void kernel_launch(void* const* d_in, const int* in_sizes, int n_in,
                              void* d_out, int out_size) {
    const float* h    = (const float*)d_in[0];
    const float* ea   = (const float*)d_in[1];
    const float* Wq   = (const float*)d_in[2];
    const float* bq   = (const float*)d_in[3];
    const float* Wk   = (const float*)d_in[4];
    const float* bk   = (const float*)d_in[5];
    const float* Wv   = (const float*)d_in[6];
    const float* bv   = (const float*)d_in[7];
    const float* Wo   = (const float*)d_in[8];
    const float* bo   = (const float*)d_in[9];
    const float* We   = (const float*)d_in[10];
    const float* be   = (const float*)d_in[11];
    const float* ln1g = (const float*)d_in[12];
    const float* ln1b = (const float*)d_in[13];
    const float* flng = (const float*)d_in[14];
    const float* flnb = (const float*)d_in[15];
    const float* W1   = (const float*)d_in[16];
    const float* b1   = (const float*)d_in[17];
    const float* W2   = (const float*)d_in[18];
    const float* b2   = (const float*)d_in[19];
    const int*   eidx = (const int*)d_in[20];
    float* out = (float*)d_out;

    __nv_bfloat16 *pQb, *pKb, *pVb, *pAttnb, *pX2b, *pGb, *pWob, *pW1b, *pW2b;
    float *pY, *pH1;
    cudaGetSymbolAddress((void**)&pQb,    g_Qb);
    cudaGetSymbolAddress((void**)&pKb,    g_Kb);
    cudaGetSymbolAddress((void**)&pVb,    g_Vb);
    cudaGetSymbolAddress((void**)&pAttnb, g_attnb);
    cudaGetSymbolAddress((void**)&pX2b,   g_x2b);
    cudaGetSymbolAddress((void**)&pGb,    g_Gb);
    cudaGetSymbolAddress((void**)&pWob,   g_Wob);
    cudaGetSymbolAddress((void**)&pW1b,   g_W1b);
    cudaGetSymbolAddress((void**)&pW2b,   g_W2b);
    cudaGetSymbolAddress((void**)&pY,     g_Y);
    cudaGetSymbolAddress((void**)&pH1,    g_h1);

    conv_kernel<<<1024, 256>>>(h, Wq, Wk, Wv, Wo, W1, W2);
    reset_winner_kernel<<<1024, 1024>>>();
    edge_kernel<<<NEDGE / 256, 256>>>(ea, We, be, eidx);
    winner_kernel<<<NEDGE / 256, 256>>>(eidx);

    gemm_qkv_bf16<<<dim3(12, 64), 128>>>(bq, bk, bv);

    attn_mma<<<dim3(N_NODES / 64, NHEAD, KSPLIT), 128>>>(pQb, pKb, pVb);
    corr_kernel<<<N_NODES / 8, 256>>>(pQb, pKb, pVb);
    combine_kernel<<<(N_NODES * DMODEL / 4) / 256, 256>>>();

    gemm_bf16<<<dim3(4, 64), 128>>>(pAttnb, pWob, bo, h, pY, nullptr,
                                    DMODEL, DMODEL, 0);

    ln_kernel<<<N_NODES / 8, 256>>>(pY, ln1g, ln1b, flng, flnb, pH1, pX2b);

    gemm_bf16<<<dim3(8, 64), 128>>>(pX2b, pW1b, b1, nullptr, nullptr, pGb,
                                    HID, DMODEL, 1);
    gemm_bf16<<<dim3(4, 64), 128>>>(pGb, pW2b, b2, pH1, out, nullptr,
                                    DMODEL, HID, 0);
}

// round 9
// speedup vs baseline: 1.9351x; 1.1338x over previous
#include <cuda_runtime.h>
#include <cuda_bf16.h>
#include <math.h>

#define N_NODES 2048
#define DMODEL  256
#define NHEAD   8
#define DK      32
#define NEDGE   65536
#define HID     512
#define KSPLIT  4
#define NSLOT   (KSPLIT + 1)
#define CAPL    256
#define ATILES  ((N_NODES / KSPLIT) / 64)

typedef unsigned long long ull;
typedef unsigned int u32;

// ---- mma / ldmatrix / cp.async helpers ----
__device__ __forceinline__ u32 su32(const void* p) {
    return (u32)__cvta_generic_to_shared(p);
}
__device__ __forceinline__ void ldsm_x4(u32& r0, u32& r1, u32& r2, u32& r3, u32 a) {
    asm volatile("ldmatrix.sync.aligned.m8n8.x4.shared.b16 {%0,%1,%2,%3},[%4];"
                 : "=r"(r0), "=r"(r1), "=r"(r2), "=r"(r3) : "r"(a));
}
__device__ __forceinline__ void ldsm_x4t(u32& r0, u32& r1, u32& r2, u32& r3, u32 a) {
    asm volatile("ldmatrix.sync.aligned.m8n8.x4.trans.shared.b16 {%0,%1,%2,%3},[%4];"
                 : "=r"(r0), "=r"(r1), "=r"(r2), "=r"(r3) : "r"(a));
}
__device__ __forceinline__ void mma16816(float& c0, float& c1, float& c2, float& c3,
                                         u32 a0, u32 a1, u32 a2, u32 a3, u32 b0, u32 b1) {
    asm volatile("mma.sync.aligned.m16n8k16.row.col.f32.bf16.bf16.f32 "
                 "{%0,%1,%2,%3},{%4,%5,%6,%7},{%8,%9},{%0,%1,%2,%3};"
                 : "+f"(c0), "+f"(c1), "+f"(c2), "+f"(c3)
                 : "r"(a0), "r"(a1), "r"(a2), "r"(a3), "r"(b0), "r"(b1));
}
__device__ __forceinline__ float ex2f(float x) {
    float r; asm("ex2.approx.f32 %0,%1;" : "=f"(r) : "f"(x)); return r;
}
__device__ __forceinline__ u32 cvt2bf(float hi, float lo) {
    u32 r; asm("cvt.rn.bf16x2.f32 %0,%1,%2;" : "=r"(r) : "f"(hi), "f"(lo)); return r;
}
__device__ __forceinline__ float bflo(u32 w) { return __uint_as_float(w << 16); }
__device__ __forceinline__ float bfhi(u32 w) { return __uint_as_float(w & 0xffff0000u); }
__device__ __forceinline__ void cp16(u32 dst, const void* src) {
    asm volatile("cp.async.ca.shared.global [%0],[%1],16;" :: "r"(dst), "l"(src));
}

// ---------------- scratch ----------------
__device__ __nv_bfloat16 g_hb[N_NODES * DMODEL];
__device__ __nv_bfloat16 g_Wqb[DMODEL * DMODEL];
__device__ __nv_bfloat16 g_Wkb[DMODEL * DMODEL];
__device__ __nv_bfloat16 g_Wvb[DMODEL * DMODEL];
__device__ __nv_bfloat16 g_Wob[DMODEL * DMODEL];
__device__ __nv_bfloat16 g_W1b[DMODEL * HID];
__device__ __nv_bfloat16 g_W2b[HID * DMODEL];
__device__ __nv_bfloat16 g_Qb[N_NODES * DMODEL];
__device__ __nv_bfloat16 g_Kb[N_NODES * DMODEL];
__device__ __nv_bfloat16 g_Vb[N_NODES * DMODEL];
__device__ __nv_bfloat16 g_attnb[N_NODES * DMODEL];
__device__ __nv_bfloat16 g_x2b[N_NODES * DMODEL];
__device__ __nv_bfloat16 g_Gb[N_NODES * HID];
__device__ float g_eb[NEDGE * NHEAD];                 // pre-scaled by log2(e)
__device__ int   g_cnt[N_NODES];
__device__ u32   g_list[N_NODES * CAPL];
__device__ float g_part[NSLOT * N_NODES * DMODEL];
__device__ float g_lp[NSLOT * N_NODES * NHEAD];
__device__ float g_Y[N_NODES * DMODEL];
__device__ float g_h1[N_NODES * DMODEL];

// ---------------- fp32 -> bf16 conversions (h + weights) + g_cnt reset ----------
__global__ __launch_bounds__(256) void conv_kernel(const float* __restrict__ h,
                                                   const float* __restrict__ Wq,
                                                   const float* __restrict__ Wk,
                                                   const float* __restrict__ Wv,
                                                   const float* __restrict__ Wo,
                                                   const float* __restrict__ W1,
                                                   const float* __restrict__ W2) {
    int gid = blockIdx.x * 256 + threadIdx.x;   // 262144 float4 tasks
    if (gid < 512) ((int4*)g_cnt)[gid] = make_int4(0, 0, 0, 0);
    const float* src; __nv_bfloat16* dst; int off;
    if (gid < 131072)      { src = h;  dst = g_hb;  off = gid; }
    else if (gid < 147456) { src = Wq; dst = g_Wqb; off = gid - 131072; }
    else if (gid < 163840) { src = Wk; dst = g_Wkb; off = gid - 147456; }
    else if (gid < 180224) { src = Wv; dst = g_Wvb; off = gid - 163840; }
    else if (gid < 196608) { src = Wo; dst = g_Wob; off = gid - 180224; }
    else if (gid < 229376) { src = W1; dst = g_W1b; off = gid - 196608; }
    else                   { src = W2; dst = g_W2b; off = gid - 229376; }
    float4 v = ((const float4*)src)[off];
    uint2 p;
    p.x = cvt2bf(v.y, v.x);
    p.y = cvt2bf(v.w, v.z);
    ((uint2*)dst)[off] = p;
}

// ---------------- edge bias (log2e-scaled) + per-src list append ----------------
__global__ __launch_bounds__(256) void edge_kernel(const float* __restrict__ ea,
                                                   const float* __restrict__ We,
                                                   const float* __restrict__ be,
                                                   const int*   __restrict__ eidx) {
    const float L2E = 1.4426950408889634f;
    int e = blockIdx.x * blockDim.x + threadIdx.x;
    float a[7];
#pragma unroll
    for (int j = 0; j < 7; j++) a[j] = ea[e * 7 + j];
#pragma unroll
    for (int hh = 0; hh < 8; hh++) {
        float v = be[hh];
#pragma unroll
        for (int j = 0; j < 7; j++) v += a[j] * We[j * 8 + hh];
        g_eb[e * 8 + hh] = v * L2E;
    }
    int src = eidx[e];
    int dst = eidx[NEDGE + e];
    int pos = atomicAdd(&g_cnt[src], 1);
    if (pos < CAPL) g_list[(size_t)src * CAPL + pos] = ((u32)dst << 16) | (u32)e;
}

// ---------------- bf16 tensor-core GEMM: 32x64 tile, BK=32, cp.async 3-stage ------
__device__ __forceinline__ void gemm_bf16_body(const __nv_bfloat16* __restrict__ A,
                                               const __nv_bfloat16* __restrict__ B,
                                               const float* __restrict__ bias,
                                               const float* __restrict__ R,
                                               float* __restrict__ Cf,
                                               __nv_bfloat16* __restrict__ Cb,
                                               int N, int K, int gelu,
                                               int bm, int bn) {
    __shared__ __align__(16) __nv_bfloat16 As[3][32][40];   // 80B rows
    __shared__ __align__(16) __nv_bfloat16 Bs[3][32][72];   // 144B rows
    const int tid = threadIdx.x, warp = tid >> 5, lane = tid & 31;
    const int wm = warp & 1, wn = warp >> 1;
    const int lr = lane & 7, lm = lane >> 3;

    const int ar = tid >> 2, ac = tid & 3;
    const int br0 = tid >> 3, bc = tid & 7;
    const int br1 = br0 + 16;

    const u32 sA = su32(&As[0][0][0]);
    const u32 sB = su32(&Bs[0][0][0]);
    const u32 dstA  = sA + ar * 80 + ac * 16;
    const u32 dstB0 = sB + br0 * 144 + bc * 16;
    const u32 dstB1 = sB + br1 * 144 + bc * 16;
    const __nv_bfloat16* srcA = A + (size_t)(bm + ar) * K + ac * 8;

    const int Kk = K >> 5;
    float acc[4][4] = {};

    auto issue = [&](int kb, int st) {
        if (kb < Kk) {
            cp16(dstA + st * 2560, srcA + kb * 32);
            cp16(dstB0 + st * 4608, B + (size_t)(kb * 32 + br0) * N + bn + bc * 8);
            cp16(dstB1 + st * 4608, B + (size_t)(kb * 32 + br1) * N + bn + bc * 8);
        }
        asm volatile("cp.async.commit_group;");
    };
    issue(0, 0);
    issue(1, 1);

    const u32 aBase = sA + (wm * 16 + lr + (lm & 1) * 8) * 80 + (lm >> 1) * 16;
    const u32 bBase = sB + (lr + (lm & 1) * 8) * 144 + (wn * 32 + (lm >> 1) * 8) * 2;

    for (int kb = 0; kb < Kk; kb++) {
        asm volatile("cp.async.wait_group 1;");
        __syncthreads();
        issue(kb + 2, (kb + 2) % 3);
        const u32 aS = aBase + (kb % 3) * 2560;
        const u32 bS = bBase + (kb % 3) * 4608;
#pragma unroll
        for (int ks = 0; ks < 2; ks++) {
            u32 a0, a1, a2, a3;
            ldsm_x4(a0, a1, a2, a3, aS + ks * 32);
#pragma unroll
            for (int ng2 = 0; ng2 < 2; ng2++) {
                u32 b0, b1, b2, b3;
                ldsm_x4t(b0, b1, b2, b3, bS + ks * 16 * 144 + ng2 * 32);
                mma16816(acc[ng2 * 2][0], acc[ng2 * 2][1], acc[ng2 * 2][2], acc[ng2 * 2][3],
                         a0, a1, a2, a3, b0, b1);
                mma16816(acc[ng2 * 2 + 1][0], acc[ng2 * 2 + 1][1],
                         acc[ng2 * 2 + 1][2], acc[ng2 * 2 + 1][3],
                         a0, a1, a2, a3, b2, b3);
            }
        }
    }

    const int rr = lane >> 2, cql = 2 * (lane & 3);
    const int r0 = bm + wm * 16 + rr, r1 = r0 + 8;
#pragma unroll
    for (int idx = 0; idx < 4; idx++) {
        const int col = bn + wn * 32 + idx * 8 + cql;
        float b0 = bias[col], b1 = bias[col + 1];
        float o0 = acc[idx][0] + b0, o1 = acc[idx][1] + b1;
        float o2 = acc[idx][2] + b0, o3 = acc[idx][3] + b1;
        if (gelu) {
            o0 *= normcdff(o0); o1 *= normcdff(o1);
            o2 *= normcdff(o2); o3 *= normcdff(o3);
        }
        if (R) {
            o0 += R[(size_t)r0 * N + col]; o1 += R[(size_t)r0 * N + col + 1];
            o2 += R[(size_t)r1 * N + col]; o3 += R[(size_t)r1 * N + col + 1];
        }
        if (Cb) {
            *(u32*)&Cb[(size_t)r0 * N + col] = cvt2bf(o1, o0);
            *(u32*)&Cb[(size_t)r1 * N + col] = cvt2bf(o3, o2);
        } else {
            *(float2*)&Cf[(size_t)r0 * N + col] = make_float2(o0, o1);
            *(float2*)&Cf[(size_t)r1 * N + col] = make_float2(o2, o3);
        }
    }
}

__global__ __launch_bounds__(128) void gemm_bf16(const __nv_bfloat16* __restrict__ A,
                                                 const __nv_bfloat16* __restrict__ B,
                                                 const float* __restrict__ bias,
                                                 const float* __restrict__ R,
                                                 float* __restrict__ Cf,
                                                 __nv_bfloat16* __restrict__ Cb,
                                                 int N, int K, int gelu) {
    gemm_bf16_body(A, B, bias, R, Cf, Cb, N, K, gelu, blockIdx.y * 32, blockIdx.x * 64);
}

__global__ __launch_bounds__(128) void gemm_qkv_bf16(const float* __restrict__ bq,
                                                     const float* __restrict__ bk,
                                                     const float* __restrict__ bv) {
    int sel = blockIdx.x >> 2;
    int bn  = (blockIdx.x & 3) * 64;
    const __nv_bfloat16* B = (sel == 0) ? g_Wqb : (sel == 1) ? g_Wkb : g_Wvb;
    const float* bias      = (sel == 0) ? bq : (sel == 1) ? bk : bv;
    __nv_bfloat16* Cb      = (sel == 0) ? g_Qb : (sel == 1) ? g_Kb : g_Vb;
    gemm_bf16_body(g_hb, B, bias, nullptr, nullptr, Cb, DMODEL, DMODEL, 0,
                   blockIdx.y * 32, bn);
}

// ---------------- dense flash attention, split-K, cp.async 3-stage ----------
__global__ __launch_bounds__(128, 5) void attn_mma(const __nv_bfloat16* __restrict__ Qb,
                                                   const __nv_bfloat16* __restrict__ Kb,
                                                   const __nv_bfloat16* __restrict__ Vb) {
    __shared__ __align__(16) __nv_bfloat16 Qs[64][40];
    __shared__ __align__(16) __nv_bfloat16 Ks[3][64][40];
    __shared__ __align__(16) __nv_bfloat16 Vs[3][64][40];

    const int h     = blockIdx.y;
    const int qb    = blockIdx.x * 64;
    const int chunk = blockIdx.z;
    const int kb0   = chunk * (N_NODES / KSPLIT);
    const int tid = threadIdx.x;
    const int warp = tid >> 5, lane = tid & 31;

    const int row0 = tid >> 2, ch0 = tid & 3;
    const int row1 = (tid + 128) >> 2, ch1 = (tid + 128) & 3;

    // stage Q, build per-warp A-fragments
    *(uint4*)((char*)&Qs[row0][0] + ch0 * 16) =
        *(const uint4*)((const char*)(Qb + (size_t)(qb + row0) * DMODEL + h * DK) + ch0 * 16);
    *(uint4*)((char*)&Qs[row1][0] + ch1 * 16) =
        *(const uint4*)((const char*)(Qb + (size_t)(qb + row1) * DMODEL + h * DK) + ch1 * 16);
    __syncthreads();
    const int lr = lane & 7, lm = lane >> 3;
    u32 qa[2][4];
    {
        int row = warp * 16 + lr + (lm & 1) * 8;
#pragma unroll
        for (int c = 0; c < 2; c++) {
            u32 a = su32(&Qs[row][c * 16 + (lm >> 1) * 8]);
            ldsm_x4(qa[c][0], qa[c][1], qa[c][2], qa[c][3], a);
        }
    }

    // cp.async destinations
    const u32 kd0 = su32(&Ks[0][row0][0]) + ch0 * 16;
    const u32 kd1 = su32(&Ks[0][row1][0]) + ch1 * 16;
    const u32 vd0 = su32(&Vs[0][row0][0]) + ch0 * 16;
    const u32 vd1 = su32(&Vs[0][row1][0]) + ch1 * 16;

    auto issueT = [&](int kt, int st) {
        if (kt < ATILES) {
            int kb = kb0 + kt * 64;
            const char* kp0 = (const char*)(Kb + (size_t)(kb + row0) * DMODEL + h * DK) + ch0 * 16;
            const char* kp1 = (const char*)(Kb + (size_t)(kb + row1) * DMODEL + h * DK) + ch1 * 16;
            const char* vp0 = (const char*)(Vb + (size_t)(kb + row0) * DMODEL + h * DK) + ch0 * 16;
            const char* vp1 = (const char*)(Vb + (size_t)(kb + row1) * DMODEL + h * DK) + ch1 * 16;
            cp16(kd0 + st * 5120, kp0);
            cp16(kd1 + st * 5120, kp1);
            cp16(vd0 + st * 5120, vp0);
            cp16(vd1 + st * 5120, vp1);
        }
        asm volatile("cp.async.commit_group;");
    };
    issueT(0, 0);
    issueT(1, 1);

    const u32 kaddr = su32(&Ks[0][lr][lm * 8]);
    const u32 vaddr = su32(&Vs[0][lr + (lm & 1) * 8][(lm >> 1) * 8]);

    float O[4][4];
#pragma unroll
    for (int t = 0; t < 4; t++)
#pragma unroll
        for (int j = 0; j < 4; j++) O[t][j] = 0.f;
    float l0 = 0.f, l1 = 0.f;

    const float SCALE2 = 1.4426950408889634f * 0.17677669529663688f;

    for (int kt = 0; kt < ATILES; kt++) {
        asm volatile("cp.async.wait_group 1;");
        __syncthreads();
        issueT(kt + 2, (kt + 2) % 3);
        const u32 kS = kaddr + (kt % 3) * 5120;
        const u32 vS = vaddr + (kt % 3) * 5120;

        u32 P[8][2];
#pragma unroll
        for (int kg = 0; kg < 8; kg++) {
            u32 b0, b1, b2, b3;
            ldsm_x4(b0, b1, b2, b3, kS + kg * 640);
            float c0 = 0.f, c1 = 0.f, c2 = 0.f, c3 = 0.f;
            mma16816(c0, c1, c2, c3, qa[0][0], qa[0][1], qa[0][2], qa[0][3], b0, b1);
            mma16816(c0, c1, c2, c3, qa[1][0], qa[1][1], qa[1][2], qa[1][3], b2, b3);
            float p0 = ex2f(c0 * SCALE2);
            float p1 = ex2f(c1 * SCALE2);
            float p2 = ex2f(c2 * SCALE2);
            float p3 = ex2f(c3 * SCALE2);
            l0 += p0 + p1;
            l1 += p2 + p3;
            P[kg][0] = cvt2bf(p1, p0);
            P[kg][1] = cvt2bf(p3, p2);
        }

#pragma unroll
        for (int ck = 0; ck < 4; ck++) {
            u32 a0 = P[2 * ck][0], a1 = P[2 * ck][1];
            u32 a2 = P[2 * ck + 1][0], a3 = P[2 * ck + 1][1];
#pragma unroll
            for (int tp = 0; tp < 2; tp++) {
                u32 v0, v1, v2, v3;
                ldsm_x4t(v0, v1, v2, v3, vS + ck * 1280 + tp * 32);
                mma16816(O[2 * tp][0], O[2 * tp][1], O[2 * tp][2], O[2 * tp][3],
                         a0, a1, a2, a3, v0, v1);
                mma16816(O[2 * tp + 1][0], O[2 * tp + 1][1], O[2 * tp + 1][2], O[2 * tp + 1][3],
                         a0, a1, a2, a3, v2, v3);
            }
        }
    }

    l0 += __shfl_xor_sync(0xffffffffu, l0, 1);
    l0 += __shfl_xor_sync(0xffffffffu, l0, 2);
    l1 += __shfl_xor_sync(0xffffffffu, l1, 1);
    l1 += __shfl_xor_sync(0xffffffffu, l1, 2);

    const int r0 = qb + warp * 16 + (lane >> 2);
    const int r1 = r0 + 8;
    const int cql = 2 * (lane & 3);

    float* part = g_part + (size_t)chunk * N_NODES * DMODEL;
#pragma unroll
    for (int t = 0; t < 4; t++) {
        int col = h * DK + t * 8 + cql;
        *(float2*)&part[(size_t)r0 * DMODEL + col] = make_float2(O[t][0], O[t][1]);
        *(float2*)&part[(size_t)r1 * DMODEL + col] = make_float2(O[t][2], O[t][3]);
    }
    if ((lane & 3) == 0) {
        g_lp[((size_t)chunk * N_NODES + r0) * NHEAD + h] = l0;
        g_lp[((size_t)chunk * N_NODES + r1) * NHEAD + h] = l1;
    }
}

// ---------------- sparse bias correction with in-list dedup ----------------
// entry v = (dst<<16)|e; among same dst, winner = max v (max edge index).
__global__ __launch_bounds__(256) void corr_kernel(const __nv_bfloat16* __restrict__ Qb,
                                                   const __nv_bfloat16* __restrict__ Kb,
                                                   const __nv_bfloat16* __restrict__ Vb) {
    __shared__ u32 slist[8][CAPL];
    __shared__ u32 wlist[8][CAPL];
    const int w    = threadIdx.x >> 5;
    const int q    = blockIdx.x * 8 + w;
    const int lane = threadIdx.x & 31;
    const int h = lane >> 2, g = lane & 3;
    const float SCALE2 = 1.4426950408889634f * 0.17677669529663688f;
    const u32 lmask_lt = (1u << lane) - 1u;

    float qv[8];
    {
        uint4 wq = *(const uint4*)(Qb + (size_t)q * DMODEL + h * DK + g * 8);
        const u32 ws[4] = {wq.x, wq.y, wq.z, wq.w};
#pragma unroll
        for (int i = 0; i < 4; i++) {
            qv[2 * i]     = bflo(ws[i]) * SCALE2;
            qv[2 * i + 1] = bfhi(ws[i]) * SCALE2;
        }
    }

    int cnt = g_cnt[q];
    if (cnt > CAPL) cnt = CAPL;
    for (int i = lane; i < cnt; i += 32)
        slist[w][i] = g_list[(size_t)q * CAPL + i];
    __syncwarp();

    // dedup + compact winners into wlist
    int ncnt = 0;
    for (int base = 0; base < cnt; base += 32) {
        int i = base + lane;
        u32 v = 0;
        bool win = false;
        if (i < cnt) {
            v = slist[w][i];
            win = true;
            for (int j = 0; j < cnt; j++) {
                u32 u = slist[w][j];
                if (((u ^ v) & 0xFFFF0000u) == 0 && u > v) win = false;
            }
        }
        u32 m = __ballot_sync(0xffffffffu, win);
        if (win) wlist[w][ncnt + __popc(m & lmask_lt)] = v;
        ncnt += __popc(m);
    }
    __syncwarp();

    float O[8];
#pragma unroll
    for (int i = 0; i < 8; i++) O[i] = 0.f;
    float lacc = 0.f;

    for (int i = 0; i < ncnt; i += 4) {
#pragma unroll
        for (int j = 0; j < 4; j++) {
            if (i + j >= ncnt) break;               // warp-uniform
            u32 v = wlist[w][i + j];
            int k    = (int)(v >> 16);
            int widx = (int)(v & 0xFFFFu);
            uint4 kw = *(const uint4*)(Kb + (size_t)k * DMODEL + h * DK + g * 8);
            uint4 vw = *(const uint4*)(Vb + (size_t)k * DMODEL + h * DK + g * 8);
            float eb = g_eb[(size_t)widx * 8 + h];
            const u32 ks[4] = {kw.x, kw.y, kw.z, kw.w};
            float s = 0.f;
#pragma unroll
            for (int t = 0; t < 4; t++) {
                s += qv[2 * t] * bflo(ks[t]);
                s += qv[2 * t + 1] * bfhi(ks[t]);
            }
            s += __shfl_xor_sync(0xffffffffu, s, 1);
            s += __shfl_xor_sync(0xffffffffu, s, 2);
            float pd = ex2f(s + eb) - ex2f(s);
            lacc += pd;
            const u32 vs[4] = {vw.x, vw.y, vw.z, vw.w};
#pragma unroll
            for (int t = 0; t < 4; t++) {
                O[2 * t]     += pd * bflo(vs[t]);
                O[2 * t + 1] += pd * bfhi(vs[t]);
            }
        }
    }

    float* part = g_part + (size_t)KSPLIT * N_NODES * DMODEL + (size_t)q * DMODEL + h * DK + g * 8;
    *(float4*)&part[0] = make_float4(O[0], O[1], O[2], O[3]);
    *(float4*)&part[4] = make_float4(O[4], O[5], O[6], O[7]);
    if (g == 0)
        g_lp[((size_t)KSPLIT * N_NODES + q) * NHEAD + h] = lacc;
}

// ---------------- combine partials -> bf16 attn ----------------
__global__ __launch_bounds__(256) void combine_kernel() {
    int gid = blockIdx.x * 256 + threadIdx.x;   // 2048*64
    int row = gid >> 6;
    int col = (gid & 63) << 2;
    int h = col >> 5;
    float ls = 0.f;
    float4 acc = make_float4(0.f, 0.f, 0.f, 0.f);
#pragma unroll
    for (int c = 0; c < NSLOT; c++) {
        ls += g_lp[((size_t)c * N_NODES + row) * NHEAD + h];
        float4 p = *(const float4*)&g_part[((size_t)c * N_NODES + row) * DMODEL + col];
        acc.x += p.x; acc.y += p.y; acc.z += p.z; acc.w += p.w;
    }
    float inv = 1.f / ls;
    uint2 p;
    p.x = cvt2bf(acc.y * inv, acc.x * inv);
    p.y = cvt2bf(acc.w * inv, acc.z * inv);
    *(uint2*)&g_attnb[(size_t)row * DMODEL + col] = p;
}

// ---------------- fused double LayerNorm ----------------
__global__ __launch_bounds__(256) void ln_kernel(const float* __restrict__ Y,
                                                 const float* __restrict__ g1,
                                                 const float* __restrict__ b1,
                                                 const float* __restrict__ g2,
                                                 const float* __restrict__ b2,
                                                 float* __restrict__ H1,
                                                 __nv_bfloat16* __restrict__ X2b) {
    const int lane = threadIdx.x & 31;
    const int row  = blockIdx.x * 8 + (threadIdx.x >> 5);
    const float4* y4 = (const float4*)(Y + (size_t)row * DMODEL);
    float v[8];
    {
        float4 a = y4[lane * 2], b = y4[lane * 2 + 1];
        v[0] = a.x; v[1] = a.y; v[2] = a.z; v[3] = a.w;
        v[4] = b.x; v[5] = b.y; v[6] = b.z; v[7] = b.w;
    }

    float s = 0.f;
#pragma unroll
    for (int j = 0; j < 8; j++) s += v[j];
#pragma unroll
    for (int o = 16; o; o >>= 1) s += __shfl_xor_sync(0xffffffffu, s, o);
    float mu = s * (1.f / 256.f);
    float q = 0.f;
#pragma unroll
    for (int j = 0; j < 8; j++) { float d = v[j] - mu; q += d * d; }
#pragma unroll
    for (int o = 16; o; o >>= 1) q += __shfl_xor_sync(0xffffffffu, q, o);
    float rs = rsqrtf(q * (1.f / 256.f) + 1e-5f);

    const int c0 = lane * 8;
    float hv[8];
#pragma unroll
    for (int j = 0; j < 8; j++)
        hv[j] = (v[j] - mu) * rs * g1[c0 + j] + b1[c0 + j];
    {
        float4* h4 = (float4*)(H1 + (size_t)row * DMODEL + c0);
        h4[0] = make_float4(hv[0], hv[1], hv[2], hv[3]);
        h4[1] = make_float4(hv[4], hv[5], hv[6], hv[7]);
    }

    s = 0.f;
#pragma unroll
    for (int j = 0; j < 8; j++) s += hv[j];
#pragma unroll
    for (int o = 16; o; o >>= 1) s += __shfl_xor_sync(0xffffffffu, s, o);
    mu = s * (1.f / 256.f);
    q = 0.f;
#pragma unroll
    for (int j = 0; j < 8; j++) { float d = hv[j] - mu; q += d * d; }
#pragma unroll
    for (int o = 16; o; o >>= 1) q += __shfl_xor_sync(0xffffffffu, q, o);
    rs = rsqrtf(q * (1.f / 256.f) + 1e-5f);

    uint4 px;
    float x0 = (hv[0] - mu) * rs * g2[c0 + 0] + b2[c0 + 0];
    float x1 = (hv[1] - mu) * rs * g2[c0 + 1] + b2[c0 + 1];
    float x2 = (hv[2] - mu) * rs * g2[c0 + 2] + b2[c0 + 2];
    float x3 = (hv[3] - mu) * rs * g2[c0 + 3] + b2[c0 + 3];
    float x4 = (hv[4] - mu) * rs * g2[c0 + 4] + b2[c0 + 4];
    float x5 = (hv[5] - mu) * rs * g2[c0 + 5] + b2[c0 + 5];
    float x6 = (hv[6] - mu) * rs * g2[c0 + 6] + b2[c0 + 6];
    float x7 = (hv[7] - mu) * rs * g2[c0 + 7] + b2[c0 + 7];
    px.x = cvt2bf(x1, x0);
    px.y = cvt2bf(x3, x2);
    px.z = cvt2bf(x5, x4);
    px.w = cvt2bf(x7, x6);
    *(uint4*)&X2b[(size_t)row * DMODEL + c0] = px;
}

// ---------------- launch ----------------
extern "C" void kernel_launch(void* const* d_in, const int* in_sizes, int n_in,
                              void* d_out, int out_size) {
    const float* h    = (const float*)d_in[0];
    const float* ea   = (const float*)d_in[1];
    const float* Wq   = (const float*)d_in[2];
    const float* bq   = (const float*)d_in[3];
    const float* Wk   = (const float*)d_in[4];
    const float* bk   = (const float*)d_in[5];
    const float* Wv   = (const float*)d_in[6];
    const float* bv   = (const float*)d_in[7];
    const float* Wo   = (const float*)d_in[8];
    const float* bo   = (const float*)d_in[9];
    const float* We   = (const float*)d_in[10];
    const float* be   = (const float*)d_in[11];
    const float* ln1g = (const float*)d_in[12];
    const float* ln1b = (const float*)d_in[13];
    const float* flng = (const float*)d_in[14];
    const float* flnb = (const float*)d_in[15];
    const float* W1   = (const float*)d_in[16];
    const float* b1   = (const float*)d_in[17];
    const float* W2   = (const float*)d_in[18];
    const float* b2   = (const float*)d_in[19];
    const int*   eidx = (const int*)d_in[20];
    float* out = (float*)d_out;

    __nv_bfloat16 *pQb, *pKb, *pVb, *pAttnb, *pX2b, *pGb, *pWob, *pW1b, *pW2b;
    float *pY, *pH1;
    cudaGetSymbolAddress((void**)&pQb,    g_Qb);
    cudaGetSymbolAddress((void**)&pKb,    g_Kb);
    cudaGetSymbolAddress((void**)&pVb,    g_Vb);
    cudaGetSymbolAddress((void**)&pAttnb, g_attnb);
    cudaGetSymbolAddress((void**)&pX2b,   g_x2b);
    cudaGetSymbolAddress((void**)&pGb,    g_Gb);
    cudaGetSymbolAddress((void**)&pWob,   g_Wob);
    cudaGetSymbolAddress((void**)&pW1b,   g_W1b);
    cudaGetSymbolAddress((void**)&pW2b,   g_W2b);
    cudaGetSymbolAddress((void**)&pY,     g_Y);
    cudaGetSymbolAddress((void**)&pH1,    g_h1);

    conv_kernel<<<1024, 256>>>(h, Wq, Wk, Wv, Wo, W1, W2);
    edge_kernel<<<NEDGE / 256, 256>>>(ea, We, be, eidx);

    gemm_qkv_bf16<<<dim3(12, 64), 128>>>(bq, bk, bv);

    attn_mma<<<dim3(N_NODES / 64, NHEAD, KSPLIT), 128>>>(pQb, pKb, pVb);
    corr_kernel<<<N_NODES / 8, 256>>>(pQb, pKb, pVb);
    combine_kernel<<<(N_NODES * DMODEL / 4) / 256, 256>>>();

    gemm_bf16<<<dim3(4, 64), 128>>>(pAttnb, pWob, bo, h, pY, nullptr,
                                    DMODEL, DMODEL, 0);

    ln_kernel<<<N_NODES / 8, 256>>>(pY, ln1g, ln1b, flng, flnb, pH1, pX2b);

    gemm_bf16<<<dim3(8, 64), 128>>>(pX2b, pW1b, b1, nullptr, nullptr, pGb,
                                    HID, DMODEL, 1);
    gemm_bf16<<<dim3(4, 64), 128>>>(pGb, pW2b, b2, pH1, out, nullptr,
                                    DMODEL, HID, 0);
}

// round 10
// speedup vs baseline: 1.9481x; 1.0067x over previous
#include <cuda_runtime.h>
#include <cuda_bf16.h>
#include <math.h>

#define N_NODES 2048
#define DMODEL  256
#define NHEAD   8
#define DK      32
#define NEDGE   65536
#define HID     512
#define KSPLIT  4
#define CAPL    256
#define ATILES  ((N_NODES / KSPLIT) / 64)

typedef unsigned long long ull;
typedef unsigned int u32;

// ---- mma / ldmatrix / cp.async helpers ----
__device__ __forceinline__ u32 su32(const void* p) {
    return (u32)__cvta_generic_to_shared(p);
}
__device__ __forceinline__ void ldsm_x4(u32& r0, u32& r1, u32& r2, u32& r3, u32 a) {
    asm volatile("ldmatrix.sync.aligned.m8n8.x4.shared.b16 {%0,%1,%2,%3},[%4];"
                 : "=r"(r0), "=r"(r1), "=r"(r2), "=r"(r3) : "r"(a));
}
__device__ __forceinline__ void ldsm_x4t(u32& r0, u32& r1, u32& r2, u32& r3, u32 a) {
    asm volatile("ldmatrix.sync.aligned.m8n8.x4.trans.shared.b16 {%0,%1,%2,%3},[%4];"
                 : "=r"(r0), "=r"(r1), "=r"(r2), "=r"(r3) : "r"(a));
}
__device__ __forceinline__ void mma16816(float& c0, float& c1, float& c2, float& c3,
                                         u32 a0, u32 a1, u32 a2, u32 a3, u32 b0, u32 b1) {
    asm volatile("mma.sync.aligned.m16n8k16.row.col.f32.bf16.bf16.f32 "
                 "{%0,%1,%2,%3},{%4,%5,%6,%7},{%8,%9},{%0,%1,%2,%3};"
                 : "+f"(c0), "+f"(c1), "+f"(c2), "+f"(c3)
                 : "r"(a0), "r"(a1), "r"(a2), "r"(a3), "r"(b0), "r"(b1));
}
__device__ __forceinline__ float ex2f(float x) {
    float r; asm("ex2.approx.f32 %0,%1;" : "=f"(r) : "f"(x)); return r;
}
__device__ __forceinline__ u32 cvt2bf(float hi, float lo) {
    u32 r; asm("cvt.rn.bf16x2.f32 %0,%1,%2;" : "=r"(r) : "f"(hi), "f"(lo)); return r;
}
__device__ __forceinline__ float bflo(u32 w) { return __uint_as_float(w << 16); }
__device__ __forceinline__ float bfhi(u32 w) { return __uint_as_float(w & 0xffff0000u); }
__device__ __forceinline__ void cp16(u32 dst, const void* src) {
    asm volatile("cp.async.ca.shared.global [%0],[%1],16;" :: "r"(dst), "l"(src));
}

// ---------------- scratch ----------------
__device__ __nv_bfloat16 g_hb[N_NODES * DMODEL];
__device__ __nv_bfloat16 g_Wqb[DMODEL * DMODEL];
__device__ __nv_bfloat16 g_Wkb[DMODEL * DMODEL];
__device__ __nv_bfloat16 g_Wvb[DMODEL * DMODEL];
__device__ __nv_bfloat16 g_Wob[DMODEL * DMODEL];
__device__ __nv_bfloat16 g_W1b[DMODEL * HID];
__device__ __nv_bfloat16 g_W2b[HID * DMODEL];
__device__ __nv_bfloat16 g_Qb[N_NODES * DMODEL];
__device__ __nv_bfloat16 g_Kb[N_NODES * DMODEL];
__device__ __nv_bfloat16 g_Vb[N_NODES * DMODEL];
__device__ __nv_bfloat16 g_attnb[N_NODES * DMODEL];
__device__ __nv_bfloat16 g_x2b[N_NODES * DMODEL];
__device__ __nv_bfloat16 g_Gb[N_NODES * HID];
__device__ float g_eb[NEDGE * NHEAD];                 // pre-scaled by log2(e)
__device__ int   g_cnt[N_NODES];
__device__ u32   g_list[N_NODES * CAPL];
__device__ float g_part[KSPLIT * N_NODES * DMODEL];
__device__ float g_lp[KSPLIT * N_NODES * NHEAD];
__device__ float g_Y[N_NODES * DMODEL];
__device__ float g_h1[N_NODES * DMODEL];

// ---------------- fp32 -> bf16 conversions (h + weights) + g_cnt reset ----------
__global__ __launch_bounds__(256) void conv_kernel(const float* __restrict__ h,
                                                   const float* __restrict__ Wq,
                                                   const float* __restrict__ Wk,
                                                   const float* __restrict__ Wv,
                                                   const float* __restrict__ Wo,
                                                   const float* __restrict__ W1,
                                                   const float* __restrict__ W2) {
    int gid = blockIdx.x * 256 + threadIdx.x;
    if (gid < 512) ((int4*)g_cnt)[gid] = make_int4(0, 0, 0, 0);
    const float* src; __nv_bfloat16* dst; int off;
    if (gid < 131072)      { src = h;  dst = g_hb;  off = gid; }
    else if (gid < 147456) { src = Wq; dst = g_Wqb; off = gid - 131072; }
    else if (gid < 163840) { src = Wk; dst = g_Wkb; off = gid - 147456; }
    else if (gid < 180224) { src = Wv; dst = g_Wvb; off = gid - 163840; }
    else if (gid < 196608) { src = Wo; dst = g_Wob; off = gid - 180224; }
    else if (gid < 229376) { src = W1; dst = g_W1b; off = gid - 196608; }
    else                   { src = W2; dst = g_W2b; off = gid - 229376; }
    float4 v = ((const float4*)src)[off];
    uint2 p;
    p.x = cvt2bf(v.y, v.x);
    p.y = cvt2bf(v.w, v.z);
    ((uint2*)dst)[off] = p;
}

// ---------------- edge bias (log2e-scaled) + per-src list append ----------------
__global__ __launch_bounds__(256) void edge_kernel(const float* __restrict__ ea,
                                                   const float* __restrict__ We,
                                                   const float* __restrict__ be,
                                                   const int*   __restrict__ eidx) {
    const float L2E = 1.4426950408889634f;
    int e = blockIdx.x * blockDim.x + threadIdx.x;
    float a[7];
#pragma unroll
    for (int j = 0; j < 7; j++) a[j] = ea[e * 7 + j];
#pragma unroll
    for (int hh = 0; hh < 8; hh++) {
        float v = be[hh];
#pragma unroll
        for (int j = 0; j < 7; j++) v += a[j] * We[j * 8 + hh];
        g_eb[e * 8 + hh] = v * L2E;
    }
    int src = eidx[e];
    int dst = eidx[NEDGE + e];
    int pos = atomicAdd(&g_cnt[src], 1);
    if (pos < CAPL) g_list[(size_t)src * CAPL + pos] = ((u32)dst << 16) | (u32)e;
}

// ---------------- bf16 tensor-core GEMM: 32x64 tile, BK=32, cp.async 3-stage ------
__device__ __forceinline__ void gemm_bf16_body(const __nv_bfloat16* __restrict__ A,
                                               const __nv_bfloat16* __restrict__ B,
                                               const float* __restrict__ bias,
                                               const float* __restrict__ R,
                                               float* __restrict__ Cf,
                                               __nv_bfloat16* __restrict__ Cb,
                                               int N, int K, int gelu,
                                               int bm, int bn) {
    __shared__ __align__(16) __nv_bfloat16 As[3][32][40];
    __shared__ __align__(16) __nv_bfloat16 Bs[3][32][72];
    const int tid = threadIdx.x, warp = tid >> 5, lane = tid & 31;
    const int wm = warp & 1, wn = warp >> 1;
    const int lr = lane & 7, lm = lane >> 3;

    const int ar = tid >> 2, ac = tid & 3;
    const int br0 = tid >> 3, bc = tid & 7;
    const int br1 = br0 + 16;

    const u32 sA = su32(&As[0][0][0]);
    const u32 sB = su32(&Bs[0][0][0]);
    const u32 dstA  = sA + ar * 80 + ac * 16;
    const u32 dstB0 = sB + br0 * 144 + bc * 16;
    const u32 dstB1 = sB + br1 * 144 + bc * 16;
    const __nv_bfloat16* srcA = A + (size_t)(bm + ar) * K + ac * 8;

    const int Kk = K >> 5;
    float acc[4][4] = {};

    auto issue = [&](int kb, int st) {
        if (kb < Kk) {
            cp16(dstA + st * 2560, srcA + kb * 32);
            cp16(dstB0 + st * 4608, B + (size_t)(kb * 32 + br0) * N + bn + bc * 8);
            cp16(dstB1 + st * 4608, B + (size_t)(kb * 32 + br1) * N + bn + bc * 8);
        }
        asm volatile("cp.async.commit_group;");
    };
    issue(0, 0);
    issue(1, 1);

    const u32 aBase = sA + (wm * 16 + lr + (lm & 1) * 8) * 80 + (lm >> 1) * 16;
    const u32 bBase = sB + (lr + (lm & 1) * 8) * 144 + (wn * 32 + (lm >> 1) * 8) * 2;

    for (int kb = 0; kb < Kk; kb++) {
        asm volatile("cp.async.wait_group 1;");
        __syncthreads();
        issue(kb + 2, (kb + 2) % 3);
        const u32 aS = aBase + (kb % 3) * 2560;
        const u32 bS = bBase + (kb % 3) * 4608;
#pragma unroll
        for (int ks = 0; ks < 2; ks++) {
            u32 a0, a1, a2, a3;
            ldsm_x4(a0, a1, a2, a3, aS + ks * 32);
#pragma unroll
            for (int ng2 = 0; ng2 < 2; ng2++) {
                u32 b0, b1, b2, b3;
                ldsm_x4t(b0, b1, b2, b3, bS + ks * 16 * 144 + ng2 * 32);
                mma16816(acc[ng2 * 2][0], acc[ng2 * 2][1], acc[ng2 * 2][2], acc[ng2 * 2][3],
                         a0, a1, a2, a3, b0, b1);
                mma16816(acc[ng2 * 2 + 1][0], acc[ng2 * 2 + 1][1],
                         acc[ng2 * 2 + 1][2], acc[ng2 * 2 + 1][3],
                         a0, a1, a2, a3, b2, b3);
            }
        }
    }

    const int rr = lane >> 2, cql = 2 * (lane & 3);
    const int r0 = bm + wm * 16 + rr, r1 = r0 + 8;
#pragma unroll
    for (int idx = 0; idx < 4; idx++) {
        const int col = bn + wn * 32 + idx * 8 + cql;
        float b0 = bias[col], b1 = bias[col + 1];
        float o0 = acc[idx][0] + b0, o1 = acc[idx][1] + b1;
        float o2 = acc[idx][2] + b0, o3 = acc[idx][3] + b1;
        if (gelu) {
            o0 *= normcdff(o0); o1 *= normcdff(o1);
            o2 *= normcdff(o2); o3 *= normcdff(o3);
        }
        if (R) {
            o0 += R[(size_t)r0 * N + col]; o1 += R[(size_t)r0 * N + col + 1];
            o2 += R[(size_t)r1 * N + col]; o3 += R[(size_t)r1 * N + col + 1];
        }
        if (Cb) {
            *(u32*)&Cb[(size_t)r0 * N + col] = cvt2bf(o1, o0);
            *(u32*)&Cb[(size_t)r1 * N + col] = cvt2bf(o3, o2);
        } else {
            *(float2*)&Cf[(size_t)r0 * N + col] = make_float2(o0, o1);
            *(float2*)&Cf[(size_t)r1 * N + col] = make_float2(o2, o3);
        }
    }
}

__global__ __launch_bounds__(128) void gemm_bf16(const __nv_bfloat16* __restrict__ A,
                                                 const __nv_bfloat16* __restrict__ B,
                                                 const float* __restrict__ bias,
                                                 const float* __restrict__ R,
                                                 float* __restrict__ Cf,
                                                 __nv_bfloat16* __restrict__ Cb,
                                                 int N, int K, int gelu) {
    gemm_bf16_body(A, B, bias, R, Cf, Cb, N, K, gelu, blockIdx.y * 32, blockIdx.x * 64);
}

__global__ __launch_bounds__(128) void gemm_qkv_bf16(const float* __restrict__ bq,
                                                     const float* __restrict__ bk,
                                                     const float* __restrict__ bv) {
    int sel = blockIdx.x >> 2;
    int bn  = (blockIdx.x & 3) * 64;
    const __nv_bfloat16* B = (sel == 0) ? g_Wqb : (sel == 1) ? g_Wkb : g_Wvb;
    const float* bias      = (sel == 0) ? bq : (sel == 1) ? bk : bv;
    __nv_bfloat16* Cb      = (sel == 0) ? g_Qb : (sel == 1) ? g_Kb : g_Vb;
    gemm_bf16_body(g_hb, B, bias, nullptr, nullptr, Cb, DMODEL, DMODEL, 0,
                   blockIdx.y * 32, bn);
}

// ---------------- dense flash attention: 128 queries/block, split-K, cp.async ----
__global__ __launch_bounds__(128, 3) void attn_mma(const __nv_bfloat16* __restrict__ Qb,
                                                   const __nv_bfloat16* __restrict__ Kb,
                                                   const __nv_bfloat16* __restrict__ Vb) {
    __shared__ __align__(16) __nv_bfloat16 Qs[128][40];
    __shared__ __align__(16) __nv_bfloat16 Ks[3][64][40];
    __shared__ __align__(16) __nv_bfloat16 Vs[3][64][40];

    const int h     = blockIdx.y;
    const int qb    = blockIdx.x * 128;
    const int chunk = blockIdx.z;
    const int kb0   = chunk * (N_NODES / KSPLIT);
    const int tid = threadIdx.x;
    const int warp = tid >> 5, lane = tid & 31;

    // stage Q (128 rows x 32 cols): 512 16B tasks
#pragma unroll
    for (int i = 0; i < 4; i++) {
        int task = tid + 128 * i;
        int row = task >> 2, ch = task & 3;
        *(uint4*)((char*)&Qs[row][0] + ch * 16) =
            *(const uint4*)((const char*)(Qb + (size_t)(qb + row) * DMODEL + h * DK) + ch * 16);
    }
    __syncthreads();
    const int lr = lane & 7, lm = lane >> 3;
    u32 qa[2][2][4];
#pragma unroll
    for (int s = 0; s < 2; s++) {
        int row = warp * 32 + s * 16 + lr + (lm & 1) * 8;
#pragma unroll
        for (int c = 0; c < 2; c++) {
            u32 a = su32(&Qs[row][c * 16 + (lm >> 1) * 8]);
            ldsm_x4(qa[s][c][0], qa[s][c][1], qa[s][c][2], qa[s][c][3], a);
        }
    }

    // cp.async staging for K/V tiles (64 keys)
    const int row0 = tid >> 2, ch0 = tid & 3;
    const int row1 = (tid + 128) >> 2, ch1 = (tid + 128) & 3;
    const u32 kd0 = su32(&Ks[0][row0][0]) + ch0 * 16;
    const u32 kd1 = su32(&Ks[0][row1][0]) + ch1 * 16;
    const u32 vd0 = su32(&Vs[0][row0][0]) + ch0 * 16;
    const u32 vd1 = su32(&Vs[0][row1][0]) + ch1 * 16;

    auto issueT = [&](int kt, int st) {
        if (kt < ATILES) {
            int kb = kb0 + kt * 64;
            cp16(kd0 + st * 5120, (const char*)(Kb + (size_t)(kb + row0) * DMODEL + h * DK) + ch0 * 16);
            cp16(kd1 + st * 5120, (const char*)(Kb + (size_t)(kb + row1) * DMODEL + h * DK) + ch1 * 16);
            cp16(vd0 + st * 5120, (const char*)(Vb + (size_t)(kb + row0) * DMODEL + h * DK) + ch0 * 16);
            cp16(vd1 + st * 5120, (const char*)(Vb + (size_t)(kb + row1) * DMODEL + h * DK) + ch1 * 16);
        }
        asm volatile("cp.async.commit_group;");
    };
    issueT(0, 0);
    issueT(1, 1);

    const u32 kaddr = su32(&Ks[0][lr][lm * 8]);
    const u32 vaddr = su32(&Vs[0][lr + (lm & 1) * 8][(lm >> 1) * 8]);

    float O[2][4][4];
#pragma unroll
    for (int s = 0; s < 2; s++)
#pragma unroll
        for (int t = 0; t < 4; t++)
#pragma unroll
            for (int j = 0; j < 4; j++) O[s][t][j] = 0.f;
    float l[2][2] = {};

    const float SCALE2 = 1.4426950408889634f * 0.17677669529663688f;

    for (int kt = 0; kt < ATILES; kt++) {
        asm volatile("cp.async.wait_group 1;");
        __syncthreads();
        issueT(kt + 2, (kt + 2) % 3);
        const u32 kS = kaddr + (kt % 3) * 5120;
        const u32 vS = vaddr + (kt % 3) * 5120;

        u32 P[2][8][2];
#pragma unroll
        for (int kg = 0; kg < 8; kg++) {
            u32 b0, b1, b2, b3;
            ldsm_x4(b0, b1, b2, b3, kS + kg * 640);
#pragma unroll
            for (int s = 0; s < 2; s++) {
                float c0 = 0.f, c1 = 0.f, c2 = 0.f, c3 = 0.f;
                mma16816(c0, c1, c2, c3, qa[s][0][0], qa[s][0][1], qa[s][0][2], qa[s][0][3], b0, b1);
                mma16816(c0, c1, c2, c3, qa[s][1][0], qa[s][1][1], qa[s][1][2], qa[s][1][3], b2, b3);
                float p0 = ex2f(c0 * SCALE2);
                float p1 = ex2f(c1 * SCALE2);
                float p2 = ex2f(c2 * SCALE2);
                float p3 = ex2f(c3 * SCALE2);
                l[s][0] += p0 + p1;
                l[s][1] += p2 + p3;
                P[s][kg][0] = cvt2bf(p1, p0);
                P[s][kg][1] = cvt2bf(p3, p2);
            }
        }

#pragma unroll
        for (int ck = 0; ck < 4; ck++) {
#pragma unroll
            for (int tp = 0; tp < 2; tp++) {
                u32 v0, v1, v2, v3;
                ldsm_x4t(v0, v1, v2, v3, vS + ck * 1280 + tp * 32);
#pragma unroll
                for (int s = 0; s < 2; s++) {
                    u32 a0 = P[s][2 * ck][0], a1 = P[s][2 * ck][1];
                    u32 a2 = P[s][2 * ck + 1][0], a3 = P[s][2 * ck + 1][1];
                    mma16816(O[s][2 * tp][0], O[s][2 * tp][1], O[s][2 * tp][2], O[s][2 * tp][3],
                             a0, a1, a2, a3, v0, v1);
                    mma16816(O[s][2 * tp + 1][0], O[s][2 * tp + 1][1],
                             O[s][2 * tp + 1][2], O[s][2 * tp + 1][3],
                             a0, a1, a2, a3, v2, v3);
                }
            }
        }
    }

    const int cql = 2 * (lane & 3);
    float* part = g_part + (size_t)chunk * N_NODES * DMODEL;
#pragma unroll
    for (int s = 0; s < 2; s++) {
        float l0 = l[s][0], l1 = l[s][1];
        l0 += __shfl_xor_sync(0xffffffffu, l0, 1);
        l0 += __shfl_xor_sync(0xffffffffu, l0, 2);
        l1 += __shfl_xor_sync(0xffffffffu, l1, 1);
        l1 += __shfl_xor_sync(0xffffffffu, l1, 2);
        const int r0 = qb + warp * 32 + s * 16 + (lane >> 2);
        const int r1 = r0 + 8;
#pragma unroll
        for (int t = 0; t < 4; t++) {
            int col = h * DK + t * 8 + cql;
            *(float2*)&part[(size_t)r0 * DMODEL + col] = make_float2(O[s][t][0], O[s][t][1]);
            *(float2*)&part[(size_t)r1 * DMODEL + col] = make_float2(O[s][t][2], O[s][t][3]);
        }
        if ((lane & 3) == 0) {
            g_lp[((size_t)chunk * N_NODES + r0) * NHEAD + h] = l0;
            g_lp[((size_t)chunk * N_NODES + r1) * NHEAD + h] = l1;
        }
    }
}

// ---------------- sparse bias correction + final combine -> bf16 attn ----------
__global__ __launch_bounds__(256) void corr_kernel(const __nv_bfloat16* __restrict__ Qb,
                                                   const __nv_bfloat16* __restrict__ Kb,
                                                   const __nv_bfloat16* __restrict__ Vb) {
    __shared__ u32 slist[8][CAPL];
    __shared__ u32 wlist[8][CAPL];
    const int w    = threadIdx.x >> 5;
    const int q    = blockIdx.x * 8 + w;
    const int lane = threadIdx.x & 31;
    const int h = lane >> 2, g = lane & 3;
    const float SCALE2 = 1.4426950408889634f * 0.17677669529663688f;
    const u32 lmask_lt = (1u << lane) - 1u;

    float qv[8];
    {
        uint4 wq = *(const uint4*)(Qb + (size_t)q * DMODEL + h * DK + g * 8);
        const u32 ws[4] = {wq.x, wq.y, wq.z, wq.w};
#pragma unroll
        for (int i = 0; i < 4; i++) {
            qv[2 * i]     = bflo(ws[i]) * SCALE2;
            qv[2 * i + 1] = bfhi(ws[i]) * SCALE2;
        }
    }

    int cnt = g_cnt[q];
    if (cnt > CAPL) cnt = CAPL;
    for (int i = lane; i < cnt; i += 32)
        slist[w][i] = g_list[(size_t)q * CAPL + i];
    __syncwarp();

    // dedup (winner = max (dst<<16)|e per dst) + compact
    int ncnt = 0;
    for (int base = 0; base < cnt; base += 32) {
        int i = base + lane;
        u32 v = 0;
        bool win = false;
        if (i < cnt) {
            v = slist[w][i];
            win = true;
            for (int j = 0; j < cnt; j++) {
                u32 u = slist[w][j];
                if (((u ^ v) & 0xFFFF0000u) == 0 && u > v) win = false;
            }
        }
        u32 m = __ballot_sync(0xffffffffu, win);
        if (win) wlist[w][ncnt + __popc(m & lmask_lt)] = v;
        ncnt += __popc(m);
    }
    __syncwarp();

    float O[8];
#pragma unroll
    for (int i = 0; i < 8; i++) O[i] = 0.f;
    float lacc = 0.f;

    for (int i = 0; i < ncnt; i += 4) {
#pragma unroll
        for (int j = 0; j < 4; j++) {
            if (i + j >= ncnt) break;               // warp-uniform
            u32 v = wlist[w][i + j];
            int k    = (int)(v >> 16);
            int widx = (int)(v & 0xFFFFu);
            uint4 kw = *(const uint4*)(Kb + (size_t)k * DMODEL + h * DK + g * 8);
            uint4 vw = *(const uint4*)(Vb + (size_t)k * DMODEL + h * DK + g * 8);
            float eb = g_eb[(size_t)widx * 8 + h];
            const u32 ks[4] = {kw.x, kw.y, kw.z, kw.w};
            float s = 0.f;
#pragma unroll
            for (int t = 0; t < 4; t++) {
                s += qv[2 * t] * bflo(ks[t]);
                s += qv[2 * t + 1] * bfhi(ks[t]);
            }
            s += __shfl_xor_sync(0xffffffffu, s, 1);
            s += __shfl_xor_sync(0xffffffffu, s, 2);
            float pd = ex2f(s + eb) - ex2f(s);
            lacc += pd;
            const u32 vs[4] = {vw.x, vw.y, vw.z, vw.w};
#pragma unroll
            for (int t = 0; t < 4; t++) {
                O[2 * t]     += pd * bflo(vs[t]);
                O[2 * t + 1] += pd * bfhi(vs[t]);
            }
        }
    }

    // combine with dense split-K partials, normalize, emit bf16
    float ltot = lacc;
#pragma unroll
    for (int c = 0; c < KSPLIT; c++)
        ltot += g_lp[((size_t)c * N_NODES + q) * NHEAD + h];
    const int col = h * DK + g * 8;
#pragma unroll
    for (int c = 0; c < KSPLIT; c++) {
        const float* p = g_part + ((size_t)c * N_NODES + q) * DMODEL + col;
        float4 p0 = *(const float4*)&p[0];
        float4 p1 = *(const float4*)&p[4];
        O[0] += p0.x; O[1] += p0.y; O[2] += p0.z; O[3] += p0.w;
        O[4] += p1.x; O[5] += p1.y; O[6] += p1.z; O[7] += p1.w;
    }
    float inv = 1.f / ltot;
    uint4 px;
    px.x = cvt2bf(O[1] * inv, O[0] * inv);
    px.y = cvt2bf(O[3] * inv, O[2] * inv);
    px.z = cvt2bf(O[5] * inv, O[4] * inv);
    px.w = cvt2bf(O[7] * inv, O[6] * inv);
    *(uint4*)&g_attnb[(size_t)q * DMODEL + col] = px;
}

// ---------------- fused double LayerNorm ----------------
__global__ __launch_bounds__(256) void ln_kernel(const float* __restrict__ Y,
                                                 const float* __restrict__ g1,
                                                 const float* __restrict__ b1,
                                                 const float* __restrict__ g2,
                                                 const float* __restrict__ b2,
                                                 float* __restrict__ H1,
                                                 __nv_bfloat16* __restrict__ X2b) {
    const int lane = threadIdx.x & 31;
    const int row  = blockIdx.x * 8 + (threadIdx.x >> 5);
    const float4* y4 = (const float4*)(Y + (size_t)row * DMODEL);
    float v[8];
    {
        float4 a = y4[lane * 2], b = y4[lane * 2 + 1];
        v[0] = a.x; v[1] = a.y; v[2] = a.z; v[3] = a.w;
        v[4] = b.x; v[5] = b.y; v[6] = b.z; v[7] = b.w;
    }

    float s = 0.f;
#pragma unroll
    for (int j = 0; j < 8; j++) s += v[j];
#pragma unroll
    for (int o = 16; o; o >>= 1) s += __shfl_xor_sync(0xffffffffu, s, o);
    float mu = s * (1.f / 256.f);
    float q = 0.f;
#pragma unroll
    for (int j = 0; j < 8; j++) { float d = v[j] - mu; q += d * d; }
#pragma unroll
    for (int o = 16; o; o >>= 1) q += __shfl_xor_sync(0xffffffffu, q, o);
    float rs = rsqrtf(q * (1.f / 256.f) + 1e-5f);

    const int c0 = lane * 8;
    float hv[8];
#pragma unroll
    for (int j = 0; j < 8; j++)
        hv[j] = (v[j] - mu) * rs * g1[c0 + j] + b1[c0 + j];
    {
        float4* h4 = (float4*)(H1 + (size_t)row * DMODEL + c0);
        h4[0] = make_float4(hv[0], hv[1], hv[2], hv[3]);
        h4[1] = make_float4(hv[4], hv[5], hv[6], hv[7]);
    }

    s = 0.f;
#pragma unroll
    for (int j = 0; j < 8; j++) s += hv[j];
#pragma unroll
    for (int o = 16; o; o >>= 1) s += __shfl_xor_sync(0xffffffffu, s, o);
    mu = s * (1.f / 256.f);
    q = 0.f;
#pragma unroll
    for (int j = 0; j < 8; j++) { float d = hv[j] - mu; q += d * d; }
#pragma unroll
    for (int o = 16; o; o >>= 1) q += __shfl_xor_sync(0xffffffffu, q, o);
    rs = rsqrtf(q * (1.f / 256.f) + 1e-5f);

    uint4 px;
    float x0 = (hv[0] - mu) * rs * g2[c0 + 0] + b2[c0 + 0];
    float x1 = (hv[1] - mu) * rs * g2[c0 + 1] + b2[c0 + 1];
    float x2 = (hv[2] - mu) * rs * g2[c0 + 2] + b2[c0 + 2];
    float x3 = (hv[3] - mu) * rs * g2[c0 + 3] + b2[c0 + 3];
    float x4 = (hv[4] - mu) * rs * g2[c0 + 4] + b2[c0 + 4];
    float x5 = (hv[5] - mu) * rs * g2[c0 + 5] + b2[c0 + 5];
    float x6 = (hv[6] - mu) * rs * g2[c0 + 6] + b2[c0 + 6];
    float x7 = (hv[7] - mu) * rs * g2[c0 + 7] + b2[c0 + 7];
    px.x = cvt2bf(x1, x0);
    px.y = cvt2bf(x3, x2);
    px.z = cvt2bf(x5, x4);
    px.w = cvt2bf(x7, x6);
    *(uint4*)&X2b[(size_t)row * DMODEL + c0] = px;
}

// ---------------- launch ----------------
extern "C" void kernel_launch(void* const* d_in, const int* in_sizes, int n_in,
                              void* d_out, int out_size) {
    const float* h    = (const float*)d_in[0];
    const float* ea   = (const float*)d_in[1];
    const float* Wq   = (const float*)d_in[2];
    const float* bq   = (const float*)d_in[3];
    const float* Wk   = (const float*)d_in[4];
    const float* bk   = (const float*)d_in[5];
    const float* Wv   = (const float*)d_in[6];
    const float* bv   = (const float*)d_in[7];
    const float* Wo   = (const float*)d_in[8];
    const float* bo   = (const float*)d_in[9];
    const float* We   = (const float*)d_in[10];
    const float* be   = (const float*)d_in[11];
    const float* ln1g = (const float*)d_in[12];
    const float* ln1b = (const float*)d_in[13];
    const float* flng = (const float*)d_in[14];
    const float* flnb = (const float*)d_in[15];
    const float* W1   = (const float*)d_in[16];
    const float* b1   = (const float*)d_in[17];
    const float* W2   = (const float*)d_in[18];
    const float* b2   = (const float*)d_in[19];
    const int*   eidx = (const int*)d_in[20];
    float* out = (float*)d_out;

    __nv_bfloat16 *pQb, *pKb, *pVb, *pAttnb, *pX2b, *pGb, *pWob, *pW1b, *pW2b;
    float *pY, *pH1;
    cudaGetSymbolAddress((void**)&pQb,    g_Qb);
    cudaGetSymbolAddress((void**)&pKb,    g_Kb);
    cudaGetSymbolAddress((void**)&pVb,    g_Vb);
    cudaGetSymbolAddress((void**)&pAttnb, g_attnb);
    cudaGetSymbolAddress((void**)&pX2b,   g_x2b);
    cudaGetSymbolAddress((void**)&pGb,    g_Gb);
    cudaGetSymbolAddress((void**)&pWob,   g_Wob);
    cudaGetSymbolAddress((void**)&pW1b,   g_W1b);
    cudaGetSymbolAddress((void**)&pW2b,   g_W2b);
    cudaGetSymbolAddress((void**)&pY,     g_Y);
    cudaGetSymbolAddress((void**)&pH1,    g_h1);

    conv_kernel<<<1024, 256>>>(h, Wq, Wk, Wv, Wo, W1, W2);
    edge_kernel<<<NEDGE / 256, 256>>>(ea, We, be, eidx);

    gemm_qkv_bf16<<<dim3(12, 64), 128>>>(bq, bk, bv);

    attn_mma<<<dim3(N_NODES / 128, NHEAD, KSPLIT), 128>>>(pQb, pKb, pVb);
    corr_kernel<<<N_NODES / 8, 256>>>(pQb, pKb, pVb);

    gemm_bf16<<<dim3(4, 64), 128>>>(pAttnb, pWob, bo, h, pY, nullptr,
                                    DMODEL, DMODEL, 0);

    ln_kernel<<<N_NODES / 8, 256>>>(pY, ln1g, ln1b, flng, flnb, pH1, pX2b);

    gemm_bf16<<<dim3(8, 64), 128>>>(pX2b, pW1b, b1, nullptr, nullptr, pGb,
                                    HID, DMODEL, 1);
    gemm_bf16<<<dim3(4, 64), 128>>>(pGb, pW2b, b2, pH1, out, nullptr,
                                    DMODEL, HID, 0);
}

// round 11
// speedup vs baseline: 2.0661x; 1.0606x over previous
#include <cuda_runtime.h>
#include <cuda_fp16.h>
#include <math.h>

#define N_NODES 2048
#define DMODEL  256
#define NHEAD   8
#define DK      32
#define NEDGE   65536
#define HID     512
#define KSPLIT  8
#define CAPL    256
#define ATILES  ((N_NODES / KSPLIT) / 64)

typedef unsigned long long ull;
typedef unsigned int u32;

// ---- mma / ldmatrix / cp.async helpers ----
__device__ __forceinline__ u32 su32(const void* p) {
    return (u32)__cvta_generic_to_shared(p);
}
__device__ __forceinline__ void ldsm_x4(u32& r0, u32& r1, u32& r2, u32& r3, u32 a) {
    asm volatile("ldmatrix.sync.aligned.m8n8.x4.shared.b16 {%0,%1,%2,%3},[%4];"
                 : "=r"(r0), "=r"(r1), "=r"(r2), "=r"(r3) : "r"(a));
}
__device__ __forceinline__ void ldsm_x4t(u32& r0, u32& r1, u32& r2, u32& r3, u32 a) {
    asm volatile("ldmatrix.sync.aligned.m8n8.x4.trans.shared.b16 {%0,%1,%2,%3},[%4];"
                 : "=r"(r0), "=r"(r1), "=r"(r2), "=r"(r3) : "r"(a));
}
__device__ __forceinline__ void mma16816h(float& c0, float& c1, float& c2, float& c3,
                                          u32 a0, u32 a1, u32 a2, u32 a3, u32 b0, u32 b1) {
    asm volatile("mma.sync.aligned.m16n8k16.row.col.f32.f16.f16.f32 "
                 "{%0,%1,%2,%3},{%4,%5,%6,%7},{%8,%9},{%0,%1,%2,%3};"
                 : "+f"(c0), "+f"(c1), "+f"(c2), "+f"(c3)
                 : "r"(a0), "r"(a1), "r"(a2), "r"(a3), "r"(b0), "r"(b1));
}
__device__ __forceinline__ float ex2f(float x) {
    float r; asm("ex2.approx.f32 %0,%1;" : "=f"(r) : "f"(x)); return r;
}
__device__ __forceinline__ u32 ex2h2(u32 a) {
    u32 r; asm("ex2.approx.f16x2 %0,%1;" : "=r"(r) : "r"(a)); return r;
}
__device__ __forceinline__ u32 f2h2(float lo, float hi) {
    __half2 h = __floats2half2_rn(lo, hi);
    return *(u32*)&h;
}
__device__ __forceinline__ float hlo(u32 w) { __half2 h = *(__half2*)&w; return __low2float(h); }
__device__ __forceinline__ float hhi(u32 w) { __half2 h = *(__half2*)&w; return __high2float(h); }
__device__ __forceinline__ void cp16(u32 dst, const void* src) {
    asm volatile("cp.async.ca.shared.global [%0],[%1],16;" :: "r"(dst), "l"(src));
}

// ---------------- scratch ----------------
__device__ __half g_hb[N_NODES * DMODEL];
__device__ __half g_Wqb[DMODEL * DMODEL];
__device__ __half g_Wkb[DMODEL * DMODEL];
__device__ __half g_Wvb[DMODEL * DMODEL];
__device__ __half g_Wob[DMODEL * DMODEL];
__device__ __half g_W1b[DMODEL * HID];
__device__ __half g_W2b[HID * DMODEL];
__device__ __half g_Qb[N_NODES * DMODEL];     // pre-scaled by log2e/sqrt(dk)
__device__ __half g_Kb[N_NODES * DMODEL];
__device__ __half g_Vb[N_NODES * DMODEL];
__device__ __half g_attnb[N_NODES * DMODEL];
__device__ __half g_x2b[N_NODES * DMODEL];
__device__ __half g_Gb[N_NODES * HID];
__device__ float g_eb[NEDGE * NHEAD];         // pre-scaled by log2(e)
__device__ int   g_cnt[N_NODES];              // self-resetting (corr zeroes it)
__device__ u32   g_list[N_NODES * CAPL];
__device__ float g_part[KSPLIT * N_NODES * DMODEL];
__device__ float g_lp[KSPLIT * N_NODES * NHEAD];
__device__ float g_Y[N_NODES * DMODEL];
__device__ float g_h1[N_NODES * DMODEL];

// ---------------- conv (blocks 0..1023) + edge (blocks 1024..1279) ----------------
__global__ __launch_bounds__(256) void prep_kernel(const float* __restrict__ h,
                                                   const float* __restrict__ Wq,
                                                   const float* __restrict__ Wk,
                                                   const float* __restrict__ Wv,
                                                   const float* __restrict__ Wo,
                                                   const float* __restrict__ W1,
                                                   const float* __restrict__ W2,
                                                   const float* __restrict__ ea,
                                                   const float* __restrict__ We,
                                                   const float* __restrict__ be,
                                                   const int*   __restrict__ eidx) {
    int gid = blockIdx.x * 256 + threadIdx.x;
    if (gid < 262144) {
        const float* src; __half* dst; int off;
        if (gid < 131072)      { src = h;  dst = g_hb;  off = gid; }
        else if (gid < 147456) { src = Wq; dst = g_Wqb; off = gid - 131072; }
        else if (gid < 163840) { src = Wk; dst = g_Wkb; off = gid - 147456; }
        else if (gid < 180224) { src = Wv; dst = g_Wvb; off = gid - 163840; }
        else if (gid < 196608) { src = Wo; dst = g_Wob; off = gid - 180224; }
        else if (gid < 229376) { src = W1; dst = g_W1b; off = gid - 196608; }
        else                   { src = W2; dst = g_W2b; off = gid - 229376; }
        float4 v = ((const float4*)src)[off];
        uint2 p;
        p.x = f2h2(v.x, v.y);
        p.y = f2h2(v.z, v.w);
        ((uint2*)dst)[off] = p;
    } else {
        const float L2E = 1.4426950408889634f;
        int e = gid - 262144;
        float a[7];
#pragma unroll
        for (int j = 0; j < 7; j++) a[j] = ea[e * 7 + j];
#pragma unroll
        for (int hh = 0; hh < 8; hh++) {
            float v = be[hh];
#pragma unroll
            for (int j = 0; j < 7; j++) v += a[j] * We[j * 8 + hh];
            g_eb[e * 8 + hh] = v * L2E;
        }
        int src = eidx[e];
        int dst = eidx[NEDGE + e];
        int pos = atomicAdd(&g_cnt[src], 1);
        if (pos < CAPL) g_list[(size_t)src * CAPL + pos] = ((u32)dst << 16) | (u32)e;
    }
}

// ---------------- fp16 tensor-core GEMM: 32x64 tile, BK=32, cp.async 4-stage ------
__device__ __forceinline__ void gemm_f16_body(const __half* __restrict__ A,
                                              const __half* __restrict__ B,
                                              const float* __restrict__ bias,
                                              const float* __restrict__ R,
                                              float* __restrict__ Cf,
                                              __half* __restrict__ Cb,
                                              int N, int K, int gelu, float oscale,
                                              int bm, int bn) {
    __shared__ __align__(16) __half As[4][32][40];
    __shared__ __align__(16) __half Bs[4][32][72];
    const int tid = threadIdx.x, warp = tid >> 5, lane = tid & 31;
    const int wm = warp & 1, wn = warp >> 1;
    const int lr = lane & 7, lm = lane >> 3;

    const int ar = tid >> 2, ac = tid & 3;
    const int br0 = tid >> 3, bc = tid & 7;
    const int br1 = br0 + 16;

    const u32 sA = su32(&As[0][0][0]);
    const u32 sB = su32(&Bs[0][0][0]);
    const u32 dstA  = sA + ar * 80 + ac * 16;
    const u32 dstB0 = sB + br0 * 144 + bc * 16;
    const u32 dstB1 = sB + br1 * 144 + bc * 16;
    const __half* srcA = A + (size_t)(bm + ar) * K + ac * 8;

    const int Kk = K >> 5;
    float acc[4][4] = {};

    auto issue = [&](int kb, int st) {
        if (kb < Kk) {
            cp16(dstA + st * 2560, srcA + kb * 32);
            cp16(dstB0 + st * 4608, B + (size_t)(kb * 32 + br0) * N + bn + bc * 8);
            cp16(dstB1 + st * 4608, B + (size_t)(kb * 32 + br1) * N + bn + bc * 8);
        }
        asm volatile("cp.async.commit_group;");
    };
    issue(0, 0);
    issue(1, 1);
    issue(2, 2);

    const u32 aBase = sA + (wm * 16 + lr + (lm & 1) * 8) * 80 + (lm >> 1) * 16;
    const u32 bBase = sB + (lr + (lm & 1) * 8) * 144 + (wn * 32 + (lm >> 1) * 8) * 2;

    for (int kb = 0; kb < Kk; kb++) {
        asm volatile("cp.async.wait_group 2;");
        __syncthreads();
        issue(kb + 3, (kb + 3) & 3);
        const u32 aS = aBase + (kb & 3) * 2560;
        const u32 bS = bBase + (kb & 3) * 4608;
#pragma unroll
        for (int ks = 0; ks < 2; ks++) {
            u32 a0, a1, a2, a3;
            ldsm_x4(a0, a1, a2, a3, aS + ks * 32);
#pragma unroll
            for (int ng2 = 0; ng2 < 2; ng2++) {
                u32 b0, b1, b2, b3;
                ldsm_x4t(b0, b1, b2, b3, bS + ks * 16 * 144 + ng2 * 32);
                mma16816h(acc[ng2 * 2][0], acc[ng2 * 2][1], acc[ng2 * 2][2], acc[ng2 * 2][3],
                          a0, a1, a2, a3, b0, b1);
                mma16816h(acc[ng2 * 2 + 1][0], acc[ng2 * 2 + 1][1],
                          acc[ng2 * 2 + 1][2], acc[ng2 * 2 + 1][3],
                          a0, a1, a2, a3, b2, b3);
            }
        }
    }

    const int rr = lane >> 2, cql = 2 * (lane & 3);
    const int r0 = bm + wm * 16 + rr, r1 = r0 + 8;
#pragma unroll
    for (int idx = 0; idx < 4; idx++) {
        const int col = bn + wn * 32 + idx * 8 + cql;
        float b0 = bias[col], b1 = bias[col + 1];
        float o0 = (acc[idx][0] + b0) * oscale, o1 = (acc[idx][1] + b1) * oscale;
        float o2 = (acc[idx][2] + b0) * oscale, o3 = (acc[idx][3] + b1) * oscale;
        if (gelu) {
            o0 *= normcdff(o0); o1 *= normcdff(o1);
            o2 *= normcdff(o2); o3 *= normcdff(o3);
        }
        if (R) {
            o0 += R[(size_t)r0 * N + col]; o1 += R[(size_t)r0 * N + col + 1];
            o2 += R[(size_t)r1 * N + col]; o3 += R[(size_t)r1 * N + col + 1];
        }
        if (Cb) {
            *(u32*)&Cb[(size_t)r0 * N + col] = f2h2(o0, o1);
            *(u32*)&Cb[(size_t)r1 * N + col] = f2h2(o2, o3);
        } else {
            *(float2*)&Cf[(size_t)r0 * N + col] = make_float2(o0, o1);
            *(float2*)&Cf[(size_t)r1 * N + col] = make_float2(o2, o3);
        }
    }
}

__global__ __launch_bounds__(128) void gemm_f16(const __half* __restrict__ A,
                                                const __half* __restrict__ B,
                                                const float* __restrict__ bias,
                                                const float* __restrict__ R,
                                                float* __restrict__ Cf,
                                                __half* __restrict__ Cb,
                                                int N, int K, int gelu) {
    gemm_f16_body(A, B, bias, R, Cf, Cb, N, K, gelu, 1.0f, blockIdx.y * 32, blockIdx.x * 64);
}

__global__ __launch_bounds__(128) void gemm_qkv_f16(const float* __restrict__ bq,
                                                    const float* __restrict__ bk,
                                                    const float* __restrict__ bv) {
    const float SCALE2 = 1.4426950408889634f * 0.17677669529663688f;
    int sel = blockIdx.x >> 2;
    int bn  = (blockIdx.x & 3) * 64;
    const __half* B   = (sel == 0) ? g_Wqb : (sel == 1) ? g_Wkb : g_Wvb;
    const float* bias = (sel == 0) ? bq : (sel == 1) ? bk : bv;
    __half* Cb        = (sel == 0) ? g_Qb : (sel == 1) ? g_Kb : g_Vb;
    float oscale      = (sel == 0) ? SCALE2 : 1.0f;
    gemm_f16_body(g_hb, B, bias, nullptr, nullptr, Cb, DMODEL, DMODEL, 0, oscale,
                  blockIdx.y * 32, bn);
}

// ---------------- dense flash attention: 128 q/block, split-K=8, f16x2 exp ----
__global__ __launch_bounds__(128, 3) void attn_mma(const __half* __restrict__ Qb,
                                                   const __half* __restrict__ Kb,
                                                   const __half* __restrict__ Vb) {
    __shared__ __align__(16) __half Qs[128][40];
    __shared__ __align__(16) __half Ks[3][64][40];
    __shared__ __align__(16) __half Vs[3][64][40];

    const int h     = blockIdx.y;
    const int qb    = blockIdx.x * 128;
    const int chunk = blockIdx.z;
    const int kb0   = chunk * (N_NODES / KSPLIT);
    const int tid = threadIdx.x;
    const int warp = tid >> 5, lane = tid & 31;

#pragma unroll
    for (int i = 0; i < 4; i++) {
        int task = tid + 128 * i;
        int row = task >> 2, ch = task & 3;
        *(uint4*)((char*)&Qs[row][0] + ch * 16) =
            *(const uint4*)((const char*)(Qb + (size_t)(qb + row) * DMODEL + h * DK) + ch * 16);
    }
    __syncthreads();
    const int lr = lane & 7, lm = lane >> 3;
    u32 qa[2][2][4];
#pragma unroll
    for (int s = 0; s < 2; s++) {
        int row = warp * 32 + s * 16 + lr + (lm & 1) * 8;
#pragma unroll
        for (int c = 0; c < 2; c++) {
            u32 a = su32(&Qs[row][c * 16 + (lm >> 1) * 8]);
            ldsm_x4(qa[s][c][0], qa[s][c][1], qa[s][c][2], qa[s][c][3], a);
        }
    }

    const int row0 = tid >> 2, ch0 = tid & 3;
    const int row1 = (tid + 128) >> 2, ch1 = (tid + 128) & 3;
    const u32 kd0 = su32(&Ks[0][row0][0]) + ch0 * 16;
    const u32 kd1 = su32(&Ks[0][row1][0]) + ch1 * 16;
    const u32 vd0 = su32(&Vs[0][row0][0]) + ch0 * 16;
    const u32 vd1 = su32(&Vs[0][row1][0]) + ch1 * 16;

    auto issueT = [&](int kt, int st) {
        if (kt < ATILES) {
            int kb = kb0 + kt * 64;
            cp16(kd0 + st * 5120, (const char*)(Kb + (size_t)(kb + row0) * DMODEL + h * DK) + ch0 * 16);
            cp16(kd1 + st * 5120, (const char*)(Kb + (size_t)(kb + row1) * DMODEL + h * DK) + ch1 * 16);
            cp16(vd0 + st * 5120, (const char*)(Vb + (size_t)(kb + row0) * DMODEL + h * DK) + ch0 * 16);
            cp16(vd1 + st * 5120, (const char*)(Vb + (size_t)(kb + row1) * DMODEL + h * DK) + ch1 * 16);
        }
        asm volatile("cp.async.commit_group;");
    };
    issueT(0, 0);
    issueT(1, 1);

    const u32 kaddr = su32(&Ks[0][lr][lm * 8]);
    const u32 vaddr = su32(&Vs[0][lr + (lm & 1) * 8][(lm >> 1) * 8]);

    float O[2][4][4];
#pragma unroll
    for (int s = 0; s < 2; s++)
#pragma unroll
        for (int t = 0; t < 4; t++)
#pragma unroll
            for (int j = 0; j < 4; j++) O[s][t][j] = 0.f;
    float l[2][2] = {};

    for (int kt = 0; kt < ATILES; kt++) {
        asm volatile("cp.async.wait_group 1;");
        __syncthreads();
        issueT(kt + 2, (kt + 2) % 3);
        const u32 kS = kaddr + (kt % 3) * 5120;
        const u32 vS = vaddr + (kt % 3) * 5120;

        u32 P[2][8][2];
#pragma unroll
        for (int kg = 0; kg < 8; kg++) {
            u32 b0, b1, b2, b3;
            ldsm_x4(b0, b1, b2, b3, kS + kg * 640);
#pragma unroll
            for (int s = 0; s < 2; s++) {
                float c0 = 0.f, c1 = 0.f, c2 = 0.f, c3 = 0.f;
                mma16816h(c0, c1, c2, c3, qa[s][0][0], qa[s][0][1], qa[s][0][2], qa[s][0][3], b0, b1);
                mma16816h(c0, c1, c2, c3, qa[s][1][0], qa[s][1][1], qa[s][1][2], qa[s][1][3], b2, b3);
                // scores already log2e-scaled (Q pre-scaled); packed f16 exp2
                u32 p01 = ex2h2(f2h2(c0, c1));
                u32 p23 = ex2h2(f2h2(c2, c3));
                l[s][0] += hlo(p01) + hhi(p01);
                l[s][1] += hlo(p23) + hhi(p23);
                P[s][kg][0] = p01;
                P[s][kg][1] = p23;
            }
        }

#pragma unroll
        for (int ck = 0; ck < 4; ck++) {
#pragma unroll
            for (int tp = 0; tp < 2; tp++) {
                u32 v0, v1, v2, v3;
                ldsm_x4t(v0, v1, v2, v3, vS + ck * 1280 + tp * 32);
#pragma unroll
                for (int s = 0; s < 2; s++) {
                    u32 a0 = P[s][2 * ck][0], a1 = P[s][2 * ck][1];
                    u32 a2 = P[s][2 * ck + 1][0], a3 = P[s][2 * ck + 1][1];
                    mma16816h(O[s][2 * tp][0], O[s][2 * tp][1], O[s][2 * tp][2], O[s][2 * tp][3],
                              a0, a1, a2, a3, v0, v1);
                    mma16816h(O[s][2 * tp + 1][0], O[s][2 * tp + 1][1],
                              O[s][2 * tp + 1][2], O[s][2 * tp + 1][3],
                              a0, a1, a2, a3, v2, v3);
                }
            }
        }
    }

    const int cql = 2 * (lane & 3);
    float* part = g_part + (size_t)chunk * N_NODES * DMODEL;
#pragma unroll
    for (int s = 0; s < 2; s++) {
        float l0 = l[s][0], l1 = l[s][1];
        l0 += __shfl_xor_sync(0xffffffffu, l0, 1);
        l0 += __shfl_xor_sync(0xffffffffu, l0, 2);
        l1 += __shfl_xor_sync(0xffffffffu, l1, 1);
        l1 += __shfl_xor_sync(0xffffffffu, l1, 2);
        const int r0 = qb + warp * 32 + s * 16 + (lane >> 2);
        const int r1 = r0 + 8;
#pragma unroll
        for (int t = 0; t < 4; t++) {
            int col = h * DK + t * 8 + cql;
            *(float2*)&part[(size_t)r0 * DMODEL + col] = make_float2(O[s][t][0], O[s][t][1]);
            *(float2*)&part[(size_t)r1 * DMODEL + col] = make_float2(O[s][t][2], O[s][t][3]);
        }
        if ((lane & 3) == 0) {
            g_lp[((size_t)chunk * N_NODES + r0) * NHEAD + h] = l0;
            g_lp[((size_t)chunk * N_NODES + r1) * NHEAD + h] = l1;
        }
    }
}

// ---------------- sparse bias correction + combine -> f16 attn ----------
__global__ __launch_bounds__(256) void corr_kernel(const __half* __restrict__ Qb,
                                                   const __half* __restrict__ Kb,
                                                   const __half* __restrict__ Vb) {
    __shared__ u32 slist[8][CAPL];
    __shared__ u32 wlist[8][CAPL];
    const int w    = threadIdx.x >> 5;
    const int q    = blockIdx.x * 8 + w;
    const int lane = threadIdx.x & 31;
    const int h = lane >> 2, g = lane & 3;
    const u32 lmask_lt = (1u << lane) - 1u;

    float qv[8];
    {
        uint4 wq = *(const uint4*)(Qb + (size_t)q * DMODEL + h * DK + g * 8);
        const u32 ws[4] = {wq.x, wq.y, wq.z, wq.w};
#pragma unroll
        for (int i = 0; i < 4; i++) {
            qv[2 * i]     = hlo(ws[i]);   // Q pre-scaled
            qv[2 * i + 1] = hhi(ws[i]);
        }
    }

    int cnt = g_cnt[q];
    if (lane == 0) g_cnt[q] = 0;          // self-reset for next graph replay
    if (cnt > CAPL) cnt = CAPL;
    for (int i = lane; i < cnt; i += 32)
        slist[w][i] = g_list[(size_t)q * CAPL + i];
    __syncwarp();

    // dedup (winner = max (dst<<16)|e per dst) + compact
    int ncnt = 0;
    for (int base = 0; base < cnt; base += 32) {
        int i = base + lane;
        u32 v = 0;
        bool win = false;
        if (i < cnt) {
            v = slist[w][i];
            win = true;
            for (int j = 0; j < cnt; j++) {
                u32 u = slist[w][j];
                if (((u ^ v) & 0xFFFF0000u) == 0 && u > v) win = false;
            }
        }
        u32 m = __ballot_sync(0xffffffffu, win);
        if (win) wlist[w][ncnt + __popc(m & lmask_lt)] = v;
        ncnt += __popc(m);
    }
    __syncwarp();

    float O[8];
#pragma unroll
    for (int i = 0; i < 8; i++) O[i] = 0.f;
    float lacc = 0.f;

    for (int i = 0; i < ncnt; i += 4) {
#pragma unroll
        for (int j = 0; j < 4; j++) {
            if (i + j >= ncnt) break;               // warp-uniform
            u32 v = wlist[w][i + j];
            int k    = (int)(v >> 16);
            int widx = (int)(v & 0xFFFFu);
            uint4 kw = *(const uint4*)(Kb + (size_t)k * DMODEL + h * DK + g * 8);
            uint4 vw = *(const uint4*)(Vb + (size_t)k * DMODEL + h * DK + g * 8);
            float eb = g_eb[(size_t)widx * 8 + h];
            const u32 ks[4] = {kw.x, kw.y, kw.z, kw.w};
            float s = 0.f;
#pragma unroll
            for (int t = 0; t < 4; t++) {
                s += qv[2 * t] * hlo(ks[t]);
                s += qv[2 * t + 1] * hhi(ks[t]);
            }
            s += __shfl_xor_sync(0xffffffffu, s, 1);
            s += __shfl_xor_sync(0xffffffffu, s, 2);
            float pd = ex2f(s + eb) - ex2f(s);
            lacc += pd;
            const u32 vs[4] = {vw.x, vw.y, vw.z, vw.w};
#pragma unroll
            for (int t = 0; t < 4; t++) {
                O[2 * t]     += pd * hlo(vs[t]);
                O[2 * t + 1] += pd * hhi(vs[t]);
            }
        }
    }

    // combine with dense split-K partials, normalize, emit f16
    float ltot = lacc;
#pragma unroll
    for (int c = 0; c < KSPLIT; c++)
        ltot += g_lp[((size_t)c * N_NODES + q) * NHEAD + h];
    const int col = h * DK + g * 8;
#pragma unroll
    for (int c = 0; c < KSPLIT; c++) {
        const float* p = g_part + ((size_t)c * N_NODES + q) * DMODEL + col;
        float4 p0 = *(const float4*)&p[0];
        float4 p1 = *(const float4*)&p[4];
        O[0] += p0.x; O[1] += p0.y; O[2] += p0.z; O[3] += p0.w;
        O[4] += p1.x; O[5] += p1.y; O[6] += p1.z; O[7] += p1.w;
    }
    float inv = 1.f / ltot;
    uint4 px;
    px.x = f2h2(O[0] * inv, O[1] * inv);
    px.y = f2h2(O[2] * inv, O[3] * inv);
    px.z = f2h2(O[4] * inv, O[5] * inv);
    px.w = f2h2(O[6] * inv, O[7] * inv);
    *(uint4*)&g_attnb[(size_t)q * DMODEL + col] = px;
}

// ---------------- fused double LayerNorm ----------------
__global__ __launch_bounds__(256) void ln_kernel(const float* __restrict__ Y,
                                                 const float* __restrict__ g1,
                                                 const float* __restrict__ b1,
                                                 const float* __restrict__ g2,
                                                 const float* __restrict__ b2,
                                                 float* __restrict__ H1,
                                                 __half* __restrict__ X2h) {
    const int lane = threadIdx.x & 31;
    const int row  = blockIdx.x * 8 + (threadIdx.x >> 5);
    const float4* y4 = (const float4*)(Y + (size_t)row * DMODEL);
    float v[8];
    {
        float4 a = y4[lane * 2], b = y4[lane * 2 + 1];
        v[0] = a.x; v[1] = a.y; v[2] = a.z; v[3] = a.w;
        v[4] = b.x; v[5] = b.y; v[6] = b.z; v[7] = b.w;
    }

    float s = 0.f;
#pragma unroll
    for (int j = 0; j < 8; j++) s += v[j];
#pragma unroll
    for (int o = 16; o; o >>= 1) s += __shfl_xor_sync(0xffffffffu, s, o);
    float mu = s * (1.f / 256.f);
    float q = 0.f;
#pragma unroll
    for (int j = 0; j < 8; j++) { float d = v[j] - mu; q += d * d; }
#pragma unroll
    for (int o = 16; o; o >>= 1) q += __shfl_xor_sync(0xffffffffu, q, o);
    float rs = rsqrtf(q * (1.f / 256.f) + 1e-5f);

    const int c0 = lane * 8;
    float hv[8];
#pragma unroll
    for (int j = 0; j < 8; j++)
        hv[j] = (v[j] - mu) * rs * g1[c0 + j] + b1[c0 + j];
    {
        float4* h4 = (float4*)(H1 + (size_t)row * DMODEL + c0);
        h4[0] = make_float4(hv[0], hv[1], hv[2], hv[3]);
        h4[1] = make_float4(hv[4], hv[5], hv[6], hv[7]);
    }

    s = 0.f;
#pragma unroll
    for (int j = 0; j < 8; j++) s += hv[j];
#pragma unroll
    for (int o = 16; o; o >>= 1) s += __shfl_xor_sync(0xffffffffu, s, o);
    mu = s * (1.f / 256.f);
    q = 0.f;
#pragma unroll
    for (int j = 0; j < 8; j++) { float d = hv[j] - mu; q += d * d; }
#pragma unroll
    for (int o = 16; o; o >>= 1) q += __shfl_xor_sync(0xffffffffu, q, o);
    rs = rsqrtf(q * (1.f / 256.f) + 1e-5f);

    float x[8];
#pragma unroll
    for (int j = 0; j < 8; j++)
        x[j] = (hv[j] - mu) * rs * g2[c0 + j] + b2[c0 + j];
    uint4 px;
    px.x = f2h2(x[0], x[1]);
    px.y = f2h2(x[2], x[3]);
    px.z = f2h2(x[4], x[5]);
    px.w = f2h2(x[6], x[7]);
    *(uint4*)&X2h[(size_t)row * DMODEL + c0] = px;
}

// ---------------- launch ----------------
extern "C" void kernel_launch(void* const* d_in, const int* in_sizes, int n_in,
                              void* d_out, int out_size) {
    const float* h    = (const float*)d_in[0];
    const float* ea   = (const float*)d_in[1];
    const float* Wq   = (const float*)d_in[2];
    const float* bq   = (const float*)d_in[3];
    const float* Wk   = (const float*)d_in[4];
    const float* bk   = (const float*)d_in[5];
    const float* Wv   = (const float*)d_in[6];
    const float* bv   = (const float*)d_in[7];
    const float* Wo   = (const float*)d_in[8];
    const float* bo   = (const float*)d_in[9];
    const float* We   = (const float*)d_in[10];
    const float* be   = (const float*)d_in[11];
    const float* ln1g = (const float*)d_in[12];
    const float* ln1b = (const float*)d_in[13];
    const float* flng = (const float*)d_in[14];
    const float* flnb = (const float*)d_in[15];
    const float* W1   = (const float*)d_in[16];
    const float* b1   = (const float*)d_in[17];
    const float* W2   = (const float*)d_in[18];
    const float* b2   = (const float*)d_in[19];
    const int*   eidx = (const int*)d_in[20];
    float* out = (float*)d_out;

    __half *pQb, *pKb, *pVb, *pAttnb, *pX2b, *pGb, *pWob, *pW1b, *pW2b;
    float *pY, *pH1;
    cudaGetSymbolAddress((void**)&pQb,    g_Qb);
    cudaGetSymbolAddress((void**)&pKb,    g_Kb);
    cudaGetSymbolAddress((void**)&pVb,    g_Vb);
    cudaGetSymbolAddress((void**)&pAttnb, g_attnb);
    cudaGetSymbolAddress((void**)&pX2b,   g_x2b);
    cudaGetSymbolAddress((void**)&pGb,    g_Gb);
    cudaGetSymbolAddress((void**)&pWob,   g_Wob);
    cudaGetSymbolAddress((void**)&pW1b,   g_W1b);
    cudaGetSymbolAddress((void**)&pW2b,   g_W2b);
    cudaGetSymbolAddress((void**)&pY,     g_Y);
    cudaGetSymbolAddress((void**)&pH1,    g_h1);

    prep_kernel<<<1280, 256>>>(h, Wq, Wk, Wv, Wo, W1, W2, ea, We, be, eidx);

    gemm_qkv_f16<<<dim3(12, 64), 128>>>(bq, bk, bv);

    attn_mma<<<dim3(N_NODES / 128, NHEAD, KSPLIT), 128>>>(pQb, pKb, pVb);
    corr_kernel<<<N_NODES / 8, 256>>>(pQb, pKb, pVb);

    gemm_f16<<<dim3(4, 64), 128>>>(pAttnb, pWob, bo, h, pY, nullptr,
                                   DMODEL, DMODEL, 0);

    ln_kernel<<<N_NODES / 8, 256>>>(pY, ln1g, ln1b, flng, flnb, pH1, pX2b);

    gemm_f16<<<dim3(8, 64), 128>>>(pX2b, pW1b, b1, nullptr, nullptr, pGb,
                                   HID, DMODEL, 1);
    gemm_f16<<<dim3(4, 64), 128>>>(pGb, pW2b, b2, pH1, out, nullptr,
                                   DMODEL, HID, 0);
}

// round 12
// speedup vs baseline: 2.2639x; 1.0957x over previous
#include <cuda_runtime.h>
#include <cuda_fp16.h>
#include <math.h>

#define N_NODES 2048
#define DMODEL  256
#define NHEAD   8
#define DK      32
#define NEDGE   65536
#define HID     512
#define KSPLIT  8
#define CAPL    256
#define ATILES  ((N_NODES / KSPLIT) / 64)

typedef unsigned long long ull;
typedef unsigned int u32;

// ---- mma / ldmatrix / cp.async helpers ----
__device__ __forceinline__ u32 su32(const void* p) {
    return (u32)__cvta_generic_to_shared(p);
}
__device__ __forceinline__ void ldsm_x4(u32& r0, u32& r1, u32& r2, u32& r3, u32 a) {
    asm volatile("ldmatrix.sync.aligned.m8n8.x4.shared.b16 {%0,%1,%2,%3},[%4];"
                 : "=r"(r0), "=r"(r1), "=r"(r2), "=r"(r3) : "r"(a));
}
__device__ __forceinline__ void ldsm_x4t(u32& r0, u32& r1, u32& r2, u32& r3, u32 a) {
    asm volatile("ldmatrix.sync.aligned.m8n8.x4.trans.shared.b16 {%0,%1,%2,%3},[%4];"
                 : "=r"(r0), "=r"(r1), "=r"(r2), "=r"(r3) : "r"(a));
}
__device__ __forceinline__ void mma16816h(float& c0, float& c1, float& c2, float& c3,
                                          u32 a0, u32 a1, u32 a2, u32 a3, u32 b0, u32 b1) {
    asm volatile("mma.sync.aligned.m16n8k16.row.col.f32.f16.f16.f32 "
                 "{%0,%1,%2,%3},{%4,%5,%6,%7},{%8,%9},{%0,%1,%2,%3};"
                 : "+f"(c0), "+f"(c1), "+f"(c2), "+f"(c3)
                 : "r"(a0), "r"(a1), "r"(a2), "r"(a3), "r"(b0), "r"(b1));
}
__device__ __forceinline__ float ex2f(float x) {
    float r; asm("ex2.approx.f32 %0,%1;" : "=f"(r) : "f"(x)); return r;
}
__device__ __forceinline__ u32 ex2h2(u32 a) {
    u32 r; asm("ex2.approx.f16x2 %0,%1;" : "=r"(r) : "r"(a)); return r;
}
__device__ __forceinline__ u32 f2h2(float lo, float hi) {
    __half2 h = __floats2half2_rn(lo, hi);
    return *(u32*)&h;
}
__device__ __forceinline__ float hlo(u32 w) { __half2 h = *(__half2*)&w; return __low2float(h); }
__device__ __forceinline__ float hhi(u32 w) { __half2 h = *(__half2*)&w; return __high2float(h); }
__device__ __forceinline__ void cp16(u32 dst, const void* src) {
    asm volatile("cp.async.ca.shared.global [%0],[%1],16;" :: "r"(dst), "l"(src));
}

// ---------------- scratch ----------------
__device__ __half g_hb[N_NODES * DMODEL];
__device__ __half g_Wqb[DMODEL * DMODEL];
__device__ __half g_Wkb[DMODEL * DMODEL];
__device__ __half g_Wvb[DMODEL * DMODEL];
__device__ __half g_Wob[DMODEL * DMODEL];
__device__ __half g_W1b[DMODEL * HID];
__device__ __half g_W2b[HID * DMODEL];
__device__ __half g_Qb[N_NODES * DMODEL];     // pre-scaled by log2e/sqrt(dk)
__device__ __half g_Kb[N_NODES * DMODEL];
__device__ __half g_Vb[N_NODES * DMODEL];
__device__ __half g_attnb[N_NODES * DMODEL];
__device__ __half g_x2b[N_NODES * DMODEL];
__device__ __half g_Gb[N_NODES * HID];
__device__ float g_eb[NEDGE * NHEAD];         // pre-scaled by log2(e)
__device__ int   g_cnt[N_NODES];              // self-resetting (corr zeroes it)
__device__ u32   g_list[N_NODES * CAPL];
__device__ float g_part[KSPLIT * N_NODES * DMODEL];
__device__ float g_lp[KSPLIT * N_NODES * NHEAD];
__device__ float g_Y[N_NODES * DMODEL];
__device__ float g_h1[N_NODES * DMODEL];

// ---------------- conv (blocks 0..1023) + edge (blocks 1024..1279) ----------------
__global__ __launch_bounds__(256) void prep_kernel(const float* __restrict__ h,
                                                   const float* __restrict__ Wq,
                                                   const float* __restrict__ Wk,
                                                   const float* __restrict__ Wv,
                                                   const float* __restrict__ Wo,
                                                   const float* __restrict__ W1,
                                                   const float* __restrict__ W2,
                                                   const float* __restrict__ ea,
                                                   const float* __restrict__ We,
                                                   const float* __restrict__ be,
                                                   const int*   __restrict__ eidx) {
    int gid = blockIdx.x * 256 + threadIdx.x;
    if (gid < 262144) {
        const float* src; __half* dst; int off;
        if (gid < 131072)      { src = h;  dst = g_hb;  off = gid; }
        else if (gid < 147456) { src = Wq; dst = g_Wqb; off = gid - 131072; }
        else if (gid < 163840) { src = Wk; dst = g_Wkb; off = gid - 147456; }
        else if (gid < 180224) { src = Wv; dst = g_Wvb; off = gid - 163840; }
        else if (gid < 196608) { src = Wo; dst = g_Wob; off = gid - 180224; }
        else if (gid < 229376) { src = W1; dst = g_W1b; off = gid - 196608; }
        else                   { src = W2; dst = g_W2b; off = gid - 229376; }
        float4 v = ((const float4*)src)[off];
        uint2 p;
        p.x = f2h2(v.x, v.y);
        p.y = f2h2(v.z, v.w);
        ((uint2*)dst)[off] = p;
    } else {
        const float L2E = 1.4426950408889634f;
        int e = gid - 262144;
        float a[7];
#pragma unroll
        for (int j = 0; j < 7; j++) a[j] = ea[e * 7 + j];
#pragma unroll
        for (int hh = 0; hh < 8; hh++) {
            float v = be[hh];
#pragma unroll
            for (int j = 0; j < 7; j++) v += a[j] * We[j * 8 + hh];
            g_eb[e * 8 + hh] = v * L2E;
        }
        int src = eidx[e];
        int dst = eidx[NEDGE + e];
        int pos = atomicAdd(&g_cnt[src], 1);
        if (pos < CAPL) g_list[(size_t)src * CAPL + pos] = ((u32)dst << 16) | (u32)e;
    }
}

// ---------------- fp16 tensor-core GEMM: 32x64 tile, BK=32, cp.async 4-stage ------
__device__ __forceinline__ void gemm_f16_body(const __half* __restrict__ A,
                                              const __half* __restrict__ B,
                                              const float* __restrict__ bias,
                                              const float* __restrict__ R,
                                              float* __restrict__ Cf,
                                              __half* __restrict__ Cb,
                                              int N, int K, int gelu, float oscale,
                                              int bm, int bn) {
    __shared__ __align__(16) __half As[4][32][40];
    __shared__ __align__(16) __half Bs[4][32][72];
    const int tid = threadIdx.x, warp = tid >> 5, lane = tid & 31;
    const int wm = warp & 1, wn = warp >> 1;
    const int lr = lane & 7, lm = lane >> 3;

    const int ar = tid >> 2, ac = tid & 3;
    const int br0 = tid >> 3, bc = tid & 7;
    const int br1 = br0 + 16;

    const u32 sA = su32(&As[0][0][0]);
    const u32 sB = su32(&Bs[0][0][0]);
    const u32 dstA  = sA + ar * 80 + ac * 16;
    const u32 dstB0 = sB + br0 * 144 + bc * 16;
    const u32 dstB1 = sB + br1 * 144 + bc * 16;
    const __half* srcA = A + (size_t)(bm + ar) * K + ac * 8;

    const int Kk = K >> 5;
    float acc[4][4] = {};

    auto issue = [&](int kb, int st) {
        if (kb < Kk) {
            cp16(dstA + st * 2560, srcA + kb * 32);
            cp16(dstB0 + st * 4608, B + (size_t)(kb * 32 + br0) * N + bn + bc * 8);
            cp16(dstB1 + st * 4608, B + (size_t)(kb * 32 + br1) * N + bn + bc * 8);
        }
        asm volatile("cp.async.commit_group;");
    };
    issue(0, 0);
    issue(1, 1);
    issue(2, 2);

    const u32 aBase = sA + (wm * 16 + lr + (lm & 1) * 8) * 80 + (lm >> 1) * 16;
    const u32 bBase = sB + (lr + (lm & 1) * 8) * 144 + (wn * 32 + (lm >> 1) * 8) * 2;

    for (int kb = 0; kb < Kk; kb++) {
        asm volatile("cp.async.wait_group 2;");
        __syncthreads();
        issue(kb + 3, (kb + 3) & 3);
        const u32 aS = aBase + (kb & 3) * 2560;
        const u32 bS = bBase + (kb & 3) * 4608;
#pragma unroll
        for (int ks = 0; ks < 2; ks++) {
            u32 a0, a1, a2, a3;
            ldsm_x4(a0, a1, a2, a3, aS + ks * 32);
#pragma unroll
            for (int ng2 = 0; ng2 < 2; ng2++) {
                u32 b0, b1, b2, b3;
                ldsm_x4t(b0, b1, b2, b3, bS + ks * 16 * 144 + ng2 * 32);
                mma16816h(acc[ng2 * 2][0], acc[ng2 * 2][1], acc[ng2 * 2][2], acc[ng2 * 2][3],
                          a0, a1, a2, a3, b0, b1);
                mma16816h(acc[ng2 * 2 + 1][0], acc[ng2 * 2 + 1][1],
                          acc[ng2 * 2 + 1][2], acc[ng2 * 2 + 1][3],
                          a0, a1, a2, a3, b2, b3);
            }
        }
    }

    const int rr = lane >> 2, cql = 2 * (lane & 3);
    const int r0 = bm + wm * 16 + rr, r1 = r0 + 8;
#pragma unroll
    for (int idx = 0; idx < 4; idx++) {
        const int col = bn + wn * 32 + idx * 8 + cql;
        float b0 = bias[col], b1 = bias[col + 1];
        float o0 = (acc[idx][0] + b0) * oscale, o1 = (acc[idx][1] + b1) * oscale;
        float o2 = (acc[idx][2] + b0) * oscale, o3 = (acc[idx][3] + b1) * oscale;
        if (gelu) {
            o0 *= normcdff(o0); o1 *= normcdff(o1);
            o2 *= normcdff(o2); o3 *= normcdff(o3);
        }
        if (R) {
            o0 += R[(size_t)r0 * N + col]; o1 += R[(size_t)r0 * N + col + 1];
            o2 += R[(size_t)r1 * N + col]; o3 += R[(size_t)r1 * N + col + 1];
        }
        if (Cb) {
            *(u32*)&Cb[(size_t)r0 * N + col] = f2h2(o0, o1);
            *(u32*)&Cb[(size_t)r1 * N + col] = f2h2(o2, o3);
        } else {
            *(float2*)&Cf[(size_t)r0 * N + col] = make_float2(o0, o1);
            *(float2*)&Cf[(size_t)r1 * N + col] = make_float2(o2, o3);
        }
    }
}

__global__ __launch_bounds__(128) void gemm_f16(const __half* __restrict__ A,
                                                const __half* __restrict__ B,
                                                const float* __restrict__ bias,
                                                const float* __restrict__ R,
                                                float* __restrict__ Cf,
                                                __half* __restrict__ Cb,
                                                int N, int K, int gelu) {
    gemm_f16_body(A, B, bias, R, Cf, Cb, N, K, gelu, 1.0f, blockIdx.y * 32, blockIdx.x * 64);
}

__global__ __launch_bounds__(128) void gemm_qkv_f16(const float* __restrict__ bq,
                                                    const float* __restrict__ bk,
                                                    const float* __restrict__ bv) {
    const float SCALE2 = 1.4426950408889634f * 0.17677669529663688f;
    int sel = blockIdx.x >> 2;
    int bn  = (blockIdx.x & 3) * 64;
    const __half* B   = (sel == 0) ? g_Wqb : (sel == 1) ? g_Wkb : g_Wvb;
    const float* bias = (sel == 0) ? bq : (sel == 1) ? bk : bv;
    __half* Cb        = (sel == 0) ? g_Qb : (sel == 1) ? g_Kb : g_Vb;
    float oscale      = (sel == 0) ? SCALE2 : 1.0f;
    gemm_f16_body(g_hb, B, bias, nullptr, nullptr, Cb, DMODEL, DMODEL, 0, oscale,
                  blockIdx.y * 32, bn);
}

// ---------------- dense flash attention: 128 q/block, split-K=8, f16x2 exp ----
__global__ __launch_bounds__(128, 3) void attn_mma(const __half* __restrict__ Qb,
                                                   const __half* __restrict__ Kb,
                                                   const __half* __restrict__ Vb) {
    __shared__ __align__(16) __half Qs[128][40];
    __shared__ __align__(16) __half Ks[3][64][40];
    __shared__ __align__(16) __half Vs[3][64][40];

    const int h     = blockIdx.y;
    const int qb    = blockIdx.x * 128;
    const int chunk = blockIdx.z;
    const int kb0   = chunk * (N_NODES / KSPLIT);
    const int tid = threadIdx.x;
    const int warp = tid >> 5, lane = tid & 31;

#pragma unroll
    for (int i = 0; i < 4; i++) {
        int task = tid + 128 * i;
        int row = task >> 2, ch = task & 3;
        *(uint4*)((char*)&Qs[row][0] + ch * 16) =
            *(const uint4*)((const char*)(Qb + (size_t)(qb + row) * DMODEL + h * DK) + ch * 16);
    }
    __syncthreads();
    const int lr = lane & 7, lm = lane >> 3;
    u32 qa[2][2][4];
#pragma unroll
    for (int s = 0; s < 2; s++) {
        int row = warp * 32 + s * 16 + lr + (lm & 1) * 8;
#pragma unroll
        for (int c = 0; c < 2; c++) {
            u32 a = su32(&Qs[row][c * 16 + (lm >> 1) * 8]);
            ldsm_x4(qa[s][c][0], qa[s][c][1], qa[s][c][2], qa[s][c][3], a);
        }
    }

    const int row0 = tid >> 2, ch0 = tid & 3;
    const int row1 = (tid + 128) >> 2, ch1 = (tid + 128) & 3;
    const u32 kd0 = su32(&Ks[0][row0][0]) + ch0 * 16;
    const u32 kd1 = su32(&Ks[0][row1][0]) + ch1 * 16;
    const u32 vd0 = su32(&Vs[0][row0][0]) + ch0 * 16;
    const u32 vd1 = su32(&Vs[0][row1][0]) + ch1 * 16;

    auto issueT = [&](int kt, int st) {
        if (kt < ATILES) {
            int kb = kb0 + kt * 64;
            cp16(kd0 + st * 5120, (const char*)(Kb + (size_t)(kb + row0) * DMODEL + h * DK) + ch0 * 16);
            cp16(kd1 + st * 5120, (const char*)(Kb + (size_t)(kb + row1) * DMODEL + h * DK) + ch1 * 16);
            cp16(vd0 + st * 5120, (const char*)(Vb + (size_t)(kb + row0) * DMODEL + h * DK) + ch0 * 16);
            cp16(vd1 + st * 5120, (const char*)(Vb + (size_t)(kb + row1) * DMODEL + h * DK) + ch1 * 16);
        }
        asm volatile("cp.async.commit_group;");
    };
    issueT(0, 0);
    issueT(1, 1);

    const u32 kaddr = su32(&Ks[0][lr][lm * 8]);
    const u32 vaddr = su32(&Vs[0][lr + (lm & 1) * 8][(lm >> 1) * 8]);

    float O[2][4][4];
#pragma unroll
    for (int s = 0; s < 2; s++)
#pragma unroll
        for (int t = 0; t < 4; t++)
#pragma unroll
            for (int j = 0; j < 4; j++) O[s][t][j] = 0.f;
    float l[2][2] = {};

    for (int kt = 0; kt < ATILES; kt++) {
        asm volatile("cp.async.wait_group 1;");
        __syncthreads();
        issueT(kt + 2, (kt + 2) % 3);
        const u32 kS = kaddr + (kt % 3) * 5120;
        const u32 vS = vaddr + (kt % 3) * 5120;

        u32 P[2][8][2];
#pragma unroll
        for (int kg = 0; kg < 8; kg++) {
            u32 b0, b1, b2, b3;
            ldsm_x4(b0, b1, b2, b3, kS + kg * 640);
#pragma unroll
            for (int s = 0; s < 2; s++) {
                float c0 = 0.f, c1 = 0.f, c2 = 0.f, c3 = 0.f;
                mma16816h(c0, c1, c2, c3, qa[s][0][0], qa[s][0][1], qa[s][0][2], qa[s][0][3], b0, b1);
                mma16816h(c0, c1, c2, c3, qa[s][1][0], qa[s][1][1], qa[s][1][2], qa[s][1][3], b2, b3);
                u32 p01 = ex2h2(f2h2(c0, c1));
                u32 p23 = ex2h2(f2h2(c2, c3));
                l[s][0] += hlo(p01) + hhi(p01);
                l[s][1] += hlo(p23) + hhi(p23);
                P[s][kg][0] = p01;
                P[s][kg][1] = p23;
            }
        }

#pragma unroll
        for (int ck = 0; ck < 4; ck++) {
#pragma unroll
            for (int tp = 0; tp < 2; tp++) {
                u32 v0, v1, v2, v3;
                ldsm_x4t(v0, v1, v2, v3, vS + ck * 1280 + tp * 32);
#pragma unroll
                for (int s = 0; s < 2; s++) {
                    u32 a0 = P[s][2 * ck][0], a1 = P[s][2 * ck][1];
                    u32 a2 = P[s][2 * ck + 1][0], a3 = P[s][2 * ck + 1][1];
                    mma16816h(O[s][2 * tp][0], O[s][2 * tp][1], O[s][2 * tp][2], O[s][2 * tp][3],
                              a0, a1, a2, a3, v0, v1);
                    mma16816h(O[s][2 * tp + 1][0], O[s][2 * tp + 1][1],
                              O[s][2 * tp + 1][2], O[s][2 * tp + 1][3],
                              a0, a1, a2, a3, v2, v3);
                }
            }
        }
    }

    const int cql = 2 * (lane & 3);
    float* part = g_part + (size_t)chunk * N_NODES * DMODEL;
#pragma unroll
    for (int s = 0; s < 2; s++) {
        float l0 = l[s][0], l1 = l[s][1];
        l0 += __shfl_xor_sync(0xffffffffu, l0, 1);
        l0 += __shfl_xor_sync(0xffffffffu, l0, 2);
        l1 += __shfl_xor_sync(0xffffffffu, l1, 1);
        l1 += __shfl_xor_sync(0xffffffffu, l1, 2);
        const int r0 = qb + warp * 32 + s * 16 + (lane >> 2);
        const int r1 = r0 + 8;
#pragma unroll
        for (int t = 0; t < 4; t++) {
            int col = h * DK + t * 8 + cql;
            *(float2*)&part[(size_t)r0 * DMODEL + col] = make_float2(O[s][t][0], O[s][t][1]);
            *(float2*)&part[(size_t)r1 * DMODEL + col] = make_float2(O[s][t][2], O[s][t][3]);
        }
        if ((lane & 3) == 0) {
            g_lp[((size_t)chunk * N_NODES + r0) * NHEAD + h] = l0;
            g_lp[((size_t)chunk * N_NODES + r1) * NHEAD + h] = l1;
        }
    }
}

// ---------------- sparse bias correction + combine -> f16 attn ----------------
// block 128 = 4 warps = 2 queries x 2 head-halves. lane = h_local*8 + g,
// h = ws*4 + h_local, lane owns dims [g*4, g*4+4). Register double-buffered hits.
__global__ __launch_bounds__(128) void corr_kernel(const __half* __restrict__ Qb,
                                                   const __half* __restrict__ Kb,
                                                   const __half* __restrict__ Vb) {
    __shared__ u32 slist[2][CAPL];
    __shared__ u32 wlist[2][CAPL];
    __shared__ int scnt[2];
    const int warp = threadIdx.x >> 5;   // 0..3
    const int qi   = warp >> 1;          // 0,1
    const int ws   = warp & 1;           // head half
    const int q    = blockIdx.x * 2 + qi;
    const int lane = threadIdx.x & 31;
    const int hl = lane >> 3, g = lane & 7;
    const int h = ws * 4 + hl;
    const u32 lmask_lt = (1u << lane) - 1u;

    if (threadIdx.x < 2) scnt[threadIdx.x] = g_cnt[blockIdx.x * 2 + threadIdx.x];
    __syncthreads();
    if (threadIdx.x < 2) g_cnt[blockIdx.x * 2 + threadIdx.x] = 0;  // self-reset
    int cnt = scnt[qi];
    if (cnt > CAPL) cnt = CAPL;

    // Q slice (pre-scaled)
    float qv[4];
    {
        uint2 wq = *(const uint2*)(Qb + (size_t)q * DMODEL + h * DK + g * 4);
        qv[0] = hlo(wq.x); qv[1] = hhi(wq.x);
        qv[2] = hlo(wq.y); qv[3] = hhi(wq.y);
    }

    // load list (both warps of a pair write identical values - benign)
    for (int i = lane; i < cnt; i += 32)
        slist[qi][i] = g_list[(size_t)q * CAPL + i];
    __syncwarp();

    // dedup (winner = max (dst<<16)|e per dst) + compact; duplicated per warp
    int ncnt = 0;
    for (int base = 0; base < cnt; base += 32) {
        int i = base + lane;
        u32 v = 0;
        bool win = false;
        if (i < cnt) {
            v = slist[qi][i];
            win = true;
            for (int j = 0; j < cnt; j++) {
                u32 u = slist[qi][j];
                if (((u ^ v) & 0xFFFF0000u) == 0 && u > v) win = false;
            }
        }
        u32 m = __ballot_sync(0xffffffffu, win);
        if (win) wlist[qi][ncnt + __popc(m & lmask_lt)] = v;
        ncnt += __popc(m);
    }
    __syncwarp();

    float O4[4] = {0.f, 0.f, 0.f, 0.f};
    float lacc = 0.f;

    uint2 kA[4], vA[4];
    float eA[4];
    auto loadb = [&](int base, uint2* kk, uint2* vv, float* ee) {
#pragma unroll
        for (int j = 0; j < 4; j++) {
            int idx = base + j;
            if (idx < ncnt) {                        // warp-uniform
                u32 v = wlist[qi][idx];
                int k    = (int)(v >> 16);
                int widx = (int)(v & 0xFFFFu);
                kk[j] = *(const uint2*)(Kb + (size_t)k * DMODEL + h * DK + g * 4);
                vv[j] = *(const uint2*)(Vb + (size_t)k * DMODEL + h * DK + g * 4);
                ee[j] = g_eb[(size_t)widx * 8 + h];
            }
        }
    };
    loadb(0, kA, vA, eA);

    for (int i = 0; i < ncnt; i += 4) {
        uint2 kB[4], vB[4];
        float eB[4];
        loadb(i + 4, kB, vB, eB);                    // prefetch next batch
#pragma unroll
        for (int j = 0; j < 4; j++) {
            if (i + j >= ncnt) break;                // warp-uniform
            float s = qv[0] * hlo(kA[j].x) + qv[1] * hhi(kA[j].x)
                    + qv[2] * hlo(kA[j].y) + qv[3] * hhi(kA[j].y);
            s += __shfl_xor_sync(0xffffffffu, s, 1);
            s += __shfl_xor_sync(0xffffffffu, s, 2);
            s += __shfl_xor_sync(0xffffffffu, s, 4);
            float pd = ex2f(s + eA[j]) - ex2f(s);
            lacc += pd;
            O4[0] += pd * hlo(vA[j].x); O4[1] += pd * hhi(vA[j].x);
            O4[2] += pd * hlo(vA[j].y); O4[3] += pd * hhi(vA[j].y);
        }
#pragma unroll
        for (int j = 0; j < 4; j++) { kA[j] = kB[j]; vA[j] = vB[j]; eA[j] = eB[j]; }
    }

    // reduce lacc across the 8-lane head group (all lanes get it)
    lacc += __shfl_xor_sync(0xffffffffu, lacc, 1);
    lacc += __shfl_xor_sync(0xffffffffu, lacc, 2);
    lacc += __shfl_xor_sync(0xffffffffu, lacc, 4);

    float ltot = lacc;
#pragma unroll
    for (int c = 0; c < KSPLIT; c++)
        ltot += g_lp[((size_t)c * N_NODES + q) * NHEAD + h];
    const int col = h * DK + g * 4;
#pragma unroll
    for (int c = 0; c < KSPLIT; c++) {
        float4 p = *(const float4*)(g_part + ((size_t)c * N_NODES + q) * DMODEL + col);
        O4[0] += p.x; O4[1] += p.y; O4[2] += p.z; O4[3] += p.w;
    }
    float inv = 1.f / ltot;
    uint2 px;
    px.x = f2h2(O4[0] * inv, O4[1] * inv);
    px.y = f2h2(O4[2] * inv, O4[3] * inv);
    *(uint2*)&g_attnb[(size_t)q * DMODEL + col] = px;
}

// ---------------- fused double LayerNorm ----------------
__global__ __launch_bounds__(256) void ln_kernel(const float* __restrict__ Y,
                                                 const float* __restrict__ g1,
                                                 const float* __restrict__ b1,
                                                 const float* __restrict__ g2,
                                                 const float* __restrict__ b2,
                                                 float* __restrict__ H1,
                                                 __half* __restrict__ X2h) {
    const int lane = threadIdx.x & 31;
    const int row  = blockIdx.x * 8 + (threadIdx.x >> 5);
    const float4* y4 = (const float4*)(Y + (size_t)row * DMODEL);
    float v[8];
    {
        float4 a = y4[lane * 2], b = y4[lane * 2 + 1];
        v[0] = a.x; v[1] = a.y; v[2] = a.z; v[3] = a.w;
        v[4] = b.x; v[5] = b.y; v[6] = b.z; v[7] = b.w;
    }

    float s = 0.f;
#pragma unroll
    for (int j = 0; j < 8; j++) s += v[j];
#pragma unroll
    for (int o = 16; o; o >>= 1) s += __shfl_xor_sync(0xffffffffu, s, o);
    float mu = s * (1.f / 256.f);
    float q = 0.f;
#pragma unroll
    for (int j = 0; j < 8; j++) { float d = v[j] - mu; q += d * d; }
#pragma unroll
    for (int o = 16; o; o >>= 1) q += __shfl_xor_sync(0xffffffffu, q, o);
    float rs = rsqrtf(q * (1.f / 256.f) + 1e-5f);

    const int c0 = lane * 8;
    float hv[8];
#pragma unroll
    for (int j = 0; j < 8; j++)
        hv[j] = (v[j] - mu) * rs * g1[c0 + j] + b1[c0 + j];
    {
        float4* h4 = (float4*)(H1 + (size_t)row * DMODEL + c0);
        h4[0] = make_float4(hv[0], hv[1], hv[2], hv[3]);
        h4[1] = make_float4(hv[4], hv[5], hv[6], hv[7]);
    }

    s = 0.f;
#pragma unroll
    for (int j = 0; j < 8; j++) s += hv[j];
#pragma unroll
    for (int o = 16; o; o >>= 1) s += __shfl_xor_sync(0xffffffffu, s, o);
    mu = s * (1.f / 256.f);
    q = 0.f;
#pragma unroll
    for (int j = 0; j < 8; j++) { float d = hv[j] - mu; q += d * d; }
#pragma unroll
    for (int o = 16; o; o >>= 1) q += __shfl_xor_sync(0xffffffffu, q, o);
    rs = rsqrtf(q * (1.f / 256.f) + 1e-5f);

    float x[8];
#pragma unroll
    for (int j = 0; j < 8; j++)
        x[j] = (hv[j] - mu) * rs * g2[c0 + j] + b2[c0 + j];
    uint4 px;
    px.x = f2h2(x[0], x[1]);
    px.y = f2h2(x[2], x[3]);
    px.z = f2h2(x[4], x[5]);
    px.w = f2h2(x[6], x[7]);
    *(uint4*)&X2h[(size_t)row * DMODEL + c0] = px;
}

// ---------------- launch ----------------
extern "C" void kernel_launch(void* const* d_in, const int* in_sizes, int n_in,
                              void* d_out, int out_size) {
    const float* h    = (const float*)d_in[0];
    const float* ea   = (const float*)d_in[1];
    const float* Wq   = (const float*)d_in[2];
    const float* bq   = (const float*)d_in[3];
    const float* Wk   = (const float*)d_in[4];
    const float* bk   = (const float*)d_in[5];
    const float* Wv   = (const float*)d_in[6];
    const float* bv   = (const float*)d_in[7];
    const float* Wo   = (const float*)d_in[8];
    const float* bo   = (const float*)d_in[9];
    const float* We   = (const float*)d_in[10];
    const float* be   = (const float*)d_in[11];
    const float* ln1g = (const float*)d_in[12];
    const float* ln1b = (const float*)d_in[13];
    const float* flng = (const float*)d_in[14];
    const float* flnb = (const float*)d_in[15];
    const float* W1   = (const float*)d_in[16];
    const float* b1   = (const float*)d_in[17];
    const float* W2   = (const float*)d_in[18];
    const float* b2   = (const float*)d_in[19];
    const int*   eidx = (const int*)d_in[20];
    float* out = (float*)d_out;

    __half *pQb, *pKb, *pVb, *pAttnb, *pX2b, *pGb, *pWob, *pW1b, *pW2b;
    float *pY, *pH1;
    cudaGetSymbolAddress((void**)&pQb,    g_Qb);
    cudaGetSymbolAddress((void**)&pKb,    g_Kb);
    cudaGetSymbolAddress((void**)&pVb,    g_Vb);
    cudaGetSymbolAddress((void**)&pAttnb, g_attnb);
    cudaGetSymbolAddress((void**)&pX2b,   g_x2b);
    cudaGetSymbolAddress((void**)&pGb,    g_Gb);
    cudaGetSymbolAddress((void**)&pWob,   g_Wob);
    cudaGetSymbolAddress((void**)&pW1b,   g_W1b);
    cudaGetSymbolAddress((void**)&pW2b,   g_W2b);
    cudaGetSymbolAddress((void**)&pY,     g_Y);
    cudaGetSymbolAddress((void**)&pH1,    g_h1);

    prep_kernel<<<1280, 256>>>(h, Wq, Wk, Wv, Wo, W1, W2, ea, We, be, eidx);

    gemm_qkv_f16<<<dim3(12, 64), 128>>>(bq, bk, bv);

    attn_mma<<<dim3(N_NODES / 128, NHEAD, KSPLIT), 128>>>(pQb, pKb, pVb);
    corr_kernel<<<N_NODES / 2, 128>>>(pQb, pKb, pVb);

    gemm_f16<<<dim3(4, 64), 128>>>(pAttnb, pWob, bo, h, pY, nullptr,
                                   DMODEL, DMODEL, 0);

    ln_kernel<<<N_NODES / 8, 256>>>(pY, ln1g, ln1b, flng, flnb, pH1, pX2b);

    gemm_f16<<<dim3(8, 64), 128>>>(pX2b, pW1b, b1, nullptr, nullptr, pGb,
                                   HID, DMODEL, 1);
    gemm_f16<<<dim3(4, 64), 128>>>(pGb, pW2b, b2, pH1, out, nullptr,
                                   DMODEL, HID, 0);
}